// round 12
// baseline (speedup 1.0000x reference)
#include <cuda_runtime.h>
#include <cuda_bf16.h>
#include <math.h>
#include <stdint.h>

#define Bsz 32
#define Pn  196
#define Dn  2048
#define Hn  512
#define Vn  30000
#define Tn  19
#define Vp  30080
#define Mrows 608
#define Mp  640

// ---------------- fp32 scratch ----------------
__device__ float g_avg[Bsz * Dn];
__device__ float g_h[Bsz * Hn];
__device__ float g_c[Bsz * Hn];
__device__ float g_att_img[Bsz * Pn * Hn];
__device__ float g_emb[Bsz * Tn * Hn];
__device__ float g_embW[Bsz * Tn * 4 * Hn];
__device__ float g_xc[Bsz * Dn];
__device__ float g_pp_h[8 * Bsz * Hn];           // hproj (ks=8)
__device__ float g_pp_g[8 * Bsz * Dn];           // fbeta (ks=8)
__device__ float g_pa[8 * Bsz * 4 * Hn];         // xc@Wih_bot (ks=8)
__device__ float g_pb[4 * Bsz * 4 * Hn];         // h@Whh (ks=4)
__device__ float g_pi_h[8 * Bsz * Hn];
__device__ float g_pi_c[8 * Bsz * Hn];
__device__ int   g_cntA[Tn];
__device__ int   g_cntB[Tn];

// ---------------- bf16 split scratch ----------------
__device__ __nv_bfloat16 g_img_hi[Bsz * Pn * Dn];
__device__ __nv_bfloat16 g_img_lo[Bsz * Pn * Dn];
__device__ __nv_bfloat16 g_watt_hi[Hn * Dn];
__device__ __nv_bfloat16 g_watt_lo[Hn * Dn];
__device__ __nv_bfloat16 g_wout_hi[Vp * Hn];
__device__ __nv_bfloat16 g_wout_lo[Vp * Hn];
__device__ __nv_bfloat16 g_wih_hi[4 * Hn * Hn];
__device__ __nv_bfloat16 g_wih_lo[4 * Hn * Hn];
__device__ __nv_bfloat16 g_embh[Mp * Hn];
__device__ __nv_bfloat16 g_embl[Mp * Hn];
__device__ __nv_bfloat16 g_hallh[Mp * Hn];
__device__ __nv_bfloat16 g_halll[Mp * Hn];

__device__ __forceinline__ float sigf(float x) { return 1.f / (1.f + expf(-x)); }

__device__ __forceinline__ uint32_t smem_u32(const void* p) {
    uint32_t a;
    asm("{ .reg .u64 t; cvta.to.shared.u64 t, %1; cvt.u32.u64 %0, t; }" : "=r"(a) : "l"(p));
    return a;
}
__device__ __forceinline__ void ldmx4(uint32_t* r, uint32_t addr) {
    asm volatile("ldmatrix.sync.aligned.m8n8.x4.shared.b16 {%0,%1,%2,%3}, [%4];"
                 : "=r"(r[0]), "=r"(r[1]), "=r"(r[2]), "=r"(r[3]) : "r"(addr));
}
__device__ __forceinline__ void mma16816(float* d, const uint32_t* a, const uint32_t* b) {
    asm volatile(
        "mma.sync.aligned.m16n8k16.row.col.f32.bf16.bf16.f32 "
        "{%0,%1,%2,%3}, {%4,%5,%6,%7}, {%8,%9}, {%0,%1,%2,%3};"
        : "+f"(d[0]), "+f"(d[1]), "+f"(d[2]), "+f"(d[3])
        : "r"(a[0]), "r"(a[1]), "r"(a[2]), "r"(a[3]), "r"(b[0]), "r"(b[1]));
}
#define CP16(s, g)  asm volatile("cp.async.cg.shared.global [%0], [%1], 16;" :: "r"(s), "l"(g))
#define CPCOMMIT()  asm volatile("cp.async.commit_group;" ::: "memory")
#define CPWAIT1()   asm volatile("cp.async.wait_group 1;" ::: "memory")
#define CPWAIT0()   asm volatile("cp.async.wait_group 0;" ::: "memory")

// ==================== split-bf16 HMMA GEMM: 2-stage, 2 CTAs/SM ====================
#define RSB 80
#define TSZ (128 * RSB)
#define STG (4 * TSZ)
#define HMMA_SMEM (2 * STG)      // 81920

template <int OUTMAP>
__global__ __launch_bounds__(256, 2)
void hmma_gemm(const __nv_bfloat16* __restrict__ Ahi, const __nv_bfloat16* __restrict__ Alo,
               const __nv_bfloat16* __restrict__ Bhi, const __nv_bfloat16* __restrict__ Blo,
               const float* __restrict__ bias, float* __restrict__ C,
               int M, int N, int K, int ldc)
{
    extern __shared__ char smc[];
    const uint32_t sb = smem_u32(smc);
    const int tid = threadIdx.x;
    const int lane = tid & 31, wid = tid >> 5;
    const int wm = wid & 1, wn = wid >> 1;
    const int m0 = blockIdx.y * 128, n0 = blockIdx.x * 128;

    int r0 = tid >> 2, c0 = tid & 3;
    int r1 = (tid + 256) >> 2, c1 = tid & 3;
    const __nv_bfloat16* base0[4] = {
        Ahi + (size_t)(m0 + r0) * K + c0 * 8,
        Alo + (size_t)(m0 + r0) * K + c0 * 8,
        Bhi + (size_t)(n0 + r0) * K + c0 * 8,
        Blo + (size_t)(n0 + r0) * K + c0 * 8 };
    const __nv_bfloat16* base1[4] = {
        Ahi + (size_t)(m0 + r1) * K + c1 * 8,
        Alo + (size_t)(m0 + r1) * K + c1 * 8,
        Bhi + (size_t)(n0 + r1) * K + c1 * 8,
        Blo + (size_t)(n0 + r1) * K + c1 * 8 };
    const uint32_t so0 = (uint32_t)(r0 * RSB + c0 * 16);
    const uint32_t so1 = (uint32_t)(r1 * RSB + c1 * 16);

    const int arow = (lane & 7) | (((lane >> 3) & 1) << 3);
    const int akh  = lane >> 4;
    const int brow = (lane & 7) + ((lane >> 4) << 3);
    const int bkh  = (lane >> 3) & 1;

    float acc[4][4][4];
#pragma unroll
    for (int i = 0; i < 4; i++)
#pragma unroll
        for (int j = 0; j < 4; j++)
#pragma unroll
            for (int e = 0; e < 4; e++) acc[i][j][e] = 0.f;

    const int nit = K / 32;

#pragma unroll
    for (int pi = 0; pi < 2; pi++) {
        uint32_t dst = sb + pi * STG;
        int kof = pi * 32;
#pragma unroll
        for (int tno = 0; tno < 4; tno++) {
            CP16(dst + tno * TSZ + so0, base0[tno] + kof);
            CP16(dst + tno * TSZ + so1, base1[tno] + kof);
        }
        CPCOMMIT();
    }

    for (int it = 0; it < nit; it++) {
        if (it + 1 < nit) { CPWAIT1(); } else { CPWAIT0(); }
        __syncthreads();

        const uint32_t stb = sb + (it & 1) * STG;
#pragma unroll
        for (int ks = 0; ks < 2; ks++) {
            uint32_t ah[4][4], al[4][4], bh[4][2], bl[4][2];
#pragma unroll
            for (int mt = 0; mt < 4; mt++) {
                uint32_t ra = (uint32_t)((wm * 64 + mt * 16 + arow) * RSB + ks * 32 + akh * 16);
                ldmx4(ah[mt], stb + 0 * TSZ + ra);
                ldmx4(al[mt], stb + 1 * TSZ + ra);
            }
#pragma unroll
            for (int g = 0; g < 2; g++) {
                uint32_t rb = (uint32_t)((wn * 32 + g * 16 + brow) * RSB + ks * 32 + bkh * 16);
                uint32_t t0[4], t1[4];
                ldmx4(t0, stb + 2 * TSZ + rb);
                ldmx4(t1, stb + 3 * TSZ + rb);
                bh[g * 2][0] = t0[0]; bh[g * 2][1] = t0[1];
                bh[g * 2 + 1][0] = t0[2]; bh[g * 2 + 1][1] = t0[3];
                bl[g * 2][0] = t1[0]; bl[g * 2][1] = t1[1];
                bl[g * 2 + 1][0] = t1[2]; bl[g * 2 + 1][1] = t1[3];
            }
#pragma unroll
            for (int mt = 0; mt < 4; mt++)
#pragma unroll
                for (int nt = 0; nt < 4; nt++) {
                    mma16816(acc[mt][nt], ah[mt], bh[nt]);
                    mma16816(acc[mt][nt], ah[mt], bl[nt]);
                    mma16816(acc[mt][nt], al[mt], bh[nt]);
                }
        }
        __syncthreads();

        if (it + 2 < nit) {
            uint32_t dst = sb + (it & 1) * STG;
            int kof = (it + 2) * 32;
#pragma unroll
            for (int tno = 0; tno < 4; tno++) {
                CP16(dst + tno * TSZ + so0, base0[tno] + kof);
                CP16(dst + tno * TSZ + so1, base1[tno] + kof);
            }
            CPCOMMIT();
        }
    }

#pragma unroll
    for (int mt = 0; mt < 4; mt++) {
#pragma unroll
        for (int half = 0; half < 2; half++) {
            int r = m0 + wm * 64 + mt * 16 + (lane >> 2) + half * 8;
            bool rowok; float* Crow;
            if (OUTMAP) {
                int ob = r & 31, ot = r >> 5;
                rowok = (ot < Tn);
                Crow = C + (size_t)(ob * Tn + ot) * ldc;
            } else {
                rowok = (r < M);
                Crow = C + (size_t)r * ldc;
            }
            if (!rowok) continue;
#pragma unroll
            for (int nt = 0; nt < 4; nt++) {
                int n = n0 + wn * 32 + nt * 8 + (lane & 3) * 2;
                if (n + 1 < N) {
                    float v0 = acc[mt][nt][half * 2 + 0];
                    float v1 = acc[mt][nt][half * 2 + 1];
                    if (bias) { v0 += bias[n]; v1 += bias[n + 1]; }
                    *(float2*)(Crow + n) = make_float2(v0, v1);
                } else if (n < N) {
                    float v0 = acc[mt][nt][half * 2 + 0];
                    if (bias) v0 += bias[n];
                    Crow[n] = v0;
                }
            }
        }
    }
}

// ==================== conversions / setup ====================
__global__ void conv_split(const float* __restrict__ src, __nv_bfloat16* __restrict__ hi,
                           __nv_bfloat16* __restrict__ lo, int M, int K, int Mpad)
{
    int idx = blockIdx.x * 256 + threadIdx.x;
    if (idx >= Mpad * K) return;
    float v;
    if (M == Mpad) {
        v = src[idx];
    } else {
        int r = idx / K;
        v = (r < M) ? src[idx] : 0.f;
    }
    __nv_bfloat16 h = __float2bfloat16(v);
    hi[idx] = h;
    lo[idx] = __float2bfloat16(v - __bfloat162float(h));
}

__global__ void conv_splitT(const float* __restrict__ src, int ldsrc,
                            __nv_bfloat16* __restrict__ hi, __nv_bfloat16* __restrict__ lo,
                            int K, int N, int Npad)
{
    __shared__ float tile[32][33];
    int n0 = blockIdx.x * 32, k0 = blockIdx.y * 32;
    int tx = threadIdx.x, ty = threadIdx.y;
#pragma unroll
    for (int i = 0; i < 32; i += 8) {
        int n = n0 + tx;
        tile[ty + i][tx] = (n < N) ? src[(size_t)(k0 + ty + i) * ldsrc + n] : 0.f;
    }
    __syncthreads();
#pragma unroll
    for (int i = 0; i < 32; i += 8) {
        int n = n0 + ty + i, k = k0 + tx;
        if (n < Npad) {
            float v = tile[tx][ty + i];
            __nv_bfloat16 h = __float2bfloat16(v);
            hi[(size_t)n * K + k] = h;
            lo[(size_t)n * K + k] = __float2bfloat16(v - __bfloat162float(h));
        }
    }
}

__global__ void pad_hall_kernel()
{
    int idx = blockIdx.x * 256 + threadIdx.x;
    if (idx >= (Mp - Mrows) * Hn) return;
    g_hallh[Mrows * Hn + idx] = __float2bfloat16(0.f);
    g_halll[Mrows * Hn + idx] = __float2bfloat16(0.f);
}

// avg pool; block 0 also zeroes step counters (runs first every replay)
__global__ void avg_kernel(const float* __restrict__ img)
{
    if (blockIdx.x == 0 && threadIdx.x < Tn) {
        g_cntA[threadIdx.x] = 0;
        g_cntB[threadIdx.x] = 0;
    }
    int idx = blockIdx.x * blockDim.x + threadIdx.x;
    if (idx >= Bsz * (Dn / 4)) return;
    int b = idx >> 9;
    const float4* ip = (const float4*)img + (size_t)b * Pn * (Dn / 4) + (idx & 511);
    float4 s = make_float4(0.f, 0.f, 0.f, 0.f);
    for (int p = 0; p < Pn; p++) {
        float4 x = ip[(size_t)p * (Dn / 4)];
        s.x += x.x; s.y += x.y; s.z += x.z; s.w += x.w;
    }
    const float inv = 1.f / (float)Pn;
    s.x *= inv; s.y *= inv; s.z *= inv; s.w *= inv;
    ((float4*)g_avg)[idx] = s;
}

__global__ void emb_kernel(const int* __restrict__ caps, const float* __restrict__ E)
{
    int idx = blockIdx.x * blockDim.x + threadIdx.x;
    if (idx >= Bsz * Tn * Hn) return;
    int r = idx / Hn;
    int h = idx - r * Hn;
    int b = r / Tn, t = r - b * Tn;
    g_emb[idx] = E[(size_t)caps[b * 20 + t] * Hn + h];
}

// ==================== init-only small GEMM (split-K) ====================
__global__ __launch_bounds__(64)
void gemm_pass(const float* A0, int lda0, const float* B0, int ldb0, float* P0, int N0, int K0, int ks0, int nt0,
               const float* A1, int lda1, const float* B1, int ldb1, float* P1, int N1, int K1, int ks1, int nt1)
{
    const float* A; const float* B; float* P;
    int N, K, ks, nt, lda, ldb;
    int id = blockIdx.x;
    int blocks0 = nt0 * ks0;
    if (id < blocks0) { A=A0; B=B0; P=P0; N=N0; K=K0; ks=ks0; nt=nt0; lda=lda0; ldb=ldb0; }
    else { id -= blocks0; A=A1; B=B1; P=P1; N=N1; K=K1; ks=ks1; nt=nt1; lda=lda1; ldb=ldb1; }

    int ntile = id % nt;
    int ksi   = id / nt;
    int kLen  = K / ks;
    int kbeg  = ksi * kLen, kend = kbeg + kLen;
    int n0    = ntile * 32;

    __shared__ float As[32][36];
    __shared__ float Bs[32][32];
    const int tid = threadIdx.x;
    const int tx = tid & 7, ty = tid >> 3;
    const int lrow = tid >> 3, lc4 = tid & 7;

    float acc[4][4];
#pragma unroll
    for (int i = 0; i < 4; i++)
#pragma unroll
        for (int j = 0; j < 4; j++) acc[i][j] = 0.f;

    for (int k0 = kbeg; k0 < kend; k0 += 32) {
#pragma unroll
        for (int i = 0; i < 4; i++)
            *(float4*)&As[lrow + 8 * i][lc4 * 4] =
                *(const float4*)(A + (size_t)(lrow + 8 * i) * lda + k0 + lc4 * 4);
#pragma unroll
        for (int i = 0; i < 4; i++)
            *(float4*)&Bs[lrow + 8 * i][lc4 * 4] =
                *(const float4*)(B + (size_t)(k0 + lrow + 8 * i) * ldb + n0 + lc4 * 4);
        __syncthreads();
#pragma unroll
        for (int kk = 0; kk < 32; kk++) {
            float a[4];
#pragma unroll
            for (int i = 0; i < 4; i++) a[i] = As[ty * 4 + i][kk];
            float4 bv = *(float4*)&Bs[kk][tx * 4];
#pragma unroll
            for (int i = 0; i < 4; i++) {
                acc[i][0] = fmaf(a[i], bv.x, acc[i][0]);
                acc[i][1] = fmaf(a[i], bv.y, acc[i][1]);
                acc[i][2] = fmaf(a[i], bv.z, acc[i][2]);
                acc[i][3] = fmaf(a[i], bv.w, acc[i][3]);
            }
        }
        __syncthreads();
    }
    float* dst = P + (size_t)ksi * 32 * N;
#pragma unroll
    for (int i = 0; i < 4; i++) {
        int m = ty * 4 + i;
#pragma unroll
        for (int j = 0; j < 4; j++)
            dst[(size_t)m * N + n0 + tx * 4 + j] = acc[i][j];
    }
}

__global__ void reduce2_kernel(float* d0, const float* P0, int ks0, int N0, const float* b0, int act0, int cnt0,
                               float* d1, const float* P1, int ks1, int N1, const float* b1, int act1, int cnt1)
{
    int i = blockIdx.x * 256 + threadIdx.x;
    float* d; const float* P; int ks, N; const float* bi; int act; int cnt;
    if (i < cnt0) { d=d0; P=P0; ks=ks0; N=N0; bi=b0; act=act0; cnt=cnt0; }
    else { i -= cnt0; d=d1; P=P1; ks=ks1; N=N1; bi=b1; act=act1; cnt=cnt1; }
    if (i >= cnt) return;
    float v = 0.f;
    for (int s = 0; s < ks; s++) v += P[(size_t)s * cnt + i];
    if (bi) v += bi[i % N];
    if (act == 1) v = tanhf(v);
    else if (act == 2) v = sigf(v);
    d[i] = v;
}

// ==================== 128-thread GEMM tile (gemm_pass3 geometry) ====================
// As: 32x68 floats, Bs: 64x36 floats (flattened). barid in [8,15].
#define TILE_FLOATS (32 * 68 + 64 * 36)         // 4480 floats
#define FA_SMEM (8 * TILE_FLOATS * 4)           // 143360 bytes

__device__ __forceinline__ void bar128(int id) {
    asm volatile("bar.sync %0, 128;" :: "r"(id) : "memory");
}

__device__ __forceinline__ void tile_gemm(
    const float* __restrict__ A, int lda, int kbeg, int kLen,
    const float* __restrict__ B, int ldb, int n0,
    float* __restrict__ P, int N,
    float* As, float* Bs, int tid, int barid)
{
    const int m = (tid >> 3) * 2;
    const int nn = (tid & 7) * 4;
    float acc[2][4];
#pragma unroll
    for (int i = 0; i < 2; i++)
#pragma unroll
        for (int j = 0; j < 4; j++) acc[i][j] = 0.f;

    for (int kb = kbeg; kb < kbeg + kLen; kb += 64) {
#pragma unroll
        for (int i = 0; i < 4; i++) {
            int fi = tid + 128 * i;
            int ar = fi >> 4, ac = (fi & 15) * 4;
            *(float4*)&As[ar * 68 + ac] = *(const float4*)(A + (size_t)ar * lda + kb + ac);
            int br = fi >> 3, bc = (fi & 7) * 4;
            *(float4*)&Bs[br * 36 + bc] = *(const float4*)(B + (size_t)(kb + br) * ldb + n0 + bc);
        }
        bar128(barid);
#pragma unroll
        for (int k = 0; k < 64; k++) {
            float a0 = As[m * 68 + k], a1 = As[(m + 1) * 68 + k];
            float4 b4 = *(float4*)&Bs[k * 36 + nn];
            acc[0][0] = fmaf(a0, b4.x, acc[0][0]); acc[0][1] = fmaf(a0, b4.y, acc[0][1]);
            acc[0][2] = fmaf(a0, b4.z, acc[0][2]); acc[0][3] = fmaf(a0, b4.w, acc[0][3]);
            acc[1][0] = fmaf(a1, b4.x, acc[1][0]); acc[1][1] = fmaf(a1, b4.y, acc[1][1]);
            acc[1][2] = fmaf(a1, b4.z, acc[1][2]); acc[1][3] = fmaf(a1, b4.w, acc[1][3]);
        }
        bar128(barid);
    }
    *(float4*)(P + (size_t)m * N + n0 + nn)       = make_float4(acc[0][0], acc[0][1], acc[0][2], acc[0][3]);
    *(float4*)(P + (size_t)(m + 1) * N + n0 + nn) = make_float4(acc[1][0], acc[1][1], acc[1][2], acc[1][3]);
}

// ==================== fused step A: pass1 tiles + attctx ====================
// blocks 0..111: 8 tiles each (tiles 0..127 hproj ks8, 128..639 fbeta ks8, 640..895 Whh ks4)
// blocks 0..79 signal cntA (hproj+fbeta); blocks 112..143: attctx for b=blk-112 (wait >= 80)
__global__ __launch_bounds__(1024)
void step_fusedA(const float* __restrict__ img,
                 const float* __restrict__ W_att_h, const float* __restrict__ W_fbeta,
                 const float* __restrict__ Whh,
                 const float* __restrict__ v_att, const float* __restrict__ b_v_att,
                 const float* __restrict__ b_att_h, const float* __restrict__ b_fbeta,
                 float* __restrict__ out_alphas, int t)
{
    extern __shared__ __align__(16) float SM[];
    const int blk = blockIdx.x, tid = threadIdx.x;

    if (blk < 112) {
        const int sub = tid >> 7, ltid = tid & 127;
        const int tile = blk * 8 + sub;
        float* As = SM + sub * TILE_FLOATS;
        float* Bs = As + 32 * 68;
        const float* B; float* P; int N, ks, id;
        if (tile < 128)      { B = W_att_h; P = g_pp_h; N = Hn;     ks = 8; id = tile; }
        else if (tile < 640) { B = W_fbeta; P = g_pp_g; N = Dn;     ks = 8; id = tile - 128; }
        else                 { B = Whh;     P = g_pb;   N = 4 * Hn; ks = 4; id = tile - 640; }
        const int nt = N / 32;
        const int ntile = id % nt, ksi = id / nt;
        const int kLen = Hn / ks;
        tile_gemm(g_h, Hn, ksi * kLen, kLen, B, N, ntile * 32,
                  P + (size_t)ksi * 32 * N, N, As, Bs, ltid, 8 + sub);
        if (blk < 80) {
            __threadfence();
            __syncthreads();
            if (tid == 0) atomicAdd(&g_cntA[t], 1);
        }
        return;
    }

    // ---- attctx consumer ----
    const int b = blk - 112;
    const int w = tid >> 5, lane = tid & 31;
    float*  hp   = SM;                          // 512
    float*  va   = SM + 512;                    // 512
    float*  ee   = SM + 1024;                   // 224
    float*  sred = SM + 1248;                   // 8
    float4* redD = (float4*)(SM + 1280);        // 1024 f4 (16KB)

    if (tid == 0) {
        while (atomicAdd(&g_cntA[t], 0) < 80) { __nanosleep(64); }
    }
    __syncthreads();
    __threadfence();

    if (tid < Hn) {
        float v = b_att_h[tid];
#pragma unroll
        for (int s = 0; s < 8; s++) v += __ldcg(&g_pp_h[s * Bsz * Hn + b * Hn + tid]);
        hp[tid] = v;
        va[tid] = v_att[tid];
    }
    __syncthreads();

    const float* ai = g_att_img + (size_t)b * Pn * Hn;
    const float bv0 = b_v_att[0];
    for (int p = w; p < Pn; p += 32) {
        const float* aip = ai + (size_t)p * Hn;
        float s = 0.f;
#pragma unroll
        for (int ii = 0; ii < Hn / 32; ii++) {
            int hx = lane + 32 * ii;
            float x = aip[hx] + hp[hx];
            float th;
            asm("tanh.approx.f32 %0, %1;" : "=f"(th) : "f"(x));
            s = fmaf(th, va[hx], s);
        }
#pragma unroll
        for (int o = 16; o; o >>= 1) s += __shfl_down_sync(0xffffffffu, s, o);
        if (lane == 0) ee[p] = s + bv0;
    }
    __syncthreads();

    float v = (tid < Pn) ? ee[tid] : -1e30f;
    if (tid < 256) {
        float m = v;
#pragma unroll
        for (int o = 16; o; o >>= 1) m = fmaxf(m, __shfl_xor_sync(0xffffffffu, m, o));
        if (lane == 0) sred[w] = m;
    }
    __syncthreads();
    if (tid < 32) {
        float mm = (tid < 8) ? sred[tid] : -1e30f;
#pragma unroll
        for (int o = 4; o; o >>= 1) mm = fmaxf(mm, __shfl_xor_sync(0xffffffffu, mm, o));
        if (tid == 0) sred[0] = mm;
    }
    __syncthreads();
    float exv = (tid < Pn) ? expf(v - sred[0]) : 0.f;
    __syncthreads();
    if (tid < 256) {
        float s = exv;
#pragma unroll
        for (int o = 16; o; o >>= 1) s += __shfl_xor_sync(0xffffffffu, s, o);
        if (lane == 0) sred[w] = s;
    }
    __syncthreads();
    if (tid < 32) {
        float ss = (tid < 8) ? sred[tid] : 0.f;
#pragma unroll
        for (int o = 4; o; o >>= 1) ss += __shfl_xor_sync(0xffffffffu, ss, o);
        if (tid == 0) sred[0] = ss;
    }
    __syncthreads();
    if (tid < Pn) {
        float a = exv / sred[0];
        ee[tid] = a;
        out_alphas[((size_t)b * Tn + t) * Pn + tid] = a;
    }
    __syncthreads();

    const int ps = tid >> 9;
    const int d4 = tid & 511;
    const float4* ip = (const float4*)img + (size_t)b * Pn * (Dn / 4) + d4;
    float4 cx = make_float4(0.f, 0.f, 0.f, 0.f);
#pragma unroll 8
    for (int p = ps; p < Pn; p += 2) {
        float a = ee[p];
        float4 x = ip[(size_t)p * (Dn / 4)];
        cx.x = fmaf(a, x.x, cx.x); cx.y = fmaf(a, x.y, cx.y);
        cx.z = fmaf(a, x.z, cx.z); cx.w = fmaf(a, x.w, cx.w);
    }
    redD[ps * (Dn / 4) + d4] = cx;
    __syncthreads();
    if (tid < Dn / 4) {
        float4 r0 = redD[tid], r1 = redD[(Dn / 4) + tid];
        float4 gb = *(const float4*)(b_fbeta + tid * 4);
#pragma unroll
        for (int sp = 0; sp < 8; sp++) {
            float4 pv = __ldcg((const float4*)g_pp_g + sp * (Bsz * Dn / 4) + b * (Dn / 4) + tid);
            gb.x += pv.x; gb.y += pv.y; gb.z += pv.z; gb.w += pv.w;
        }
        float4 o4;
        o4.x = (r0.x + r1.x) * sigf(gb.x);
        o4.y = (r0.y + r1.y) * sigf(gb.y);
        o4.z = (r0.z + r1.z) * sigf(gb.z);
        o4.w = (r0.w + r1.w) * sigf(gb.w);
        ((float4*)g_xc)[b * (Dn / 4) + tid] = o4;
    }
}

// ==================== fused step B: pass2 tiles + LSTM ====================
// blocks 0..63: 8 Wih_bot tiles each (512 tiles, ks=8, kLen=256)
// blocks 64..79: lstm elems (blk-64)*1024+tid (wait cntB == 64)
__global__ __launch_bounds__(1024)
void step_fusedB(const float* __restrict__ WihBot,
                 const float* __restrict__ bih, const float* __restrict__ bhh, int t)
{
    extern __shared__ __align__(16) float SM[];
    const int blk = blockIdx.x, tid = threadIdx.x;

    if (blk < 64) {
        const int sub = tid >> 7, ltid = tid & 127;
        const int tile = blk * 8 + sub;
        float* As = SM + sub * TILE_FLOATS;
        float* Bs = As + 32 * 68;
        const int ntile = tile & 63, ksi = tile >> 6;
        tile_gemm(g_xc, Dn, ksi * 256, 256, WihBot, 4 * Hn, ntile * 32,
                  g_pa + (size_t)ksi * 32 * 4 * Hn, 4 * Hn, As, Bs, ltid, 8 + sub);
        __threadfence();
        __syncthreads();
        if (tid == 0) atomicAdd(&g_cntB[t], 1);
        return;
    }

    if (tid == 0) {
        while (atomicAdd(&g_cntB[t], 0) < 64) { __nanosleep(64); }
    }
    __syncthreads();
    __threadfence();

    const int e = (blk - 64) * 1024 + tid;       // 0..16383
    const int b = e >> 9;
    const int j = e & 511;
    const int rowE = (b * Tn + t) * 4 * Hn;
    const int rowP = b * 4 * Hn;

    float gv[4];
#pragma unroll
    for (int g = 0; g < 4; g++) {
        int n = g * Hn + j;
        float v = g_embW[rowE + n] + bih[n] + bhh[n];
#pragma unroll
        for (int s = 0; s < 8; s++) v += __ldcg(&g_pa[s * Bsz * 4 * Hn + rowP + n]);
#pragma unroll
        for (int s = 0; s < 4; s++) v += g_pb[s * Bsz * 4 * Hn + rowP + n];
        gv[g] = v;
    }
    float c = sigf(gv[1]) * g_c[e] + sigf(gv[0]) * tanhf(gv[2]);
    g_c[e] = c;
    float h = sigf(gv[3]) * tanhf(c);
    g_h[e] = h;
    size_t ro = (size_t)(t * Bsz + b) * Hn + j;
    __nv_bfloat16 hh = __float2bfloat16(h);
    g_hallh[ro] = hh;
    g_halll[ro] = __float2bfloat16(h - __bfloat162float(hh));
}

// ================================================================================
extern "C" void kernel_launch(void* const* d_in, const int* in_sizes, int n_in,
                              void* d_out, int out_size)
{
    const float* img      = (const float*)d_in[0];
    const int*   caps     = (const int*)d_in[1];
    const float* Wih      = (const float*)d_in[2];
    const float* Whh      = (const float*)d_in[3];
    const float* bih      = (const float*)d_in[4];
    const float* bhh      = (const float*)d_in[5];
    const float* W_init_h = (const float*)d_in[6];
    const float* b_init_h = (const float*)d_in[7];
    const float* W_init_c = (const float*)d_in[8];
    const float* b_init_c = (const float*)d_in[9];
    const float* W_fbeta  = (const float*)d_in[10];
    const float* b_fbeta  = (const float*)d_in[11];
    const float* W_out    = (const float*)d_in[12];
    const float* b_out    = (const float*)d_in[13];
    const float* W_att_im = (const float*)d_in[14];
    const float* b_att_im = (const float*)d_in[15];
    const float* W_att_h  = (const float*)d_in[16];
    const float* b_att_h  = (const float*)d_in[17];
    const float* v_att    = (const float*)d_in[18];
    const float* b_v_att  = (const float*)d_in[19];
    const float* E        = (const float*)d_in[20];

    float* preds  = (float*)d_out;
    float* alphas = (float*)d_out + (size_t)Bsz * Tn * Vn;

    float *p_avg, *p_h, *p_c, *p_att, *p_emb, *p_embW, *p_pih, *p_pic;
    __nv_bfloat16 *p_imgh, *p_imgl, *p_watth, *p_wattl, *p_wouth, *p_woutl;
    __nv_bfloat16 *p_wihh, *p_wihl, *p_embh, *p_embl, *p_hallh, *p_halll;
    cudaGetSymbolAddress((void**)&p_avg,   g_avg);
    cudaGetSymbolAddress((void**)&p_h,     g_h);
    cudaGetSymbolAddress((void**)&p_c,     g_c);
    cudaGetSymbolAddress((void**)&p_att,   g_att_img);
    cudaGetSymbolAddress((void**)&p_emb,   g_emb);
    cudaGetSymbolAddress((void**)&p_embW,  g_embW);
    cudaGetSymbolAddress((void**)&p_pih,   g_pi_h);
    cudaGetSymbolAddress((void**)&p_pic,   g_pi_c);
    cudaGetSymbolAddress((void**)&p_imgh,  g_img_hi);
    cudaGetSymbolAddress((void**)&p_imgl,  g_img_lo);
    cudaGetSymbolAddress((void**)&p_watth, g_watt_hi);
    cudaGetSymbolAddress((void**)&p_wattl, g_watt_lo);
    cudaGetSymbolAddress((void**)&p_wouth, g_wout_hi);
    cudaGetSymbolAddress((void**)&p_woutl, g_wout_lo);
    cudaGetSymbolAddress((void**)&p_wihh,  g_wih_hi);
    cudaGetSymbolAddress((void**)&p_wihl,  g_wih_lo);
    cudaGetSymbolAddress((void**)&p_embh,  g_embh);
    cudaGetSymbolAddress((void**)&p_embl,  g_embl);
    cudaGetSymbolAddress((void**)&p_hallh, g_hallh);
    cudaGetSymbolAddress((void**)&p_halll, g_halll);

    cudaFuncSetAttribute(hmma_gemm<0>, cudaFuncAttributeMaxDynamicSharedMemorySize, HMMA_SMEM);
    cudaFuncSetAttribute(hmma_gemm<1>, cudaFuncAttributeMaxDynamicSharedMemorySize, HMMA_SMEM);
    cudaFuncSetAttribute(step_fusedA, cudaFuncAttributeMaxDynamicSharedMemorySize, FA_SMEM);
    cudaFuncSetAttribute(step_fusedB, cudaFuncAttributeMaxDynamicSharedMemorySize, FA_SMEM);

    // ---- setup; launch index 3 = fusedA PROBE (ncu slot; outputs = correct step-0 pp) ----
    avg_kernel<<<64, 256>>>(img);                                                                // 0 (+ counter zero)
    gemm_pass<<<256, 64>>>(p_avg, Dn, W_init_h, Hn, p_pih, Hn, Dn, 8, 16,                        // 1
                           p_avg, Dn, W_init_c, Hn, p_pic, Hn, Dn, 8, 16);
    reduce2_kernel<<<128, 256>>>(p_h, p_pih, 8, Hn, b_init_h, 1, Bsz * Hn,                       // 2
                                 p_c, p_pic, 8, Hn, b_init_c, 1, Bsz * Hn);
    step_fusedA<<<144, 1024, FA_SMEM>>>(img, W_att_h, W_fbeta, Whh,                              // 3 <- ncu
                                        v_att, b_v_att, b_att_h, b_fbeta, alphas, 0);
    conv_split<<<(Bsz * Pn * Dn) / 256, 256>>>(img, p_imgh, p_imgl, Bsz * Pn, Dn, Bsz * Pn);     // 4
    conv_splitT<<<dim3(Hn / 32, Dn / 32), dim3(32, 8)>>>(W_att_im, Hn, p_watth, p_wattl, Dn, Hn, Hn);
    hmma_gemm<0><<<dim3(Hn / 128, (Bsz * Pn) / 128), 256, HMMA_SMEM>>>(
        p_imgh, p_imgl, p_watth, p_wattl, b_att_im, p_att, Bsz * Pn, Hn, Dn, Hn);
    conv_splitT<<<dim3(Vp / 32, Hn / 32), dim3(32, 8)>>>(W_out, Vn, p_wouth, p_woutl, Hn, Vn, Vp);
    conv_splitT<<<dim3(4 * Hn / 32, Hn / 32), dim3(32, 8)>>>(Wih, 4 * Hn, p_wihh, p_wihl, Hn, 4 * Hn, 4 * Hn);
    emb_kernel<<<(Bsz * Tn * Hn) / 256, 256>>>(caps, E);
    conv_split<<<(Mp * Hn) / 256, 256>>>(p_emb, p_embh, p_embl, Mrows, Hn, Mp);
    hmma_gemm<0><<<dim3(4 * Hn / 128, Mp / 128), 256, HMMA_SMEM>>>(
        p_embh, p_embl, p_wihh, p_wihl, nullptr, p_embW, Mrows, 4 * Hn, Hn, 4 * Hn);
    pad_hall_kernel<<<((Mp - Mrows) * Hn + 255) / 256, 256>>>();

    const float* WihBot = Wih + (size_t)Hn * 4 * Hn;

    // ---- recurrent steps: 2 kernels/step ----
    for (int t = 0; t < Tn; t++) {
        step_fusedA<<<144, 1024, FA_SMEM>>>(img, W_att_h, W_fbeta, Whh,
                                            v_att, b_v_att, b_att_h, b_fbeta, alphas, t);
        step_fusedB<<<80, 1024, FA_SMEM>>>(WihBot, bih, bhh, t);
    }

    // ---- final: preds = h_all @ W_out + b_out ----
    hmma_gemm<1><<<dim3(Vp / 128, Mp / 128), 256, HMMA_SMEM>>>(
        p_hallh, p_halll, p_wouth, p_woutl, b_out, preds, Mrows, Vn, Hn, Vn);
}

// round 13
// speedup vs baseline: 1.0306x; 1.0306x over previous
#include <cuda_runtime.h>
#include <cuda_bf16.h>
#include <math.h>
#include <stdint.h>

#define Bsz 32
#define Pn  196
#define Dn  2048
#define Hn  512
#define Vn  30000
#define Tn  19
#define Vp  30080
#define Mrows 608
#define Mp  640

// ---------------- fp32 scratch ----------------
__device__ float g_avg[Bsz * Dn];
__device__ float g_h[Bsz * Hn];
__device__ float g_c[Bsz * Hn];
__device__ float g_att_img[Bsz * Pn * Hn];
__device__ float g_emb[Bsz * Tn * Hn];
__device__ float g_embW[Bsz * Tn * 4 * Hn];
__device__ float g_xc[Bsz * Dn];
__device__ float g_alpha[Bsz * Pn];
__device__ float g_watthT[Hn * Hn];              // W_att_h^T fp32
__device__ float g_pp_g[8 * Bsz * Dn];           // fbeta (ks=8)
__device__ float g_pa[8 * Bsz * 4 * Hn];         // xc@Wih_bot (ks=8)
__device__ float g_pb[4 * Bsz * 4 * Hn];         // h@Whh (ks=4)
__device__ float g_pi_h[8 * Bsz * Hn];
__device__ float g_pi_c[8 * Bsz * Hn];

// ---------------- bf16 split scratch ----------------
__device__ __nv_bfloat16 g_img_hi[Bsz * Pn * Dn];
__device__ __nv_bfloat16 g_img_lo[Bsz * Pn * Dn];
__device__ __nv_bfloat16 g_watt_hi[Hn * Dn];
__device__ __nv_bfloat16 g_watt_lo[Hn * Dn];
__device__ __nv_bfloat16 g_wout_hi[Vp * Hn];
__device__ __nv_bfloat16 g_wout_lo[Vp * Hn];
__device__ __nv_bfloat16 g_wih_hi[4 * Hn * Hn];
__device__ __nv_bfloat16 g_wih_lo[4 * Hn * Hn];
__device__ __nv_bfloat16 g_embh[Mp * Hn];
__device__ __nv_bfloat16 g_embl[Mp * Hn];
__device__ __nv_bfloat16 g_hallh[Mp * Hn];
__device__ __nv_bfloat16 g_halll[Mp * Hn];

__device__ __forceinline__ float sigf(float x) { return 1.f / (1.f + expf(-x)); }

__device__ __forceinline__ uint32_t smem_u32(const void* p) {
    uint32_t a;
    asm("{ .reg .u64 t; cvta.to.shared.u64 t, %1; cvt.u32.u64 %0, t; }" : "=r"(a) : "l"(p));
    return a;
}
__device__ __forceinline__ void ldmx4(uint32_t* r, uint32_t addr) {
    asm volatile("ldmatrix.sync.aligned.m8n8.x4.shared.b16 {%0,%1,%2,%3}, [%4];"
                 : "=r"(r[0]), "=r"(r[1]), "=r"(r[2]), "=r"(r[3]) : "r"(addr));
}
__device__ __forceinline__ void mma16816(float* d, const uint32_t* a, const uint32_t* b) {
    asm volatile(
        "mma.sync.aligned.m16n8k16.row.col.f32.bf16.bf16.f32 "
        "{%0,%1,%2,%3}, {%4,%5,%6,%7}, {%8,%9}, {%0,%1,%2,%3};"
        : "+f"(d[0]), "+f"(d[1]), "+f"(d[2]), "+f"(d[3])
        : "r"(a[0]), "r"(a[1]), "r"(a[2]), "r"(a[3]), "r"(b[0]), "r"(b[1]));
}
#define CP16(s, g)  asm volatile("cp.async.cg.shared.global [%0], [%1], 16;" :: "r"(s), "l"(g))
#define CPCOMMIT()  asm volatile("cp.async.commit_group;" ::: "memory")
#define CPWAIT1()   asm volatile("cp.async.wait_group 1;" ::: "memory")
#define CPWAIT0()   asm volatile("cp.async.wait_group 0;" ::: "memory")

// ==================== split-bf16 HMMA GEMM: 2-stage, 2 CTAs/SM ====================
#define RSB 80
#define TSZ (128 * RSB)
#define STG (4 * TSZ)
#define HMMA_SMEM (2 * STG)      // 81920

template <int OUTMAP>
__global__ __launch_bounds__(256, 2)
void hmma_gemm(const __nv_bfloat16* __restrict__ Ahi, const __nv_bfloat16* __restrict__ Alo,
               const __nv_bfloat16* __restrict__ Bhi, const __nv_bfloat16* __restrict__ Blo,
               const float* __restrict__ bias, float* __restrict__ C,
               int M, int N, int K, int ldc)
{
    extern __shared__ char smc[];
    const uint32_t sb = smem_u32(smc);
    const int tid = threadIdx.x;
    const int lane = tid & 31, wid = tid >> 5;
    const int wm = wid & 1, wn = wid >> 1;
    const int m0 = blockIdx.y * 128, n0 = blockIdx.x * 128;

    int r0 = tid >> 2, c0 = tid & 3;
    int r1 = (tid + 256) >> 2, c1 = tid & 3;
    const __nv_bfloat16* base0[4] = {
        Ahi + (size_t)(m0 + r0) * K + c0 * 8,
        Alo + (size_t)(m0 + r0) * K + c0 * 8,
        Bhi + (size_t)(n0 + r0) * K + c0 * 8,
        Blo + (size_t)(n0 + r0) * K + c0 * 8 };
    const __nv_bfloat16* base1[4] = {
        Ahi + (size_t)(m0 + r1) * K + c1 * 8,
        Alo + (size_t)(m0 + r1) * K + c1 * 8,
        Bhi + (size_t)(n0 + r1) * K + c1 * 8,
        Blo + (size_t)(n0 + r1) * K + c1 * 8 };
    const uint32_t so0 = (uint32_t)(r0 * RSB + c0 * 16);
    const uint32_t so1 = (uint32_t)(r1 * RSB + c1 * 16);

    const int arow = (lane & 7) | (((lane >> 3) & 1) << 3);
    const int akh  = lane >> 4;
    const int brow = (lane & 7) + ((lane >> 4) << 3);
    const int bkh  = (lane >> 3) & 1;

    float acc[4][4][4];
#pragma unroll
    for (int i = 0; i < 4; i++)
#pragma unroll
        for (int j = 0; j < 4; j++)
#pragma unroll
            for (int e = 0; e < 4; e++) acc[i][j][e] = 0.f;

    const int nit = K / 32;

#pragma unroll
    for (int pi = 0; pi < 2; pi++) {
        uint32_t dst = sb + pi * STG;
        int kof = pi * 32;
#pragma unroll
        for (int tno = 0; tno < 4; tno++) {
            CP16(dst + tno * TSZ + so0, base0[tno] + kof);
            CP16(dst + tno * TSZ + so1, base1[tno] + kof);
        }
        CPCOMMIT();
    }

    for (int it = 0; it < nit; it++) {
        if (it + 1 < nit) { CPWAIT1(); } else { CPWAIT0(); }
        __syncthreads();

        const uint32_t stb = sb + (it & 1) * STG;
#pragma unroll
        for (int ks = 0; ks < 2; ks++) {
            uint32_t ah[4][4], al[4][4], bh[4][2], bl[4][2];
#pragma unroll
            for (int mt = 0; mt < 4; mt++) {
                uint32_t ra = (uint32_t)((wm * 64 + mt * 16 + arow) * RSB + ks * 32 + akh * 16);
                ldmx4(ah[mt], stb + 0 * TSZ + ra);
                ldmx4(al[mt], stb + 1 * TSZ + ra);
            }
#pragma unroll
            for (int g = 0; g < 2; g++) {
                uint32_t rb = (uint32_t)((wn * 32 + g * 16 + brow) * RSB + ks * 32 + bkh * 16);
                uint32_t t0[4], t1[4];
                ldmx4(t0, stb + 2 * TSZ + rb);
                ldmx4(t1, stb + 3 * TSZ + rb);
                bh[g * 2][0] = t0[0]; bh[g * 2][1] = t0[1];
                bh[g * 2 + 1][0] = t0[2]; bh[g * 2 + 1][1] = t0[3];
                bl[g * 2][0] = t1[0]; bl[g * 2][1] = t1[1];
                bl[g * 2 + 1][0] = t1[2]; bl[g * 2 + 1][1] = t1[3];
            }
#pragma unroll
            for (int mt = 0; mt < 4; mt++)
#pragma unroll
                for (int nt = 0; nt < 4; nt++) {
                    mma16816(acc[mt][nt], ah[mt], bh[nt]);
                    mma16816(acc[mt][nt], ah[mt], bl[nt]);
                    mma16816(acc[mt][nt], al[mt], bh[nt]);
                }
        }
        __syncthreads();

        if (it + 2 < nit) {
            uint32_t dst = sb + (it & 1) * STG;
            int kof = (it + 2) * 32;
#pragma unroll
            for (int tno = 0; tno < 4; tno++) {
                CP16(dst + tno * TSZ + so0, base0[tno] + kof);
                CP16(dst + tno * TSZ + so1, base1[tno] + kof);
            }
            CPCOMMIT();
        }
    }

#pragma unroll
    for (int mt = 0; mt < 4; mt++) {
#pragma unroll
        for (int half = 0; half < 2; half++) {
            int r = m0 + wm * 64 + mt * 16 + (lane >> 2) + half * 8;
            bool rowok; float* Crow;
            if (OUTMAP) {
                int ob = r & 31, ot = r >> 5;
                rowok = (ot < Tn);
                Crow = C + (size_t)(ob * Tn + ot) * ldc;
            } else {
                rowok = (r < M);
                Crow = C + (size_t)r * ldc;
            }
            if (!rowok) continue;
#pragma unroll
            for (int nt = 0; nt < 4; nt++) {
                int n = n0 + wn * 32 + nt * 8 + (lane & 3) * 2;
                if (n + 1 < N) {
                    float v0 = acc[mt][nt][half * 2 + 0];
                    float v1 = acc[mt][nt][half * 2 + 1];
                    if (bias) { v0 += bias[n]; v1 += bias[n + 1]; }
                    *(float2*)(Crow + n) = make_float2(v0, v1);
                } else if (n < N) {
                    float v0 = acc[mt][nt][half * 2 + 0];
                    if (bias) v0 += bias[n];
                    Crow[n] = v0;
                }
            }
        }
    }
}

// ==================== conversions / setup ====================
__global__ void conv_split(const float* __restrict__ src, __nv_bfloat16* __restrict__ hi,
                           __nv_bfloat16* __restrict__ lo, int M, int K, int Mpad)
{
    int idx = blockIdx.x * 256 + threadIdx.x;
    if (idx >= Mpad * K) return;
    float v;
    if (M == Mpad) {
        v = src[idx];
    } else {
        int r = idx / K;
        v = (r < M) ? src[idx] : 0.f;
    }
    __nv_bfloat16 h = __float2bfloat16(v);
    hi[idx] = h;
    lo[idx] = __float2bfloat16(v - __bfloat162float(h));
}

__global__ void conv_splitT(const float* __restrict__ src, int ldsrc,
                            __nv_bfloat16* __restrict__ hi, __nv_bfloat16* __restrict__ lo,
                            int K, int N, int Npad)
{
    __shared__ float tile[32][33];
    int n0 = blockIdx.x * 32, k0 = blockIdx.y * 32;
    int tx = threadIdx.x, ty = threadIdx.y;
#pragma unroll
    for (int i = 0; i < 32; i += 8) {
        int n = n0 + tx;
        tile[ty + i][tx] = (n < N) ? src[(size_t)(k0 + ty + i) * ldsrc + n] : 0.f;
    }
    __syncthreads();
#pragma unroll
    for (int i = 0; i < 32; i += 8) {
        int n = n0 + ty + i, k = k0 + tx;
        if (n < Npad) {
            float v = tile[tx][ty + i];
            __nv_bfloat16 h = __float2bfloat16(v);
            hi[(size_t)n * K + k] = h;
            lo[(size_t)n * K + k] = __float2bfloat16(v - __bfloat162float(h));
        }
    }
}

__global__ void pad_hall_kernel()
{
    int idx = blockIdx.x * 256 + threadIdx.x;
    if (idx >= (Mp - Mrows) * Hn) return;
    g_hallh[Mrows * Hn + idx] = __float2bfloat16(0.f);
    g_halll[Mrows * Hn + idx] = __float2bfloat16(0.f);
}

// avg pool (blocks 0..63) + W_att_h transpose fp32 (blocks 64..71)
__global__ void avg_kernel(const float* __restrict__ img, const float* __restrict__ W_att_h)
{
    if (blockIdx.x >= 64) {
        int base = (blockIdx.x - 64) * 32768;
        for (int e = 0; e < 128; e++) {
            int idx = base + e * 256 + threadIdx.x;
            int r = idx >> 9, c = idx & 511;
            g_watthT[c * Hn + r] = W_att_h[idx];
        }
        return;
    }
    int idx = blockIdx.x * blockDim.x + threadIdx.x;
    if (idx >= Bsz * (Dn / 4)) return;
    int b = idx >> 9;
    const float4* ip = (const float4*)img + (size_t)b * Pn * (Dn / 4) + (idx & 511);
    float4 s = make_float4(0.f, 0.f, 0.f, 0.f);
    for (int p = 0; p < Pn; p++) {
        float4 x = ip[(size_t)p * (Dn / 4)];
        s.x += x.x; s.y += x.y; s.z += x.z; s.w += x.w;
    }
    const float inv = 1.f / (float)Pn;
    s.x *= inv; s.y *= inv; s.z *= inv; s.w *= inv;
    ((float4*)g_avg)[idx] = s;
}

__global__ void emb_kernel(const int* __restrict__ caps, const float* __restrict__ E)
{
    int idx = blockIdx.x * blockDim.x + threadIdx.x;
    if (idx >= Bsz * Tn * Hn) return;
    int r = idx / Hn;
    int h = idx - r * Hn;
    int b = r / Tn, t = r - b * Tn;
    g_emb[idx] = E[(size_t)caps[b * 20 + t] * Hn + h];
}

// ==================== init-only small GEMM (split-K) ====================
__global__ __launch_bounds__(64)
void gemm_pass(const float* A0, int lda0, const float* B0, int ldb0, float* P0, int N0, int K0, int ks0, int nt0,
               const float* A1, int lda1, const float* B1, int ldb1, float* P1, int N1, int K1, int ks1, int nt1)
{
    const float* A; const float* B; float* P;
    int N, K, ks, nt, lda, ldb;
    int id = blockIdx.x;
    int blocks0 = nt0 * ks0;
    if (id < blocks0) { A=A0; B=B0; P=P0; N=N0; K=K0; ks=ks0; nt=nt0; lda=lda0; ldb=ldb0; }
    else { id -= blocks0; A=A1; B=B1; P=P1; N=N1; K=K1; ks=ks1; nt=nt1; lda=lda1; ldb=ldb1; }

    int ntile = id % nt;
    int ksi   = id / nt;
    int kLen  = K / ks;
    int kbeg  = ksi * kLen, kend = kbeg + kLen;
    int n0    = ntile * 32;

    __shared__ float As[32][36];
    __shared__ float Bs[32][32];
    const int tid = threadIdx.x;
    const int tx = tid & 7, ty = tid >> 3;
    const int lrow = tid >> 3, lc4 = tid & 7;

    float acc[4][4];
#pragma unroll
    for (int i = 0; i < 4; i++)
#pragma unroll
        for (int j = 0; j < 4; j++) acc[i][j] = 0.f;

    for (int k0 = kbeg; k0 < kend; k0 += 32) {
#pragma unroll
        for (int i = 0; i < 4; i++)
            *(float4*)&As[lrow + 8 * i][lc4 * 4] =
                *(const float4*)(A + (size_t)(lrow + 8 * i) * lda + k0 + lc4 * 4);
#pragma unroll
        for (int i = 0; i < 4; i++)
            *(float4*)&Bs[lrow + 8 * i][lc4 * 4] =
                *(const float4*)(B + (size_t)(k0 + lrow + 8 * i) * ldb + n0 + lc4 * 4);
        __syncthreads();
#pragma unroll
        for (int kk = 0; kk < 32; kk++) {
            float a[4];
#pragma unroll
            for (int i = 0; i < 4; i++) a[i] = As[ty * 4 + i][kk];
            float4 bv = *(float4*)&Bs[kk][tx * 4];
#pragma unroll
            for (int i = 0; i < 4; i++) {
                acc[i][0] = fmaf(a[i], bv.x, acc[i][0]);
                acc[i][1] = fmaf(a[i], bv.y, acc[i][1]);
                acc[i][2] = fmaf(a[i], bv.z, acc[i][2]);
                acc[i][3] = fmaf(a[i], bv.w, acc[i][3]);
            }
        }
        __syncthreads();
    }
    float* dst = P + (size_t)ksi * 32 * N;
#pragma unroll
    for (int i = 0; i < 4; i++) {
        int m = ty * 4 + i;
#pragma unroll
        for (int j = 0; j < 4; j++)
            dst[(size_t)m * N + n0 + tx * 4 + j] = acc[i][j];
    }
}

__global__ void reduce2_kernel(float* d0, const float* P0, int ks0, int N0, const float* b0, int act0, int cnt0,
                               float* d1, const float* P1, int ks1, int N1, const float* b1, int act1, int cnt1)
{
    int i = blockIdx.x * 256 + threadIdx.x;
    float* d; const float* P; int ks, N; const float* bi; int act; int cnt;
    if (i < cnt0) { d=d0; P=P0; ks=ks0; N=N0; bi=b0; act=act0; cnt=cnt0; }
    else { i -= cnt0; d=d1; P=P1; ks=ks1; N=N1; bi=b1; act=act1; cnt=cnt1; }
    if (i >= cnt) return;
    float v = 0.f;
    for (int s = 0; s < ks; s++) v += P[(size_t)s * cnt + i];
    if (bi) v += bi[i % N];
    if (act == 1) v = tanhf(v);
    else if (act == 2) v = sigf(v);
    d[i] = v;
}

// ==================== 128-thread GEMM tile (proven in R12) ====================
#define TILE_FLOATS (32 * 68 + 64 * 36)         // 4480 floats
#define S1_SMEM (8 * TILE_FLOATS * 4)           // 143360 bytes

__device__ __forceinline__ void bar128(int id) {
    asm volatile("bar.sync %0, 128;" :: "r"(id) : "memory");
}

__device__ __forceinline__ void tile_gemm(
    const float* __restrict__ A, int lda, int kbeg, int kLen,
    const float* __restrict__ B, int ldb, int n0,
    float* __restrict__ P, int N,
    float* As, float* Bs, int tid, int barid)
{
    const int m = (tid >> 3) * 2;
    const int nn = (tid & 7) * 4;
    float acc[2][4];
#pragma unroll
    for (int i = 0; i < 2; i++)
#pragma unroll
        for (int j = 0; j < 4; j++) acc[i][j] = 0.f;

    for (int kb = kbeg; kb < kbeg + kLen; kb += 64) {
#pragma unroll
        for (int i = 0; i < 4; i++) {
            int fi = tid + 128 * i;
            int ar = fi >> 4, ac = (fi & 15) * 4;
            *(float4*)&As[ar * 68 + ac] = *(const float4*)(A + (size_t)ar * lda + kb + ac);
            int br = fi >> 3, bc = (fi & 7) * 4;
            *(float4*)&Bs[br * 36 + bc] = *(const float4*)(B + (size_t)(kb + br) * ldb + n0 + bc);
        }
        bar128(barid);
#pragma unroll
        for (int k = 0; k < 64; k++) {
            float a0 = As[m * 68 + k], a1 = As[(m + 1) * 68 + k];
            float4 b4 = *(float4*)&Bs[k * 36 + nn];
            acc[0][0] = fmaf(a0, b4.x, acc[0][0]); acc[0][1] = fmaf(a0, b4.y, acc[0][1]);
            acc[0][2] = fmaf(a0, b4.z, acc[0][2]); acc[0][3] = fmaf(a0, b4.w, acc[0][3]);
            acc[1][0] = fmaf(a1, b4.x, acc[1][0]); acc[1][1] = fmaf(a1, b4.y, acc[1][1]);
            acc[1][2] = fmaf(a1, b4.z, acc[1][2]); acc[1][3] = fmaf(a1, b4.w, acc[1][3]);
        }
        bar128(barid);
    }
    *(float4*)(P + (size_t)m * N + n0 + nn)       = make_float4(acc[0][0], acc[0][1], acc[0][2], acc[0][3]);
    *(float4*)(P + (size_t)(m + 1) * N + n0 + nn) = make_float4(acc[1][0], acc[1][1], acc[1][2], acc[1][3]);
}

// ==================== step node 1: independent h-consumers, NO sync ====================
// blocks 0..31  : attsm for b=blk (hproj matvec + scores + softmax -> g_alpha, out_alphas)
// blocks 32..95 : fbeta tiles (512, ks=8, kLen=64)
// blocks 96..127: Whh tiles (256, ks=4, kLen=128)
__global__ __launch_bounds__(1024)
void step1_kernel(const float* __restrict__ W_fbeta, const float* __restrict__ Whh,
                  const float* __restrict__ v_att, const float* __restrict__ b_v_att,
                  const float* __restrict__ b_att_h, float* __restrict__ out_alphas, int t)
{
    extern __shared__ __align__(16) float SM[];
    const int blk = blockIdx.x, tid = threadIdx.x;

    if (blk >= 32) {
        const int sub = tid >> 7, ltid = tid & 127;
        float* As = SM + sub * TILE_FLOATS;
        float* Bs = As + 32 * 68;
        if (blk < 96) {
            const int tile = (blk - 32) * 8 + sub;        // 0..511
            const int ntile = tile & 63, ksi = tile >> 6; // nt=64, ks=8
            tile_gemm(g_h, Hn, ksi * 64, 64, W_fbeta, Dn, ntile * 32,
                      g_pp_g + (size_t)ksi * 32 * Dn, Dn, As, Bs, ltid, 8 + sub);
        } else {
            const int tile = (blk - 96) * 8 + sub;        // 0..255
            const int ntile = tile & 63, ksi = tile >> 6; // nt=64, ks=4
            tile_gemm(g_h, Hn, ksi * 128, 128, Whh, 4 * Hn, ntile * 32,
                      g_pb + (size_t)ksi * 32 * 4 * Hn, 4 * Hn, As, Bs, ltid, 8 + sub);
        }
        return;
    }

    // ---- attsm for b = blk ----
    const int b = blk;
    const int w = tid >> 5, lane = tid & 31;
    float* hs   = SM;             // 512
    float* hp   = SM + 512;       // 512
    float* va   = SM + 1024;      // 512
    float* ee   = SM + 1536;      // 224
    float* sred = SM + 1760;      // 8

    if (tid < Hn) {
        hs[tid] = g_h[b * Hn + tid];
        va[tid] = v_att[tid];
    }
    __syncthreads();

    // hproj: warp w computes j = w*16 .. w*16+15 via W_att_h^T rows
#pragma unroll
    for (int jj = 0; jj < 16; jj++) {
        int j = w * 16 + jj;
        const float* wt = g_watthT + (size_t)j * Hn;
        float s = 0.f;
#pragma unroll
        for (int i = 0; i < 16; i++) {
            int k = lane + 32 * i;
            s = fmaf(hs[k], wt[k], s);
        }
#pragma unroll
        for (int o = 16; o; o >>= 1) s += __shfl_down_sync(0xffffffffu, s, o);
        if (lane == 0) hp[j] = s + b_att_h[j];
    }
    __syncthreads();

    // scores
    const float* ai = g_att_img + (size_t)b * Pn * Hn;
    const float bv0 = b_v_att[0];
    for (int p = w; p < Pn; p += 32) {
        const float* aip = ai + (size_t)p * Hn;
        float s = 0.f;
#pragma unroll
        for (int ii = 0; ii < Hn / 32; ii++) {
            int hx = lane + 32 * ii;
            float x = aip[hx] + hp[hx];
            float th;
            asm("tanh.approx.f32 %0, %1;" : "=f"(th) : "f"(x));
            s = fmaf(th, va[hx], s);
        }
#pragma unroll
        for (int o = 16; o; o >>= 1) s += __shfl_down_sync(0xffffffffu, s, o);
        if (lane == 0) ee[p] = s + bv0;
    }
    __syncthreads();

    // softmax over P=196
    float v = (tid < Pn) ? ee[tid] : -1e30f;
    if (tid < 256) {
        float m = v;
#pragma unroll
        for (int o = 16; o; o >>= 1) m = fmaxf(m, __shfl_xor_sync(0xffffffffu, m, o));
        if (lane == 0) sred[w] = m;
    }
    __syncthreads();
    if (tid < 32) {
        float mm = (tid < 8) ? sred[tid] : -1e30f;
#pragma unroll
        for (int o = 4; o; o >>= 1) mm = fmaxf(mm, __shfl_xor_sync(0xffffffffu, mm, o));
        if (tid == 0) sred[0] = mm;
    }
    __syncthreads();
    float exv = (tid < Pn) ? expf(v - sred[0]) : 0.f;
    __syncthreads();
    if (tid < 256) {
        float s = exv;
#pragma unroll
        for (int o = 16; o; o >>= 1) s += __shfl_xor_sync(0xffffffffu, s, o);
        if (lane == 0) sred[w] = s;
    }
    __syncthreads();
    if (tid < 32) {
        float ss = (tid < 8) ? sred[tid] : 0.f;
#pragma unroll
        for (int o = 4; o; o >>= 1) ss += __shfl_xor_sync(0xffffffffu, ss, o);
        if (tid == 0) sred[0] = ss;
    }
    __syncthreads();
    if (tid < Pn) {
        float a = exv / sred[0];
        g_alpha[b * Pn + tid] = a;
        out_alphas[((size_t)b * Tn + t) * Pn + tid] = a;
    }
}

// ==================== step node 2: context + gate -> xc (256 blocks x 256) ====
__global__ __launch_bounds__(256)
void ctx_kernel(const float* __restrict__ img, const float* __restrict__ b_fbeta)
{
    const int blk = blockIdx.x, tid = threadIdx.x;
    const int b = blk >> 3, sl = blk & 7;
    __shared__ float sal[200];
    __shared__ __align__(16) float4 red[4][64];

    if (tid < Pn) sal[tid] = g_alpha[b * Pn + tid];
    __syncthreads();

    const int dl = tid & 63, pg = tid >> 6;          // 64 cols x 4 p-groups
    const int d4 = sl * 64 + dl;
    const float4* ip = (const float4*)img + (size_t)b * Pn * (Dn / 4) + d4;
    float4 cx = make_float4(0.f, 0.f, 0.f, 0.f);
#pragma unroll 8
    for (int p = pg; p < Pn; p += 4) {
        float a = sal[p];
        float4 x = ip[(size_t)p * (Dn / 4)];
        cx.x = fmaf(a, x.x, cx.x); cx.y = fmaf(a, x.y, cx.y);
        cx.z = fmaf(a, x.z, cx.z); cx.w = fmaf(a, x.w, cx.w);
    }
    red[pg][dl] = cx;
    __syncthreads();
    if (tid < 64) {
        float4 r0 = red[0][tid], r1 = red[1][tid], r2 = red[2][tid], r3 = red[3][tid];
        float4 sum = make_float4(r0.x + r1.x + r2.x + r3.x, r0.y + r1.y + r2.y + r3.y,
                                 r0.z + r1.z + r2.z + r3.z, r0.w + r1.w + r2.w + r3.w);
        int dd = sl * 64 + tid;
        float4 gb = ((const float4*)b_fbeta)[dd];
#pragma unroll
        for (int sp = 0; sp < 8; sp++) {
            float4 pv = ((const float4*)g_pp_g)[sp * (Bsz * Dn / 4) + b * (Dn / 4) + dd];
            gb.x += pv.x; gb.y += pv.y; gb.z += pv.z; gb.w += pv.w;
        }
        sum.x *= sigf(gb.x); sum.y *= sigf(gb.y);
        sum.z *= sigf(gb.z); sum.w *= sigf(gb.w);
        ((float4*)g_xc)[b * (Dn / 4) + dd] = sum;
    }
}

// ==================== step node 3: pass2 GEMM (proven gemm_pass3, 1 segment) ====
__global__ __launch_bounds__(128)
void gemm_pass3(const float* A0, int lda0, const float* B0, int ldb0, float* P0, int N0, int K0, int ks0)
{
    const int nt = N0 / 32;
    const int ntile = blockIdx.x % nt, ksi = blockIdx.x / nt;
    const int kLen = K0 / ks0;
    const int kbeg = ksi * kLen;
    const int n0 = ntile * 32;

    __shared__ __align__(16) float As[32][68];
    __shared__ __align__(16) float Bs[64][36];

    const int tid = threadIdx.x;
    const int m = (tid >> 3) * 2;
    const int nn = (tid & 7) * 4;

    float acc[2][4];
#pragma unroll
    for (int i = 0; i < 2; i++)
#pragma unroll
        for (int j = 0; j < 4; j++) acc[i][j] = 0.f;

    for (int kb = kbeg; kb < kbeg + kLen; kb += 64) {
#pragma unroll
        for (int i = 0; i < 4; i++) {
            int fi = tid + 128 * i;
            int ar = fi >> 4, ac = (fi & 15) * 4;
            *(float4*)&As[ar][ac] = *(const float4*)(A0 + (size_t)ar * lda0 + kb + ac);
            int br = fi >> 3, bc = (fi & 7) * 4;
            *(float4*)&Bs[br][bc] = *(const float4*)(B0 + (size_t)(kb + br) * ldb0 + n0 + bc);
        }
        __syncthreads();
#pragma unroll
        for (int k = 0; k < 64; k++) {
            float a0 = As[m][k], a1 = As[m + 1][k];
            float4 b4 = *(float4*)&Bs[k][nn];
            acc[0][0] = fmaf(a0, b4.x, acc[0][0]); acc[0][1] = fmaf(a0, b4.y, acc[0][1]);
            acc[0][2] = fmaf(a0, b4.z, acc[0][2]); acc[0][3] = fmaf(a0, b4.w, acc[0][3]);
            acc[1][0] = fmaf(a1, b4.x, acc[1][0]); acc[1][1] = fmaf(a1, b4.y, acc[1][1]);
            acc[1][2] = fmaf(a1, b4.z, acc[1][2]); acc[1][3] = fmaf(a1, b4.w, acc[1][3]);
        }
        __syncthreads();
    }

    float* dst = P0 + (size_t)ksi * 32 * N0 + n0;
    *(float4*)(dst + (size_t)m * N0 + nn)       = make_float4(acc[0][0], acc[0][1], acc[0][2], acc[0][3]);
    *(float4*)(dst + (size_t)(m + 1) * N0 + nn) = make_float4(acc[1][0], acc[1][1], acc[1][2], acc[1][3]);
}

// ==================== step node 4: LSTM pointwise ====================
__global__ void lstm_kernel(const float* __restrict__ bih, const float* __restrict__ bhh, int t)
{
    int idx = blockIdx.x * blockDim.x + threadIdx.x;
    if (idx >= Bsz * Hn) return;
    int b = idx >> 9;
    int j = idx & 511;
    int rowE = (b * Tn + t) * 4 * Hn;
    int rowP = b * 4 * Hn;

    float gv[4];
#pragma unroll
    for (int g = 0; g < 4; g++) {
        int n = g * Hn + j;
        float v = g_embW[rowE + n] + bih[n] + bhh[n];
#pragma unroll
        for (int s = 0; s < 8; s++) v += g_pa[s * Bsz * 4 * Hn + rowP + n];
#pragma unroll
        for (int s = 0; s < 4; s++) v += g_pb[s * Bsz * 4 * Hn + rowP + n];
        gv[g] = v;
    }
    float c = sigf(gv[1]) * g_c[idx] + sigf(gv[0]) * tanhf(gv[2]);
    g_c[idx] = c;
    float h = sigf(gv[3]) * tanhf(c);
    g_h[idx] = h;
    size_t ro = (size_t)(t * Bsz + b) * Hn + j;
    __nv_bfloat16 hh = __float2bfloat16(h);
    g_hallh[ro] = hh;
    g_halll[ro] = __float2bfloat16(h - __bfloat162float(hh));
}

// ================================================================================
extern "C" void kernel_launch(void* const* d_in, const int* in_sizes, int n_in,
                              void* d_out, int out_size)
{
    const float* img      = (const float*)d_in[0];
    const int*   caps     = (const int*)d_in[1];
    const float* Wih      = (const float*)d_in[2];
    const float* Whh      = (const float*)d_in[3];
    const float* bih      = (const float*)d_in[4];
    const float* bhh      = (const float*)d_in[5];
    const float* W_init_h = (const float*)d_in[6];
    const float* b_init_h = (const float*)d_in[7];
    const float* W_init_c = (const float*)d_in[8];
    const float* b_init_c = (const float*)d_in[9];
    const float* W_fbeta  = (const float*)d_in[10];
    const float* b_fbeta  = (const float*)d_in[11];
    const float* W_out    = (const float*)d_in[12];
    const float* b_out    = (const float*)d_in[13];
    const float* W_att_im = (const float*)d_in[14];
    const float* b_att_im = (const float*)d_in[15];
    const float* W_att_h  = (const float*)d_in[16];
    const float* b_att_h  = (const float*)d_in[17];
    const float* v_att    = (const float*)d_in[18];
    const float* b_v_att  = (const float*)d_in[19];
    const float* E        = (const float*)d_in[20];

    float* preds  = (float*)d_out;
    float* alphas = (float*)d_out + (size_t)Bsz * Tn * Vn;

    float *p_avg, *p_h, *p_c, *p_att, *p_emb, *p_embW, *p_xc, *p_pih, *p_pic, *p_pa;
    __nv_bfloat16 *p_imgh, *p_imgl, *p_watth, *p_wattl, *p_wouth, *p_woutl;
    __nv_bfloat16 *p_wihh, *p_wihl, *p_embh, *p_embl, *p_hallh, *p_halll;
    cudaGetSymbolAddress((void**)&p_avg,   g_avg);
    cudaGetSymbolAddress((void**)&p_h,     g_h);
    cudaGetSymbolAddress((void**)&p_c,     g_c);
    cudaGetSymbolAddress((void**)&p_att,   g_att_img);
    cudaGetSymbolAddress((void**)&p_emb,   g_emb);
    cudaGetSymbolAddress((void**)&p_embW,  g_embW);
    cudaGetSymbolAddress((void**)&p_xc,    g_xc);
    cudaGetSymbolAddress((void**)&p_pih,   g_pi_h);
    cudaGetSymbolAddress((void**)&p_pic,   g_pi_c);
    cudaGetSymbolAddress((void**)&p_pa,    g_pa);
    cudaGetSymbolAddress((void**)&p_imgh,  g_img_hi);
    cudaGetSymbolAddress((void**)&p_imgl,  g_img_lo);
    cudaGetSymbolAddress((void**)&p_watth, g_watt_hi);
    cudaGetSymbolAddress((void**)&p_wattl, g_watt_lo);
    cudaGetSymbolAddress((void**)&p_wouth, g_wout_hi);
    cudaGetSymbolAddress((void**)&p_woutl, g_wout_lo);
    cudaGetSymbolAddress((void**)&p_wihh,  g_wih_hi);
    cudaGetSymbolAddress((void**)&p_wihl,  g_wih_lo);
    cudaGetSymbolAddress((void**)&p_embh,  g_embh);
    cudaGetSymbolAddress((void**)&p_embl,  g_embl);
    cudaGetSymbolAddress((void**)&p_hallh, g_hallh);
    cudaGetSymbolAddress((void**)&p_halll, g_halll);

    cudaFuncSetAttribute(hmma_gemm<0>, cudaFuncAttributeMaxDynamicSharedMemorySize, HMMA_SMEM);
    cudaFuncSetAttribute(hmma_gemm<1>, cudaFuncAttributeMaxDynamicSharedMemorySize, HMMA_SMEM);
    cudaFuncSetAttribute(step1_kernel, cudaFuncAttributeMaxDynamicSharedMemorySize, S1_SMEM);

    // ---- setup; launch index 3 = step1 PROBE (ncu slot; pp_g/pb outputs valid for t=0) ----
    avg_kernel<<<72, 256>>>(img, W_att_h);                                                       // 0 (+ W_att_h^T)
    gemm_pass<<<256, 64>>>(p_avg, Dn, W_init_h, Hn, p_pih, Hn, Dn, 8, 16,                        // 1
                           p_avg, Dn, W_init_c, Hn, p_pic, Hn, Dn, 8, 16);
    reduce2_kernel<<<128, 256>>>(p_h, p_pih, 8, Hn, b_init_h, 1, Bsz * Hn,                       // 2
                                 p_c, p_pic, 8, Hn, b_init_c, 1, Bsz * Hn);
    step1_kernel<<<128, 1024, S1_SMEM>>>(W_fbeta, Whh, v_att, b_v_att, b_att_h, alphas, 0);      // 3 <- ncu
    conv_split<<<(Bsz * Pn * Dn) / 256, 256>>>(img, p_imgh, p_imgl, Bsz * Pn, Dn, Bsz * Pn);     // 4
    conv_splitT<<<dim3(Hn / 32, Dn / 32), dim3(32, 8)>>>(W_att_im, Hn, p_watth, p_wattl, Dn, Hn, Hn);
    hmma_gemm<0><<<dim3(Hn / 128, (Bsz * Pn) / 128), 256, HMMA_SMEM>>>(
        p_imgh, p_imgl, p_watth, p_wattl, b_att_im, p_att, Bsz * Pn, Hn, Dn, Hn);
    conv_splitT<<<dim3(Vp / 32, Hn / 32), dim3(32, 8)>>>(W_out, Vn, p_wouth, p_woutl, Hn, Vn, Vp);
    conv_splitT<<<dim3(4 * Hn / 32, Hn / 32), dim3(32, 8)>>>(Wih, 4 * Hn, p_wihh, p_wihl, Hn, 4 * Hn, 4 * Hn);
    emb_kernel<<<(Bsz * Tn * Hn) / 256, 256>>>(caps, E);
    conv_split<<<(Mp * Hn) / 256, 256>>>(p_emb, p_embh, p_embl, Mrows, Hn, Mp);
    hmma_gemm<0><<<dim3(4 * Hn / 128, Mp / 128), 256, HMMA_SMEM>>>(
        p_embh, p_embl, p_wihh, p_wihl, nullptr, p_embW, Mrows, 4 * Hn, Hn, 4 * Hn);
    pad_hall_kernel<<<((Mp - Mrows) * Hn + 255) / 256, 256>>>();

    const float* WihBot = Wih + (size_t)Hn * 4 * Hn;

    // ---- recurrent steps: 4 nodes/step, no intra-kernel sync ----
    for (int t = 0; t < Tn; t++) {
        step1_kernel<<<128, 1024, S1_SMEM>>>(W_fbeta, Whh, v_att, b_v_att, b_att_h, alphas, t);
        ctx_kernel<<<256, 256>>>(img, b_fbeta);
        gemm_pass3<<<512, 128>>>(p_xc, Dn, WihBot, 4 * Hn, p_pa, 4 * Hn, Dn, 8);
        lstm_kernel<<<(Bsz * Hn) / 256, 256>>>(bih, bhh, t);
    }

    // ---- final: preds = h_all @ W_out + b_out ----
    hmma_gemm<1><<<dim3(Vp / 128, Mp / 128), 256, HMMA_SMEM>>>(
        p_hallh, p_halll, p_wouth, p_woutl, b_out, preds, Mrows, Vn, Hn, Vn);
}

// round 14
// speedup vs baseline: 1.2206x; 1.1843x over previous
#include <cuda_runtime.h>
#include <cuda_bf16.h>
#include <math.h>
#include <stdint.h>

#define Bsz 32
#define Pn  196
#define Dn  2048
#define Hn  512
#define Vn  30000
#define Tn  19
#define Vp  30080
#define Mrows 608
#define Mp  640

// ---------------- fp32 scratch ----------------
__device__ float g_avg[Bsz * Dn];
__device__ float g_h[Bsz * Hn];
__device__ float g_c[Bsz * Hn];
__device__ float g_att_img[Bsz * Pn * Hn];
__device__ float g_emb[Bsz * Tn * Hn];
__device__ float g_embW[Bsz * Tn * 4 * Hn];
__device__ float g_xc[Bsz * Dn];
__device__ float g_pp_h[8 * Bsz * Hn];           // hproj (ks=8)
__device__ float g_pp_g[8 * Bsz * Dn];           // fbeta (ks=8)
__device__ float g_pa[8 * Bsz * 4 * Hn];         // xc@Wih_bot (ks=8)
__device__ float g_pb[4 * Bsz * 4 * Hn];         // h@Whh (ks=4)
__device__ float g_pi_h[8 * Bsz * Hn];
__device__ float g_pi_c[8 * Bsz * Hn];

// ---------------- bf16 split scratch ----------------
__device__ __nv_bfloat16 g_img_hi[Bsz * Pn * Dn];
__device__ __nv_bfloat16 g_img_lo[Bsz * Pn * Dn];
__device__ __nv_bfloat16 g_watt_hi[Hn * Dn];
__device__ __nv_bfloat16 g_watt_lo[Hn * Dn];
__device__ __nv_bfloat16 g_wout_hi[Vp * Hn];
__device__ __nv_bfloat16 g_wout_lo[Vp * Hn];
__device__ __nv_bfloat16 g_wih_hi[4 * Hn * Hn];
__device__ __nv_bfloat16 g_wih_lo[4 * Hn * Hn];
__device__ __nv_bfloat16 g_embh[Mp * Hn];
__device__ __nv_bfloat16 g_embl[Mp * Hn];
__device__ __nv_bfloat16 g_hallh[Mp * Hn];
__device__ __nv_bfloat16 g_halll[Mp * Hn];

__device__ __forceinline__ float sigf(float x) { return 1.f / (1.f + expf(-x)); }

__device__ __forceinline__ uint32_t smem_u32(const void* p) {
    uint32_t a;
    asm("{ .reg .u64 t; cvta.to.shared.u64 t, %1; cvt.u32.u64 %0, t; }" : "=r"(a) : "l"(p));
    return a;
}
__device__ __forceinline__ void ldmx4(uint32_t* r, uint32_t addr) {
    asm volatile("ldmatrix.sync.aligned.m8n8.x4.shared.b16 {%0,%1,%2,%3}, [%4];"
                 : "=r"(r[0]), "=r"(r[1]), "=r"(r[2]), "=r"(r[3]) : "r"(addr));
}
__device__ __forceinline__ void mma16816(float* d, const uint32_t* a, const uint32_t* b) {
    asm volatile(
        "mma.sync.aligned.m16n8k16.row.col.f32.bf16.bf16.f32 "
        "{%0,%1,%2,%3}, {%4,%5,%6,%7}, {%8,%9}, {%0,%1,%2,%3};"
        : "+f"(d[0]), "+f"(d[1]), "+f"(d[2]), "+f"(d[3])
        : "r"(a[0]), "r"(a[1]), "r"(a[2]), "r"(a[3]), "r"(b[0]), "r"(b[1]));
}
#define CP16(s, g)  asm volatile("cp.async.cg.shared.global [%0], [%1], 16;" :: "r"(s), "l"(g))
#define CPCOMMIT()  asm volatile("cp.async.commit_group;" ::: "memory")
#define CPWAIT1()   asm volatile("cp.async.wait_group 1;" ::: "memory")
#define CPWAIT0()   asm volatile("cp.async.wait_group 0;" ::: "memory")

#define RSB 80

// ==================== hmma 128x128 (proven; used for preds) ====================
#define TSZ (128 * RSB)
#define STG (4 * TSZ)
#define HMMA_SMEM (2 * STG)      // 81920

template <int OUTMAP>
__global__ __launch_bounds__(256, 2)
void hmma_gemm(const __nv_bfloat16* __restrict__ Ahi, const __nv_bfloat16* __restrict__ Alo,
               const __nv_bfloat16* __restrict__ Bhi, const __nv_bfloat16* __restrict__ Blo,
               const float* __restrict__ bias, float* __restrict__ C,
               int M, int N, int K, int ldc)
{
    extern __shared__ char smc[];
    const uint32_t sb = smem_u32(smc);
    const int tid = threadIdx.x;
    const int lane = tid & 31, wid = tid >> 5;
    const int wm = wid & 1, wn = wid >> 1;
    const int m0 = blockIdx.y * 128, n0 = blockIdx.x * 128;

    int r0 = tid >> 2, c0 = tid & 3;
    int r1 = (tid + 256) >> 2, c1 = tid & 3;
    const __nv_bfloat16* base0[4] = {
        Ahi + (size_t)(m0 + r0) * K + c0 * 8,
        Alo + (size_t)(m0 + r0) * K + c0 * 8,
        Bhi + (size_t)(n0 + r0) * K + c0 * 8,
        Blo + (size_t)(n0 + r0) * K + c0 * 8 };
    const __nv_bfloat16* base1[4] = {
        Ahi + (size_t)(m0 + r1) * K + c1 * 8,
        Alo + (size_t)(m0 + r1) * K + c1 * 8,
        Bhi + (size_t)(n0 + r1) * K + c1 * 8,
        Blo + (size_t)(n0 + r1) * K + c1 * 8 };
    const uint32_t so0 = (uint32_t)(r0 * RSB + c0 * 16);
    const uint32_t so1 = (uint32_t)(r1 * RSB + c1 * 16);

    const int arow = (lane & 7) | (((lane >> 3) & 1) << 3);
    const int akh  = lane >> 4;
    const int brow = (lane & 7) + ((lane >> 4) << 3);
    const int bkh  = (lane >> 3) & 1;

    float acc[4][4][4];
#pragma unroll
    for (int i = 0; i < 4; i++)
#pragma unroll
        for (int j = 0; j < 4; j++)
#pragma unroll
            for (int e = 0; e < 4; e++) acc[i][j][e] = 0.f;

    const int nit = K / 32;

#pragma unroll
    for (int pi = 0; pi < 2; pi++) {
        uint32_t dst = sb + pi * STG;
        int kof = pi * 32;
#pragma unroll
        for (int tno = 0; tno < 4; tno++) {
            CP16(dst + tno * TSZ + so0, base0[tno] + kof);
            CP16(dst + tno * TSZ + so1, base1[tno] + kof);
        }
        CPCOMMIT();
    }

    for (int it = 0; it < nit; it++) {
        if (it + 1 < nit) { CPWAIT1(); } else { CPWAIT0(); }
        __syncthreads();

        const uint32_t stb = sb + (it & 1) * STG;
#pragma unroll
        for (int ks = 0; ks < 2; ks++) {
            uint32_t ah[4][4], al[4][4], bh[4][2], bl[4][2];
#pragma unroll
            for (int mt = 0; mt < 4; mt++) {
                uint32_t ra = (uint32_t)((wm * 64 + mt * 16 + arow) * RSB + ks * 32 + akh * 16);
                ldmx4(ah[mt], stb + 0 * TSZ + ra);
                ldmx4(al[mt], stb + 1 * TSZ + ra);
            }
#pragma unroll
            for (int g = 0; g < 2; g++) {
                uint32_t rb = (uint32_t)((wn * 32 + g * 16 + brow) * RSB + ks * 32 + bkh * 16);
                uint32_t t0[4], t1[4];
                ldmx4(t0, stb + 2 * TSZ + rb);
                ldmx4(t1, stb + 3 * TSZ + rb);
                bh[g * 2][0] = t0[0]; bh[g * 2][1] = t0[1];
                bh[g * 2 + 1][0] = t0[2]; bh[g * 2 + 1][1] = t0[3];
                bl[g * 2][0] = t1[0]; bl[g * 2][1] = t1[1];
                bl[g * 2 + 1][0] = t1[2]; bl[g * 2 + 1][1] = t1[3];
            }
#pragma unroll
            for (int mt = 0; mt < 4; mt++)
#pragma unroll
                for (int nt = 0; nt < 4; nt++) {
                    mma16816(acc[mt][nt], ah[mt], bh[nt]);
                    mma16816(acc[mt][nt], ah[mt], bl[nt]);
                    mma16816(acc[mt][nt], al[mt], bh[nt]);
                }
        }
        __syncthreads();

        if (it + 2 < nit) {
            uint32_t dst = sb + (it & 1) * STG;
            int kof = (it + 2) * 32;
#pragma unroll
            for (int tno = 0; tno < 4; tno++) {
                CP16(dst + tno * TSZ + so0, base0[tno] + kof);
                CP16(dst + tno * TSZ + so1, base1[tno] + kof);
            }
            CPCOMMIT();
        }
    }

#pragma unroll
    for (int mt = 0; mt < 4; mt++) {
#pragma unroll
        for (int half = 0; half < 2; half++) {
            int r = m0 + wm * 64 + mt * 16 + (lane >> 2) + half * 8;
            bool rowok; float* Crow;
            if (OUTMAP) {
                int ob = r & 31, ot = r >> 5;
                rowok = (ot < Tn);
                Crow = C + (size_t)(ob * Tn + ot) * ldc;
            } else {
                rowok = (r < M);
                Crow = C + (size_t)r * ldc;
            }
            if (!rowok) continue;
#pragma unroll
            for (int nt = 0; nt < 4; nt++) {
                int n = n0 + wn * 32 + nt * 8 + (lane & 3) * 2;
                if (n + 1 < N) {
                    float v0 = acc[mt][nt][half * 2 + 0];
                    float v1 = acc[mt][nt][half * 2 + 1];
                    if (bias) { v0 += bias[n]; v1 += bias[n + 1]; }
                    *(float2*)(Crow + n) = make_float2(v0, v1);
                } else if (n < N) {
                    float v0 = acc[mt][nt][half * 2 + 0];
                    if (bias) v0 += bias[n];
                    Crow[n] = v0;
                }
            }
        }
    }
}

// ==================== hmma 128x64: higher-occupancy variant (att/embW) =========
// A tiles 128 rows, B tiles 64 rows. 8 warps = 4m x 2n, warp tile 32x32.
#define ATSZ (128 * RSB)               // 10240
#define BTSZ (64 * RSB)                // 5120
#define STG64 (2 * ATSZ + 2 * BTSZ)    // 30720
#define HMMA64_SMEM (2 * STG64)        // 61440
// stage layout: [Ahi(10240) | Alo(10240) | Bhi(5120) | Blo(5120)]
#define OFF_AH 0
#define OFF_AL ATSZ
#define OFF_BH (2 * ATSZ)
#define OFF_BL (2 * ATSZ + BTSZ)

__global__ __launch_bounds__(256, 2)
void hmma_gemm64(const __nv_bfloat16* __restrict__ Ahi, const __nv_bfloat16* __restrict__ Alo,
                 const __nv_bfloat16* __restrict__ Bhi, const __nv_bfloat16* __restrict__ Blo,
                 const float* __restrict__ bias, float* __restrict__ C,
                 int M, int N, int K, int ldc)
{
    extern __shared__ char smc[];
    const uint32_t sb = smem_u32(smc);
    const int tid = threadIdx.x;
    const int lane = tid & 31, wid = tid >> 5;
    const int wm = wid & 3, wn = wid >> 2;
    const int m0 = blockIdx.y * 128, n0 = blockIdx.x * 64;

    // A slots: tid and tid+256 (512 slots, r=s>>2, c=s&3). B slots: tid (256 slots).
    const int ra0 = tid >> 2, ca0 = tid & 3;
    const int ra1 = (tid + 256) >> 2, ca1 = tid & 3;
    const __nv_bfloat16* aHi0 = Ahi + (size_t)(m0 + ra0) * K + ca0 * 8;
    const __nv_bfloat16* aLo0 = Alo + (size_t)(m0 + ra0) * K + ca0 * 8;
    const __nv_bfloat16* aHi1 = Ahi + (size_t)(m0 + ra1) * K + ca1 * 8;
    const __nv_bfloat16* aLo1 = Alo + (size_t)(m0 + ra1) * K + ca1 * 8;
    const uint32_t soA0 = (uint32_t)(ra0 * RSB + ca0 * 16);
    const uint32_t soA1 = (uint32_t)(ra1 * RSB + ca1 * 16);
    const int rb = tid >> 2, cb = tid & 3;
    const __nv_bfloat16* bHi = Bhi + (size_t)(n0 + rb) * K + cb * 8;
    const __nv_bfloat16* bLo = Blo + (size_t)(n0 + rb) * K + cb * 8;
    const uint32_t soB = (uint32_t)(rb * RSB + cb * 16);

    const int arow = (lane & 7) | (((lane >> 3) & 1) << 3);
    const int akh  = lane >> 4;
    const int brow = (lane & 7) + ((lane >> 4) << 3);
    const int bkh  = (lane >> 3) & 1;

    float acc[2][4][4];
#pragma unroll
    for (int i = 0; i < 2; i++)
#pragma unroll
        for (int j = 0; j < 4; j++)
#pragma unroll
            for (int e = 0; e < 4; e++) acc[i][j][e] = 0.f;

    const int nit = K / 32;

#pragma unroll
    for (int pi = 0; pi < 2; pi++) {
        uint32_t dst = sb + pi * STG64;
        int kof = pi * 32;
        CP16(dst + OFF_AH + soA0, aHi0 + kof);
        CP16(dst + OFF_AH + soA1, aHi1 + kof);
        CP16(dst + OFF_AL + soA0, aLo0 + kof);
        CP16(dst + OFF_AL + soA1, aLo1 + kof);
        CP16(dst + OFF_BH + soB,  bHi  + kof);
        CP16(dst + OFF_BL + soB,  bLo  + kof);
        CPCOMMIT();
    }

    for (int it = 0; it < nit; it++) {
        if (it + 1 < nit) { CPWAIT1(); } else { CPWAIT0(); }
        __syncthreads();

        const uint32_t stb = sb + (it & 1) * STG64;
#pragma unroll
        for (int ks = 0; ks < 2; ks++) {
            uint32_t ah[2][4], al[2][4], bh[4][2], bl[4][2];
#pragma unroll
            for (int mt = 0; mt < 2; mt++) {
                uint32_t ra = (uint32_t)((wm * 32 + mt * 16 + arow) * RSB + ks * 32 + akh * 16);
                ldmx4(ah[mt], stb + OFF_AH + ra);
                ldmx4(al[mt], stb + OFF_AL + ra);
            }
#pragma unroll
            for (int g = 0; g < 2; g++) {
                uint32_t rbr = (uint32_t)((wn * 32 + g * 16 + brow) * RSB + ks * 32 + bkh * 16);
                uint32_t t0[4], t1[4];
                ldmx4(t0, stb + OFF_BH + rbr);
                ldmx4(t1, stb + OFF_BL + rbr);
                bh[g * 2][0] = t0[0]; bh[g * 2][1] = t0[1];
                bh[g * 2 + 1][0] = t0[2]; bh[g * 2 + 1][1] = t0[3];
                bl[g * 2][0] = t1[0]; bl[g * 2][1] = t1[1];
                bl[g * 2 + 1][0] = t1[2]; bl[g * 2 + 1][1] = t1[3];
            }
#pragma unroll
            for (int mt = 0; mt < 2; mt++)
#pragma unroll
                for (int nt = 0; nt < 4; nt++) {
                    mma16816(acc[mt][nt], ah[mt], bh[nt]);
                    mma16816(acc[mt][nt], ah[mt], bl[nt]);
                    mma16816(acc[mt][nt], al[mt], bh[nt]);
                }
        }
        __syncthreads();

        if (it + 2 < nit) {
            uint32_t dst = sb + (it & 1) * STG64;
            int kof = (it + 2) * 32;
            CP16(dst + OFF_AH + soA0, aHi0 + kof);
            CP16(dst + OFF_AH + soA1, aHi1 + kof);
            CP16(dst + OFF_AL + soA0, aLo0 + kof);
            CP16(dst + OFF_AL + soA1, aLo1 + kof);
            CP16(dst + OFF_BH + soB,  bHi  + kof);
            CP16(dst + OFF_BL + soB,  bLo  + kof);
            CPCOMMIT();
        }
    }

#pragma unroll
    for (int mt = 0; mt < 2; mt++) {
#pragma unroll
        for (int half = 0; half < 2; half++) {
            int r = m0 + wm * 32 + mt * 16 + (lane >> 2) + half * 8;
            if (r >= M) continue;
            float* Crow = C + (size_t)r * ldc;
#pragma unroll
            for (int nt = 0; nt < 4; nt++) {
                int n = n0 + wn * 32 + nt * 8 + (lane & 3) * 2;
                if (n + 1 < N) {
                    float v0 = acc[mt][nt][half * 2 + 0];
                    float v1 = acc[mt][nt][half * 2 + 1];
                    if (bias) { v0 += bias[n]; v1 += bias[n + 1]; }
                    *(float2*)(Crow + n) = make_float2(v0, v1);
                } else if (n < N) {
                    float v0 = acc[mt][nt][half * 2 + 0];
                    if (bias) v0 += bias[n];
                    Crow[n] = v0;
                }
            }
        }
    }
}

// ==================== conversions ====================
__global__ void conv_split(const float* __restrict__ src, __nv_bfloat16* __restrict__ hi,
                           __nv_bfloat16* __restrict__ lo, int M, int K, int Mpad)
{
    int idx = blockIdx.x * 256 + threadIdx.x;
    if (idx >= Mpad * K) return;
    float v;
    if (M == Mpad) {
        v = src[idx];
    } else {
        int r = idx / K;
        v = (r < M) ? src[idx] : 0.f;
    }
    __nv_bfloat16 h = __float2bfloat16(v);
    hi[idx] = h;
    lo[idx] = __float2bfloat16(v - __bfloat162float(h));
}

__global__ void conv_splitT(const float* __restrict__ src, int ldsrc,
                            __nv_bfloat16* __restrict__ hi, __nv_bfloat16* __restrict__ lo,
                            int K, int N, int Npad)
{
    __shared__ float tile[32][33];
    int n0 = blockIdx.x * 32, k0 = blockIdx.y * 32;
    int tx = threadIdx.x, ty = threadIdx.y;
#pragma unroll
    for (int i = 0; i < 32; i += 8) {
        int n = n0 + tx;
        tile[ty + i][tx] = (n < N) ? src[(size_t)(k0 + ty + i) * ldsrc + n] : 0.f;
    }
    __syncthreads();
#pragma unroll
    for (int i = 0; i < 32; i += 8) {
        int n = n0 + ty + i, k = k0 + tx;
        if (n < Npad) {
            float v = tile[tx][ty + i];
            __nv_bfloat16 h = __float2bfloat16(v);
            hi[(size_t)n * K + k] = h;
            lo[(size_t)n * K + k] = __float2bfloat16(v - __bfloat162float(h));
        }
    }
}

__global__ void pad_hall_kernel()
{
    int idx = blockIdx.x * 256 + threadIdx.x;
    if (idx >= (Mp - Mrows) * Hn) return;
    g_hallh[Mrows * Hn + idx] = __float2bfloat16(0.f);
    g_halll[Mrows * Hn + idx] = __float2bfloat16(0.f);
}

// ==================== 3-segment fast step GEMM (R7-proven) ====================
__global__ __launch_bounds__(128)
void gemm_pass3(const float* A0, int lda0, const float* B0, int ldb0, float* P0, int N0, int K0, int ks0,
                const float* A1, int lda1, const float* B1, int ldb1, float* P1, int N1, int K1, int ks1,
                const float* A2, int lda2, const float* B2, int ldb2, float* P2, int N2, int K2, int ks2)
{
    const float *A, *B; float* P;
    int lda, ldb, N, K, ks;
    int id = blockIdx.x;
    const int b0 = (N0 / 32) * ks0, b1 = (N1 / 32) * ks1;
    if (id < b0)            { A=A0; B=B0; P=P0; lda=lda0; ldb=ldb0; N=N0; K=K0; ks=ks0; }
    else if (id < b0 + b1)  { id -= b0; A=A1; B=B1; P=P1; lda=lda1; ldb=ldb1; N=N1; K=K1; ks=ks1; }
    else                    { id -= b0 + b1; A=A2; B=B2; P=P2; lda=lda2; ldb=ldb2; N=N2; K=K2; ks=ks2; }

    const int nt = N / 32;
    const int ntile = id % nt, ksi = id / nt;
    const int kLen = K / ks;
    const int kbeg = ksi * kLen;
    const int n0 = ntile * 32;

    __shared__ __align__(16) float As[32][68];
    __shared__ __align__(16) float Bs[64][36];

    const int tid = threadIdx.x;
    const int m = (tid >> 3) * 2;
    const int nn = (tid & 7) * 4;

    float acc[2][4];
#pragma unroll
    for (int i = 0; i < 2; i++)
#pragma unroll
        for (int j = 0; j < 4; j++) acc[i][j] = 0.f;

    for (int kb = kbeg; kb < kbeg + kLen; kb += 64) {
#pragma unroll
        for (int i = 0; i < 4; i++) {
            int fi = tid + 128 * i;
            int ar = fi >> 4, ac = (fi & 15) * 4;
            *(float4*)&As[ar][ac] = *(const float4*)(A + (size_t)ar * lda + kb + ac);
            int br = fi >> 3, bc = (fi & 7) * 4;
            *(float4*)&Bs[br][bc] = *(const float4*)(B + (size_t)(kb + br) * ldb + n0 + bc);
        }
        __syncthreads();
#pragma unroll
        for (int k = 0; k < 64; k++) {
            float a0 = As[m][k], a1 = As[m + 1][k];
            float4 b4 = *(float4*)&Bs[k][nn];
            acc[0][0] = fmaf(a0, b4.x, acc[0][0]); acc[0][1] = fmaf(a0, b4.y, acc[0][1]);
            acc[0][2] = fmaf(a0, b4.z, acc[0][2]); acc[0][3] = fmaf(a0, b4.w, acc[0][3]);
            acc[1][0] = fmaf(a1, b4.x, acc[1][0]); acc[1][1] = fmaf(a1, b4.y, acc[1][1]);
            acc[1][2] = fmaf(a1, b4.z, acc[1][2]); acc[1][3] = fmaf(a1, b4.w, acc[1][3]);
        }
        __syncthreads();
    }

    float* dst = P + (size_t)ksi * 32 * N + n0;
    *(float4*)(dst + (size_t)m * N + nn)       = make_float4(acc[0][0], acc[0][1], acc[0][2], acc[0][3]);
    *(float4*)(dst + (size_t)(m + 1) * N + nn) = make_float4(acc[1][0], acc[1][1], acc[1][2], acc[1][3]);
}

// ==================== init-only small GEMM (split-K) ====================
__global__ __launch_bounds__(64)
void gemm_pass(const float* A0, int lda0, const float* B0, int ldb0, float* P0, int N0, int K0, int ks0, int nt0,
               const float* A1, int lda1, const float* B1, int ldb1, float* P1, int N1, int K1, int ks1, int nt1)
{
    const float* A; const float* B; float* P;
    int N, K, ks, nt, lda, ldb;
    int id = blockIdx.x;
    int blocks0 = nt0 * ks0;
    if (id < blocks0) { A=A0; B=B0; P=P0; N=N0; K=K0; ks=ks0; nt=nt0; lda=lda0; ldb=ldb0; }
    else { id -= blocks0; A=A1; B=B1; P=P1; N=N1; K=K1; ks=ks1; nt=nt1; lda=lda1; ldb=ldb1; }

    int ntile = id % nt;
    int ksi   = id / nt;
    int kLen  = K / ks;
    int kbeg  = ksi * kLen, kend = kbeg + kLen;
    int n0    = ntile * 32;

    __shared__ float As[32][36];
    __shared__ float Bs[32][32];
    const int tid = threadIdx.x;
    const int tx = tid & 7, ty = tid >> 3;
    const int lrow = tid >> 3, lc4 = tid & 7;

    float acc[4][4];
#pragma unroll
    for (int i = 0; i < 4; i++)
#pragma unroll
        for (int j = 0; j < 4; j++) acc[i][j] = 0.f;

    for (int k0 = kbeg; k0 < kend; k0 += 32) {
#pragma unroll
        for (int i = 0; i < 4; i++)
            *(float4*)&As[lrow + 8 * i][lc4 * 4] =
                *(const float4*)(A + (size_t)(lrow + 8 * i) * lda + k0 + lc4 * 4);
#pragma unroll
        for (int i = 0; i < 4; i++)
            *(float4*)&Bs[lrow + 8 * i][lc4 * 4] =
                *(const float4*)(B + (size_t)(k0 + lrow + 8 * i) * ldb + n0 + lc4 * 4);
        __syncthreads();
#pragma unroll
        for (int kk = 0; kk < 32; kk++) {
            float a[4];
#pragma unroll
            for (int i = 0; i < 4; i++) a[i] = As[ty * 4 + i][kk];
            float4 bv = *(float4*)&Bs[kk][tx * 4];
#pragma unroll
            for (int i = 0; i < 4; i++) {
                acc[i][0] = fmaf(a[i], bv.x, acc[i][0]);
                acc[i][1] = fmaf(a[i], bv.y, acc[i][1]);
                acc[i][2] = fmaf(a[i], bv.z, acc[i][2]);
                acc[i][3] = fmaf(a[i], bv.w, acc[i][3]);
            }
        }
        __syncthreads();
    }
    float* dst = P + (size_t)ksi * 32 * N;
#pragma unroll
    for (int i = 0; i < 4; i++) {
        int m = ty * 4 + i;
#pragma unroll
        for (int j = 0; j < 4; j++)
            dst[(size_t)m * N + n0 + tx * 4 + j] = acc[i][j];
    }
}

__global__ void reduce2_kernel(float* d0, const float* P0, int ks0, int N0, const float* b0, int act0, int cnt0,
                               float* d1, const float* P1, int ks1, int N1, const float* b1, int act1, int cnt1)
{
    int i = blockIdx.x * 256 + threadIdx.x;
    float* d; const float* P; int ks, N; const float* bi; int act; int cnt;
    if (i < cnt0) { d=d0; P=P0; ks=ks0; N=N0; bi=b0; act=act0; cnt=cnt0; }
    else { i -= cnt0; d=d1; P=P1; ks=ks1; N=N1; bi=b1; act=act1; cnt=cnt1; }
    if (i >= cnt) return;
    float v = 0.f;
    for (int s = 0; s < ks; s++) v += P[(size_t)s * cnt + i];
    if (bi) v += bi[i % N];
    if (act == 1) v = tanhf(v);
    else if (act == 2) v = sigf(v);
    d[i] = v;
}

__global__ void avg_kernel(const float* __restrict__ img)
{
    int idx = blockIdx.x * blockDim.x + threadIdx.x;
    if (idx >= Bsz * (Dn / 4)) return;
    int b = idx >> 9;
    const float4* ip = (const float4*)img + (size_t)b * Pn * (Dn / 4) + (idx & 511);
    float4 s = make_float4(0.f, 0.f, 0.f, 0.f);
    for (int p = 0; p < Pn; p++) {
        float4 x = ip[(size_t)p * (Dn / 4)];
        s.x += x.x; s.y += x.y; s.z += x.z; s.w += x.w;
    }
    const float inv = 1.f / (float)Pn;
    s.x *= inv; s.y *= inv; s.z *= inv; s.w *= inv;
    ((float4*)g_avg)[idx] = s;
}

__global__ void emb_kernel(const int* __restrict__ caps, const float* __restrict__ E)
{
    int idx = blockIdx.x * blockDim.x + threadIdx.x;
    if (idx >= Bsz * Tn * Hn) return;
    int r = idx / Hn;
    int h = idx - r * Hn;
    int b = r / Tn, t = r - b * Tn;
    g_emb[idx] = E[(size_t)caps[b * 20 + t] * Hn + h];
}

// ==================== tile gemm for companion Whh blocks (R12-proven) ==========
#define TILE_FLOATS (32 * 68 + 64 * 36)
#define AC_SMEM (8 * TILE_FLOATS * 4)           // 143360

__device__ __forceinline__ void bar128(int id) {
    asm volatile("bar.sync %0, 128;" :: "r"(id) : "memory");
}

__device__ __forceinline__ void tile_gemm(
    const float* __restrict__ A, int lda, int kbeg, int kLen,
    const float* __restrict__ B, int ldb, int n0,
    float* __restrict__ P, int N,
    float* As, float* Bs, int tid, int barid)
{
    const int m = (tid >> 3) * 2;
    const int nn = (tid & 7) * 4;
    float acc[2][4];
#pragma unroll
    for (int i = 0; i < 2; i++)
#pragma unroll
        for (int j = 0; j < 4; j++) acc[i][j] = 0.f;

    for (int kb = kbeg; kb < kbeg + kLen; kb += 64) {
#pragma unroll
        for (int i = 0; i < 4; i++) {
            int fi = tid + 128 * i;
            int ar = fi >> 4, ac = (fi & 15) * 4;
            *(float4*)&As[ar * 68 + ac] = *(const float4*)(A + (size_t)ar * lda + kb + ac);
            int br = fi >> 3, bc = (fi & 7) * 4;
            *(float4*)&Bs[br * 36 + bc] = *(const float4*)(B + (size_t)(kb + br) * ldb + n0 + bc);
        }
        bar128(barid);
#pragma unroll
        for (int k = 0; k < 64; k++) {
            float a0 = As[m * 68 + k], a1 = As[(m + 1) * 68 + k];
            float4 b4 = *(float4*)&Bs[k * 36 + nn];
            acc[0][0] = fmaf(a0, b4.x, acc[0][0]); acc[0][1] = fmaf(a0, b4.y, acc[0][1]);
            acc[0][2] = fmaf(a0, b4.z, acc[0][2]); acc[0][3] = fmaf(a0, b4.w, acc[0][3]);
            acc[1][0] = fmaf(a1, b4.x, acc[1][0]); acc[1][1] = fmaf(a1, b4.y, acc[1][1]);
            acc[1][2] = fmaf(a1, b4.z, acc[1][2]); acc[1][3] = fmaf(a1, b4.w, acc[1][3]);
        }
        bar128(barid);
    }
    *(float4*)(P + (size_t)m * N + n0 + nn)       = make_float4(acc[0][0], acc[0][1], acc[0][2], acc[0][3]);
    *(float4*)(P + (size_t)(m + 1) * N + n0 + nn) = make_float4(acc[1][0], acc[1][1], acc[1][2], acc[1][3]);
}

// ==================== attctx (R7) + companion Whh tiles (independent) ==========
// blocks 0..31: attctx for b=blk. blocks 32..63: 8 Whh tiles each (256 tiles, ks=4).
__global__ __launch_bounds__(1024)
void attctx_kernel(const float* __restrict__ img, const float* __restrict__ Whh,
                   const float* __restrict__ v_att, const float* __restrict__ b_v_att,
                   const float* __restrict__ b_att_h, const float* __restrict__ b_fbeta,
                   float* __restrict__ out_alphas, int t)
{
    extern __shared__ __align__(16) float SM[];
    const int blk = blockIdx.x, tid = threadIdx.x;

    if (blk >= 32) {
        // independent Whh producers: read only g_h (same dependency as attctx)
        const int sub = tid >> 7, ltid = tid & 127;
        float* As = SM + sub * TILE_FLOATS;
        float* Bs = As + 32 * 68;
        const int tile = (blk - 32) * 8 + sub;        // 0..255
        const int ntile = tile & 63, ksi = tile >> 6; // nt=64, ks=4, kLen=128
        tile_gemm(g_h, Hn, ksi * 128, 128, Whh, 4 * Hn, ntile * 32,
                  g_pb + (size_t)ksi * 32 * 4 * Hn, 4 * Hn, As, Bs, ltid, 8 + sub);
        return;
    }

    const int b = blk;
    const int w = tid >> 5, lane = tid & 31;
    float*  hp   = SM;                       // 512
    float*  va   = SM + 512;                 // 512
    float*  ee   = SM + 1024;                // 224
    float*  sred = SM + 1248;                // 8 (+pad to 1280)
    float4* redD = (float4*)(SM + 1280);     // 1024 float4

    if (tid < Hn) {
        float v = b_att_h[tid];
#pragma unroll
        for (int s = 0; s < 8; s++) v += g_pp_h[s * Bsz * Hn + b * Hn + tid];
        hp[tid] = v;
        va[tid] = v_att[tid];
    }
    __syncthreads();

    const float* ai = g_att_img + (size_t)b * Pn * Hn;
    const float bv0 = b_v_att[0];
    for (int p = w; p < Pn; p += 32) {
        const float* aip = ai + (size_t)p * Hn;
        float s = 0.f;
#pragma unroll
        for (int ii = 0; ii < Hn / 32; ii++) {
            int hx = lane + 32 * ii;
            float x = aip[hx] + hp[hx];
            float th;
            asm("tanh.approx.f32 %0, %1;" : "=f"(th) : "f"(x));
            s = fmaf(th, va[hx], s);
        }
#pragma unroll
        for (int o = 16; o; o >>= 1) s += __shfl_down_sync(0xffffffffu, s, o);
        if (lane == 0) ee[p] = s + bv0;
    }
    __syncthreads();

    float v = (tid < Pn) ? ee[tid] : -1e30f;
    if (tid < 256) {
        float m = v;
#pragma unroll
        for (int o = 16; o; o >>= 1) m = fmaxf(m, __shfl_xor_sync(0xffffffffu, m, o));
        if (lane == 0) sred[w] = m;
    }
    __syncthreads();
    if (tid < 32) {
        float mm = (tid < 8) ? sred[tid] : -1e30f;
#pragma unroll
        for (int o = 4; o; o >>= 1) mm = fmaxf(mm, __shfl_xor_sync(0xffffffffu, mm, o));
        if (tid == 0) sred[0] = mm;
    }
    __syncthreads();
    float exv = (tid < Pn) ? expf(v - sred[0]) : 0.f;
    __syncthreads();
    if (tid < 256) {
        float s = exv;
#pragma unroll
        for (int o = 16; o; o >>= 1) s += __shfl_xor_sync(0xffffffffu, s, o);
        if (lane == 0) sred[w] = s;
    }
    __syncthreads();
    if (tid < 32) {
        float ss = (tid < 8) ? sred[tid] : 0.f;
#pragma unroll
        for (int o = 4; o; o >>= 1) ss += __shfl_xor_sync(0xffffffffu, ss, o);
        if (tid == 0) sred[0] = ss;
    }
    __syncthreads();
    if (tid < Pn) {
        float a = exv / sred[0];
        ee[tid] = a;
        out_alphas[((size_t)b * Tn + t) * Pn + tid] = a;
    }
    __syncthreads();

    const int ps = tid >> 9;
    const int d4 = tid & 511;
    const float4* ip = (const float4*)img + (size_t)b * Pn * (Dn / 4) + d4;
    float4 cx = make_float4(0.f, 0.f, 0.f, 0.f);
#pragma unroll 8
    for (int p = ps; p < Pn; p += 2) {
        float a = ee[p];
        float4 x = ip[(size_t)p * (Dn / 4)];
        cx.x = fmaf(a, x.x, cx.x); cx.y = fmaf(a, x.y, cx.y);
        cx.z = fmaf(a, x.z, cx.z); cx.w = fmaf(a, x.w, cx.w);
    }
    redD[ps * (Dn / 4) + d4] = cx;
    __syncthreads();
    if (tid < Dn / 4) {
        float4 r0 = redD[tid], r1 = redD[(Dn / 4) + tid];
        float4 gb = *(const float4*)(b_fbeta + tid * 4);
#pragma unroll
        for (int sp = 0; sp < 8; sp++) {
            float4 pv = ((const float4*)g_pp_g)[sp * (Bsz * Dn / 4) + b * (Dn / 4) + tid];
            gb.x += pv.x; gb.y += pv.y; gb.z += pv.z; gb.w += pv.w;
        }
        float4 o4;
        o4.x = (r0.x + r1.x) * sigf(gb.x);
        o4.y = (r0.y + r1.y) * sigf(gb.y);
        o4.z = (r0.z + r1.z) * sigf(gb.z);
        o4.w = (r0.w + r1.w) * sigf(gb.w);
        ((float4*)g_xc)[b * (Dn / 4) + tid] = o4;
    }
}

// LSTM pointwise: sum 8 pa + 4 pb partials + embW + biases; writes h + bf16 split
__global__ void lstm_kernel(const float* __restrict__ bih, const float* __restrict__ bhh, int t)
{
    int idx = blockIdx.x * blockDim.x + threadIdx.x;
    if (idx >= Bsz * Hn) return;
    int b = idx >> 9;
    int j = idx & 511;
    int rowE = (b * Tn + t) * 4 * Hn;
    int rowP = b * 4 * Hn;

    float gv[4];
#pragma unroll
    for (int g = 0; g < 4; g++) {
        int n = g * Hn + j;
        float v = g_embW[rowE + n] + bih[n] + bhh[n];
#pragma unroll
        for (int s = 0; s < 8; s++) v += g_pa[s * Bsz * 4 * Hn + rowP + n];
#pragma unroll
        for (int s = 0; s < 4; s++) v += g_pb[s * Bsz * 4 * Hn + rowP + n];
        gv[g] = v;
    }
    float c = sigf(gv[1]) * g_c[idx] + sigf(gv[0]) * tanhf(gv[2]);
    g_c[idx] = c;
    float h = sigf(gv[3]) * tanhf(c);
    g_h[idx] = h;
    size_t ro = (size_t)(t * Bsz + b) * Hn + j;
    __nv_bfloat16 hh = __float2bfloat16(h);
    g_hallh[ro] = hh;
    g_halll[ro] = __float2bfloat16(h - __bfloat162float(hh));
}

// ================================================================================
extern "C" void kernel_launch(void* const* d_in, const int* in_sizes, int n_in,
                              void* d_out, int out_size)
{
    const float* img      = (const float*)d_in[0];
    const int*   caps     = (const int*)d_in[1];
    const float* Wih      = (const float*)d_in[2];
    const float* Whh      = (const float*)d_in[3];
    const float* bih      = (const float*)d_in[4];
    const float* bhh      = (const float*)d_in[5];
    const float* W_init_h = (const float*)d_in[6];
    const float* b_init_h = (const float*)d_in[7];
    const float* W_init_c = (const float*)d_in[8];
    const float* b_init_c = (const float*)d_in[9];
    const float* W_fbeta  = (const float*)d_in[10];
    const float* b_fbeta  = (const float*)d_in[11];
    const float* W_out    = (const float*)d_in[12];
    const float* b_out    = (const float*)d_in[13];
    const float* W_att_im = (const float*)d_in[14];
    const float* b_att_im = (const float*)d_in[15];
    const float* W_att_h  = (const float*)d_in[16];
    const float* b_att_h  = (const float*)d_in[17];
    const float* v_att    = (const float*)d_in[18];
    const float* b_v_att  = (const float*)d_in[19];
    const float* E        = (const float*)d_in[20];

    float* preds  = (float*)d_out;
    float* alphas = (float*)d_out + (size_t)Bsz * Tn * Vn;

    float *p_avg, *p_h, *p_c, *p_att, *p_emb, *p_embW, *p_xc, *p_pph, *p_ppg;
    float *p_pa, *p_pb, *p_pih, *p_pic;
    __nv_bfloat16 *p_imgh, *p_imgl, *p_watth, *p_wattl, *p_wouth, *p_woutl;
    __nv_bfloat16 *p_wihh, *p_wihl, *p_embh, *p_embl, *p_hallh, *p_halll;
    cudaGetSymbolAddress((void**)&p_avg,   g_avg);
    cudaGetSymbolAddress((void**)&p_h,     g_h);
    cudaGetSymbolAddress((void**)&p_c,     g_c);
    cudaGetSymbolAddress((void**)&p_att,   g_att_img);
    cudaGetSymbolAddress((void**)&p_emb,   g_emb);
    cudaGetSymbolAddress((void**)&p_embW,  g_embW);
    cudaGetSymbolAddress((void**)&p_xc,    g_xc);
    cudaGetSymbolAddress((void**)&p_pph,   g_pp_h);
    cudaGetSymbolAddress((void**)&p_ppg,   g_pp_g);
    cudaGetSymbolAddress((void**)&p_pa,    g_pa);
    cudaGetSymbolAddress((void**)&p_pb,    g_pb);
    cudaGetSymbolAddress((void**)&p_pih,   g_pi_h);
    cudaGetSymbolAddress((void**)&p_pic,   g_pi_c);
    cudaGetSymbolAddress((void**)&p_imgh,  g_img_hi);
    cudaGetSymbolAddress((void**)&p_imgl,  g_img_lo);
    cudaGetSymbolAddress((void**)&p_watth, g_watt_hi);
    cudaGetSymbolAddress((void**)&p_wattl, g_watt_lo);
    cudaGetSymbolAddress((void**)&p_wouth, g_wout_hi);
    cudaGetSymbolAddress((void**)&p_woutl, g_wout_lo);
    cudaGetSymbolAddress((void**)&p_wihh,  g_wih_hi);
    cudaGetSymbolAddress((void**)&p_wihl,  g_wih_lo);
    cudaGetSymbolAddress((void**)&p_embh,  g_embh);
    cudaGetSymbolAddress((void**)&p_embl,  g_embl);
    cudaGetSymbolAddress((void**)&p_hallh, g_hallh);
    cudaGetSymbolAddress((void**)&p_halll, g_halll);

    cudaFuncSetAttribute(hmma_gemm<0>, cudaFuncAttributeMaxDynamicSharedMemorySize, HMMA_SMEM);
    cudaFuncSetAttribute(hmma_gemm<1>, cudaFuncAttributeMaxDynamicSharedMemorySize, HMMA_SMEM);
    cudaFuncSetAttribute(hmma_gemm64,  cudaFuncAttributeMaxDynamicSharedMemorySize, HMMA64_SMEM);
    cudaFuncSetAttribute(attctx_kernel, cudaFuncAttributeMaxDynamicSharedMemorySize, AC_SMEM);

    // ---- setup (launch index 3 = att hmma64 -> ncu slot) ----
    conv_split<<<(Bsz * Pn * Dn) / 256, 256>>>(img, p_imgh, p_imgl, Bsz * Pn, Dn, Bsz * Pn);          // 0
    conv_splitT<<<dim3(Hn / 32, Dn / 32), dim3(32, 8)>>>(W_att_im, Hn, p_watth, p_wattl, Dn, Hn, Hn); // 1
    avg_kernel<<<64, 256>>>(img);                                                                     // 2
    hmma_gemm64<<<dim3(Hn / 64, (Bsz * Pn) / 128), 256, HMMA64_SMEM>>>(                               // 3 <- ncu
        p_imgh, p_imgl, p_watth, p_wattl, b_att_im, p_att, Bsz * Pn, Hn, Dn, Hn);
    conv_splitT<<<dim3(Vp / 32, Hn / 32), dim3(32, 8)>>>(W_out, Vn, p_wouth, p_woutl, Hn, Vn, Vp);
    conv_splitT<<<dim3(4 * Hn / 32, Hn / 32), dim3(32, 8)>>>(Wih, 4 * Hn, p_wihh, p_wihl, Hn, 4 * Hn, 4 * Hn);
    gemm_pass<<<256, 64>>>(p_avg, Dn, W_init_h, Hn, p_pih, Hn, Dn, 8, 16,
                           p_avg, Dn, W_init_c, Hn, p_pic, Hn, Dn, 8, 16);
    reduce2_kernel<<<128, 256>>>(p_h, p_pih, 8, Hn, b_init_h, 1, Bsz * Hn,
                                 p_c, p_pic, 8, Hn, b_init_c, 1, Bsz * Hn);
    emb_kernel<<<(Bsz * Tn * Hn) / 256, 256>>>(caps, E);
    conv_split<<<(Mp * Hn) / 256, 256>>>(p_emb, p_embh, p_embl, Mrows, Hn, Mp);
    hmma_gemm64<<<dim3(4 * Hn / 64, Mp / 128), 256, HMMA64_SMEM>>>(
        p_embh, p_embl, p_wihh, p_wihl, nullptr, p_embW, Mrows, 4 * Hn, Hn, 4 * Hn);
    pad_hall_kernel<<<((Mp - Mrows) * Hn + 255) / 256, 256>>>();

    const float* WihBot = Wih + (size_t)Hn * 4 * Hn;

    // ---- recurrent steps: 4 nodes/step (Whh moved to attctx companions) ----
    for (int t = 0; t < Tn; t++) {
        // pass1: hproj (ks=8, 128 blk) + fbeta (ks=8, 512 blk); 3rd segment unreached
        gemm_pass3<<<128 + 512, 128>>>(
            p_h, Hn, W_att_h, Hn, p_pph, Hn, Hn, 8,
            p_h, Hn, W_fbeta, Dn, p_ppg, Dn, Hn, 8,
            p_h, Hn, W_fbeta, Dn, p_ppg, Dn, Hn, 8);
        attctx_kernel<<<64, 1024, AC_SMEM>>>(img, Whh, v_att, b_v_att, b_att_h, b_fbeta, alphas, t);
        gemm_pass3<<<512, 128>>>(
            p_xc, Dn, WihBot, 4 * Hn, p_pa, 4 * Hn, Dn, 8,
            p_xc, Dn, WihBot, 4 * Hn, p_pa, 0,      Dn, 8,
            p_xc, Dn, WihBot, 4 * Hn, p_pa, 0,      Dn, 8);
        lstm_kernel<<<(Bsz * Hn) / 256, 256>>>(bih, bhh, t);
    }

    // ---- final: preds = h_all @ W_out + b_out (proven 128x128 hmma) ----
    hmma_gemm<1><<<dim3(Vp / 128, Mp / 128), 256, HMMA_SMEM>>>(
        p_hallh, p_halll, p_wouth, p_woutl, b_out, preds, Mrows, Vn, Hn, Vn);
}

// round 15
// speedup vs baseline: 1.2562x; 1.0291x over previous
#include <cuda_runtime.h>
#include <cuda_bf16.h>
#include <math.h>
#include <stdint.h>

#define Bsz 32
#define Pn  196
#define Dn  2048
#define Hn  512
#define Vn  30000
#define Tn  19
#define Vp  30080
#define Mrows 608
#define Mp  640

// ---------------- fp32 scratch ----------------
__device__ float g_avg[Bsz * Dn];
__device__ float g_h[Bsz * Hn];
__device__ float g_c[Bsz * Hn];
__device__ float g_att_img[Bsz * Pn * Hn];
__device__ float g_emb[Bsz * Tn * Hn];
__device__ float g_embW[Bsz * Tn * 4 * Hn];
__device__ float g_xc[Bsz * Dn];
__device__ float g_pp_h[8 * Bsz * Hn];           // hproj (ks=8)
__device__ float g_pp_g[8 * Bsz * Dn];           // fbeta (ks=8)
__device__ float g_pa[8 * Bsz * 4 * Hn];         // xc@Wih_bot (ks=8)
__device__ float g_pb[4 * Bsz * 4 * Hn];         // h@Whh (ks=4)
__device__ float g_pi_h[8 * Bsz * Hn];
__device__ float g_pi_c[8 * Bsz * Hn];

// ---------------- bf16 split scratch ----------------
__device__ __nv_bfloat16 g_img_hi[Bsz * Pn * Dn];
__device__ __nv_bfloat16 g_img_lo[Bsz * Pn * Dn];
__device__ __nv_bfloat16 g_watt_hi[Hn * Dn];
__device__ __nv_bfloat16 g_watt_lo[Hn * Dn];
__device__ __nv_bfloat16 g_wout_hi[Vp * Hn];
__device__ __nv_bfloat16 g_wout_lo[Vp * Hn];
__device__ __nv_bfloat16 g_wih_hi[4 * Hn * Hn];
__device__ __nv_bfloat16 g_wih_lo[4 * Hn * Hn];
__device__ __nv_bfloat16 g_embh[Mp * Hn];
__device__ __nv_bfloat16 g_embl[Mp * Hn];
__device__ __nv_bfloat16 g_hallh[Mp * Hn];
__device__ __nv_bfloat16 g_halll[Mp * Hn];

__device__ __forceinline__ float sigf(float x) { return 1.f / (1.f + expf(-x)); }

__device__ __forceinline__ uint32_t smem_u32(const void* p) {
    uint32_t a;
    asm("{ .reg .u64 t; cvta.to.shared.u64 t, %1; cvt.u32.u64 %0, t; }" : "=r"(a) : "l"(p));
    return a;
}
__device__ __forceinline__ void ldmx4(uint32_t* r, uint32_t addr) {
    asm volatile("ldmatrix.sync.aligned.m8n8.x4.shared.b16 {%0,%1,%2,%3}, [%4];"
                 : "=r"(r[0]), "=r"(r[1]), "=r"(r[2]), "=r"(r[3]) : "r"(addr));
}
__device__ __forceinline__ void mma16816(float* d, const uint32_t* a, const uint32_t* b) {
    asm volatile(
        "mma.sync.aligned.m16n8k16.row.col.f32.bf16.bf16.f32 "
        "{%0,%1,%2,%3}, {%4,%5,%6,%7}, {%8,%9}, {%0,%1,%2,%3};"
        : "+f"(d[0]), "+f"(d[1]), "+f"(d[2]), "+f"(d[3])
        : "r"(a[0]), "r"(a[1]), "r"(a[2]), "r"(a[3]), "r"(b[0]), "r"(b[1]));
}
#define CP16(s, g)  asm volatile("cp.async.cg.shared.global [%0], [%1], 16;" :: "r"(s), "l"(g))
#define CPCOMMIT()  asm volatile("cp.async.commit_group;" ::: "memory")
#define CPWAIT1()   asm volatile("cp.async.wait_group 1;" ::: "memory")
#define CPWAIT0()   asm volatile("cp.async.wait_group 0;" ::: "memory")

#define RSB 80

// ==================== hmma 128x128 (preds) ====================
#define TSZ (128 * RSB)
#define STG (4 * TSZ)
#define HMMA_SMEM (2 * STG)      // 81920

template <int OUTMAP>
__global__ __launch_bounds__(256, 2)
void hmma_gemm(const __nv_bfloat16* __restrict__ Ahi, const __nv_bfloat16* __restrict__ Alo,
               const __nv_bfloat16* __restrict__ Bhi, const __nv_bfloat16* __restrict__ Blo,
               const float* __restrict__ bias, float* __restrict__ C,
               int M, int N, int K, int ldc)
{
    extern __shared__ char smc[];
    const uint32_t sb = smem_u32(smc);
    const int tid = threadIdx.x;
    const int lane = tid & 31, wid = tid >> 5;
    const int wm = wid & 1, wn = wid >> 1;
    const int m0 = blockIdx.y * 128, n0 = blockIdx.x * 128;

    int r0 = tid >> 2, c0 = tid & 3;
    int r1 = (tid + 256) >> 2, c1 = tid & 3;
    const __nv_bfloat16* base0[4] = {
        Ahi + (size_t)(m0 + r0) * K + c0 * 8,
        Alo + (size_t)(m0 + r0) * K + c0 * 8,
        Bhi + (size_t)(n0 + r0) * K + c0 * 8,
        Blo + (size_t)(n0 + r0) * K + c0 * 8 };
    const __nv_bfloat16* base1[4] = {
        Ahi + (size_t)(m0 + r1) * K + c1 * 8,
        Alo + (size_t)(m0 + r1) * K + c1 * 8,
        Bhi + (size_t)(n0 + r1) * K + c1 * 8,
        Blo + (size_t)(n0 + r1) * K + c1 * 8 };
    const uint32_t so0 = (uint32_t)(r0 * RSB + c0 * 16);
    const uint32_t so1 = (uint32_t)(r1 * RSB + c1 * 16);

    const int arow = (lane & 7) | (((lane >> 3) & 1) << 3);
    const int akh  = lane >> 4;
    const int brow = (lane & 7) + ((lane >> 4) << 3);
    const int bkh  = (lane >> 3) & 1;

    float acc[4][4][4];
#pragma unroll
    for (int i = 0; i < 4; i++)
#pragma unroll
        for (int j = 0; j < 4; j++)
#pragma unroll
            for (int e = 0; e < 4; e++) acc[i][j][e] = 0.f;

    const int nit = K / 32;

#pragma unroll
    for (int pi = 0; pi < 2; pi++) {
        uint32_t dst = sb + pi * STG;
        int kof = pi * 32;
#pragma unroll
        for (int tno = 0; tno < 4; tno++) {
            CP16(dst + tno * TSZ + so0, base0[tno] + kof);
            CP16(dst + tno * TSZ + so1, base1[tno] + kof);
        }
        CPCOMMIT();
    }

    for (int it = 0; it < nit; it++) {
        if (it + 1 < nit) { CPWAIT1(); } else { CPWAIT0(); }
        __syncthreads();

        const uint32_t stb = sb + (it & 1) * STG;
#pragma unroll
        for (int ks = 0; ks < 2; ks++) {
            uint32_t ah[4][4], al[4][4], bh[4][2], bl[4][2];
#pragma unroll
            for (int mt = 0; mt < 4; mt++) {
                uint32_t ra = (uint32_t)((wm * 64 + mt * 16 + arow) * RSB + ks * 32 + akh * 16);
                ldmx4(ah[mt], stb + 0 * TSZ + ra);
                ldmx4(al[mt], stb + 1 * TSZ + ra);
            }
#pragma unroll
            for (int g = 0; g < 2; g++) {
                uint32_t rb = (uint32_t)((wn * 32 + g * 16 + brow) * RSB + ks * 32 + bkh * 16);
                uint32_t t0[4], t1[4];
                ldmx4(t0, stb + 2 * TSZ + rb);
                ldmx4(t1, stb + 3 * TSZ + rb);
                bh[g * 2][0] = t0[0]; bh[g * 2][1] = t0[1];
                bh[g * 2 + 1][0] = t0[2]; bh[g * 2 + 1][1] = t0[3];
                bl[g * 2][0] = t1[0]; bl[g * 2][1] = t1[1];
                bl[g * 2 + 1][0] = t1[2]; bl[g * 2 + 1][1] = t1[3];
            }
#pragma unroll
            for (int mt = 0; mt < 4; mt++)
#pragma unroll
                for (int nt = 0; nt < 4; nt++) {
                    mma16816(acc[mt][nt], ah[mt], bh[nt]);
                    mma16816(acc[mt][nt], ah[mt], bl[nt]);
                    mma16816(acc[mt][nt], al[mt], bh[nt]);
                }
        }
        __syncthreads();

        if (it + 2 < nit) {
            uint32_t dst = sb + (it & 1) * STG;
            int kof = (it + 2) * 32;
#pragma unroll
            for (int tno = 0; tno < 4; tno++) {
                CP16(dst + tno * TSZ + so0, base0[tno] + kof);
                CP16(dst + tno * TSZ + so1, base1[tno] + kof);
            }
            CPCOMMIT();
        }
    }

#pragma unroll
    for (int mt = 0; mt < 4; mt++) {
#pragma unroll
        for (int half = 0; half < 2; half++) {
            int r = m0 + wm * 64 + mt * 16 + (lane >> 2) + half * 8;
            bool rowok; float* Crow;
            if (OUTMAP) {
                int ob = r & 31, ot = r >> 5;
                rowok = (ot < Tn);
                Crow = C + (size_t)(ob * Tn + ot) * ldc;
            } else {
                rowok = (r < M);
                Crow = C + (size_t)r * ldc;
            }
            if (!rowok) continue;
#pragma unroll
            for (int nt = 0; nt < 4; nt++) {
                int n = n0 + wn * 32 + nt * 8 + (lane & 3) * 2;
                if (n + 1 < N) {
                    float v0 = acc[mt][nt][half * 2 + 0];
                    float v1 = acc[mt][nt][half * 2 + 1];
                    if (bias) { v0 += bias[n]; v1 += bias[n + 1]; }
                    *(float2*)(Crow + n) = make_float2(v0, v1);
                } else if (n < N) {
                    float v0 = acc[mt][nt][half * 2 + 0];
                    if (bias) v0 += bias[n];
                    Crow[n] = v0;
                }
            }
        }
    }
}

// ==================== hmma 128x64: higher-occupancy variant (att/embW) =========
#define ATSZ (128 * RSB)
#define BTSZ (64 * RSB)
#define STG64 (2 * ATSZ + 2 * BTSZ)    // 30720
#define HMMA64_SMEM (2 * STG64)        // 61440
#define OFF_AH 0
#define OFF_AL ATSZ
#define OFF_BH (2 * ATSZ)
#define OFF_BL (2 * ATSZ + BTSZ)

__global__ __launch_bounds__(256, 2)
void hmma_gemm64(const __nv_bfloat16* __restrict__ Ahi, const __nv_bfloat16* __restrict__ Alo,
                 const __nv_bfloat16* __restrict__ Bhi, const __nv_bfloat16* __restrict__ Blo,
                 const float* __restrict__ bias, float* __restrict__ C,
                 int M, int N, int K, int ldc)
{
    extern __shared__ char smc[];
    const uint32_t sb = smem_u32(smc);
    const int tid = threadIdx.x;
    const int lane = tid & 31, wid = tid >> 5;
    const int wm = wid & 3, wn = wid >> 2;
    const int m0 = blockIdx.y * 128, n0 = blockIdx.x * 64;

    const int ra0 = tid >> 2, ca0 = tid & 3;
    const int ra1 = (tid + 256) >> 2, ca1 = tid & 3;
    const __nv_bfloat16* aHi0 = Ahi + (size_t)(m0 + ra0) * K + ca0 * 8;
    const __nv_bfloat16* aLo0 = Alo + (size_t)(m0 + ra0) * K + ca0 * 8;
    const __nv_bfloat16* aHi1 = Ahi + (size_t)(m0 + ra1) * K + ca1 * 8;
    const __nv_bfloat16* aLo1 = Alo + (size_t)(m0 + ra1) * K + ca1 * 8;
    const uint32_t soA0 = (uint32_t)(ra0 * RSB + ca0 * 16);
    const uint32_t soA1 = (uint32_t)(ra1 * RSB + ca1 * 16);
    const int rb = tid >> 2, cb = tid & 3;
    const __nv_bfloat16* bHi = Bhi + (size_t)(n0 + rb) * K + cb * 8;
    const __nv_bfloat16* bLo = Blo + (size_t)(n0 + rb) * K + cb * 8;
    const uint32_t soB = (uint32_t)(rb * RSB + cb * 16);

    const int arow = (lane & 7) | (((lane >> 3) & 1) << 3);
    const int akh  = lane >> 4;
    const int brow = (lane & 7) + ((lane >> 4) << 3);
    const int bkh  = (lane >> 3) & 1;

    float acc[2][4][4];
#pragma unroll
    for (int i = 0; i < 2; i++)
#pragma unroll
        for (int j = 0; j < 4; j++)
#pragma unroll
            for (int e = 0; e < 4; e++) acc[i][j][e] = 0.f;

    const int nit = K / 32;

#pragma unroll
    for (int pi = 0; pi < 2; pi++) {
        uint32_t dst = sb + pi * STG64;
        int kof = pi * 32;
        CP16(dst + OFF_AH + soA0, aHi0 + kof);
        CP16(dst + OFF_AH + soA1, aHi1 + kof);
        CP16(dst + OFF_AL + soA0, aLo0 + kof);
        CP16(dst + OFF_AL + soA1, aLo1 + kof);
        CP16(dst + OFF_BH + soB,  bHi  + kof);
        CP16(dst + OFF_BL + soB,  bLo  + kof);
        CPCOMMIT();
    }

    for (int it = 0; it < nit; it++) {
        if (it + 1 < nit) { CPWAIT1(); } else { CPWAIT0(); }
        __syncthreads();

        const uint32_t stb = sb + (it & 1) * STG64;
#pragma unroll
        for (int ks = 0; ks < 2; ks++) {
            uint32_t ah[2][4], al[2][4], bh[4][2], bl[4][2];
#pragma unroll
            for (int mt = 0; mt < 2; mt++) {
                uint32_t ra = (uint32_t)((wm * 32 + mt * 16 + arow) * RSB + ks * 32 + akh * 16);
                ldmx4(ah[mt], stb + OFF_AH + ra);
                ldmx4(al[mt], stb + OFF_AL + ra);
            }
#pragma unroll
            for (int g = 0; g < 2; g++) {
                uint32_t rbr = (uint32_t)((wn * 32 + g * 16 + brow) * RSB + ks * 32 + bkh * 16);
                uint32_t t0[4], t1[4];
                ldmx4(t0, stb + OFF_BH + rbr);
                ldmx4(t1, stb + OFF_BL + rbr);
                bh[g * 2][0] = t0[0]; bh[g * 2][1] = t0[1];
                bh[g * 2 + 1][0] = t0[2]; bh[g * 2 + 1][1] = t0[3];
                bl[g * 2][0] = t1[0]; bl[g * 2][1] = t1[1];
                bl[g * 2 + 1][0] = t1[2]; bl[g * 2 + 1][1] = t1[3];
            }
#pragma unroll
            for (int mt = 0; mt < 2; mt++)
#pragma unroll
                for (int nt = 0; nt < 4; nt++) {
                    mma16816(acc[mt][nt], ah[mt], bh[nt]);
                    mma16816(acc[mt][nt], ah[mt], bl[nt]);
                    mma16816(acc[mt][nt], al[mt], bh[nt]);
                }
        }
        __syncthreads();

        if (it + 2 < nit) {
            uint32_t dst = sb + (it & 1) * STG64;
            int kof = (it + 2) * 32;
            CP16(dst + OFF_AH + soA0, aHi0 + kof);
            CP16(dst + OFF_AH + soA1, aHi1 + kof);
            CP16(dst + OFF_AL + soA0, aLo0 + kof);
            CP16(dst + OFF_AL + soA1, aLo1 + kof);
            CP16(dst + OFF_BH + soB,  bHi  + kof);
            CP16(dst + OFF_BL + soB,  bLo  + kof);
            CPCOMMIT();
        }
    }

#pragma unroll
    for (int mt = 0; mt < 2; mt++) {
#pragma unroll
        for (int half = 0; half < 2; half++) {
            int r = m0 + wm * 32 + mt * 16 + (lane >> 2) + half * 8;
            if (r >= M) continue;
            float* Crow = C + (size_t)r * ldc;
#pragma unroll
            for (int nt = 0; nt < 4; nt++) {
                int n = n0 + wn * 32 + nt * 8 + (lane & 3) * 2;
                if (n + 1 < N) {
                    float v0 = acc[mt][nt][half * 2 + 0];
                    float v1 = acc[mt][nt][half * 2 + 1];
                    if (bias) { v0 += bias[n]; v1 += bias[n + 1]; }
                    *(float2*)(Crow + n) = make_float2(v0, v1);
                } else if (n < N) {
                    float v0 = acc[mt][nt][half * 2 + 0];
                    if (bias) v0 += bias[n];
                    Crow[n] = v0;
                }
            }
        }
    }
}

// ==================== conversions ====================
// vectorized split: 4 elements/thread (requires total % 4 == 0, no row padding)
__global__ void conv_split4(const float* __restrict__ src, __nv_bfloat16* __restrict__ hi,
                            __nv_bfloat16* __restrict__ lo, int total4)
{
    int idx = blockIdx.x * 256 + threadIdx.x;
    if (idx >= total4) return;
    float4 v = ((const float4*)src)[idx];
    __nv_bfloat162 h01, h23, l01, l23;
    h01.x = __float2bfloat16(v.x); h01.y = __float2bfloat16(v.y);
    h23.x = __float2bfloat16(v.z); h23.y = __float2bfloat16(v.w);
    l01.x = __float2bfloat16(v.x - __bfloat162float(h01.x));
    l01.y = __float2bfloat16(v.y - __bfloat162float(h01.y));
    l23.x = __float2bfloat16(v.z - __bfloat162float(h23.x));
    l23.y = __float2bfloat16(v.w - __bfloat162float(h23.y));
    ((uint2*)hi)[idx] = make_uint2(*(uint32_t*)&h01, *(uint32_t*)&h23);
    ((uint2*)lo)[idx] = make_uint2(*(uint32_t*)&l01, *(uint32_t*)&l23);
}

__global__ void conv_split(const float* __restrict__ src, __nv_bfloat16* __restrict__ hi,
                           __nv_bfloat16* __restrict__ lo, int M, int K, int Mpad)
{
    int idx = blockIdx.x * 256 + threadIdx.x;
    if (idx >= Mpad * K) return;
    float v;
    if (M == Mpad) {
        v = src[idx];
    } else {
        int r = idx / K;
        v = (r < M) ? src[idx] : 0.f;
    }
    __nv_bfloat16 h = __float2bfloat16(v);
    hi[idx] = h;
    lo[idx] = __float2bfloat16(v - __bfloat162float(h));
}

__global__ void conv_splitT(const float* __restrict__ src, int ldsrc,
                            __nv_bfloat16* __restrict__ hi, __nv_bfloat16* __restrict__ lo,
                            int K, int N, int Npad)
{
    __shared__ float tile[32][33];
    int n0 = blockIdx.x * 32, k0 = blockIdx.y * 32;
    int tx = threadIdx.x, ty = threadIdx.y;
#pragma unroll
    for (int i = 0; i < 32; i += 8) {
        int n = n0 + tx;
        tile[ty + i][tx] = (n < N) ? src[(size_t)(k0 + ty + i) * ldsrc + n] : 0.f;
    }
    __syncthreads();
#pragma unroll
    for (int i = 0; i < 32; i += 8) {
        int n = n0 + ty + i, k = k0 + tx;
        if (n < Npad) {
            float v = tile[tx][ty + i];
            __nv_bfloat16 h = __float2bfloat16(v);
            hi[(size_t)n * K + k] = h;
            lo[(size_t)n * K + k] = __float2bfloat16(v - __bfloat162float(h));
        }
    }
}

__global__ void pad_hall_kernel()
{
    int idx = blockIdx.x * 256 + threadIdx.x;
    if (idx >= (Mp - Mrows) * Hn) return;
    g_hallh[Mrows * Hn + idx] = __float2bfloat16(0.f);
    g_halll[Mrows * Hn + idx] = __float2bfloat16(0.f);
}

// ==================== 3-segment fast step GEMM (R7-proven) ====================
__global__ __launch_bounds__(128)
void gemm_pass3(const float* A0, int lda0, const float* B0, int ldb0, float* P0, int N0, int K0, int ks0,
                const float* A1, int lda1, const float* B1, int ldb1, float* P1, int N1, int K1, int ks1,
                const float* A2, int lda2, const float* B2, int ldb2, float* P2, int N2, int K2, int ks2)
{
    const float *A, *B; float* P;
    int lda, ldb, N, K, ks;
    int id = blockIdx.x;
    const int b0 = (N0 / 32) * ks0, b1 = (N1 / 32) * ks1;
    if (id < b0)            { A=A0; B=B0; P=P0; lda=lda0; ldb=ldb0; N=N0; K=K0; ks=ks0; }
    else if (id < b0 + b1)  { id -= b0; A=A1; B=B1; P=P1; lda=lda1; ldb=ldb1; N=N1; K=K1; ks=ks1; }
    else                    { id -= b0 + b1; A=A2; B=B2; P=P2; lda=lda2; ldb=ldb2; N=N2; K=K2; ks=ks2; }

    const int nt = N / 32;
    const int ntile = id % nt, ksi = id / nt;
    const int kLen = K / ks;
    const int kbeg = ksi * kLen;
    const int n0 = ntile * 32;

    __shared__ __align__(16) float As[32][68];
    __shared__ __align__(16) float Bs[64][36];

    const int tid = threadIdx.x;
    const int m = (tid >> 3) * 2;
    const int nn = (tid & 7) * 4;

    float acc[2][4];
#pragma unroll
    for (int i = 0; i < 2; i++)
#pragma unroll
        for (int j = 0; j < 4; j++) acc[i][j] = 0.f;

    for (int kb = kbeg; kb < kbeg + kLen; kb += 64) {
#pragma unroll
        for (int i = 0; i < 4; i++) {
            int fi = tid + 128 * i;
            int ar = fi >> 4, ac = (fi & 15) * 4;
            *(float4*)&As[ar][ac] = *(const float4*)(A + (size_t)ar * lda + kb + ac);
            int br = fi >> 3, bc = (fi & 7) * 4;
            *(float4*)&Bs[br][bc] = *(const float4*)(B + (size_t)(kb + br) * ldb + n0 + bc);
        }
        __syncthreads();
#pragma unroll
        for (int k = 0; k < 64; k++) {
            float a0 = As[m][k], a1 = As[m + 1][k];
            float4 b4 = *(float4*)&Bs[k][nn];
            acc[0][0] = fmaf(a0, b4.x, acc[0][0]); acc[0][1] = fmaf(a0, b4.y, acc[0][1]);
            acc[0][2] = fmaf(a0, b4.z, acc[0][2]); acc[0][3] = fmaf(a0, b4.w, acc[0][3]);
            acc[1][0] = fmaf(a1, b4.x, acc[1][0]); acc[1][1] = fmaf(a1, b4.y, acc[1][1]);
            acc[1][2] = fmaf(a1, b4.z, acc[1][2]); acc[1][3] = fmaf(a1, b4.w, acc[1][3]);
        }
        __syncthreads();
    }

    float* dst = P + (size_t)ksi * 32 * N + n0;
    *(float4*)(dst + (size_t)m * N + nn)       = make_float4(acc[0][0], acc[0][1], acc[0][2], acc[0][3]);
    *(float4*)(dst + (size_t)(m + 1) * N + nn) = make_float4(acc[1][0], acc[1][1], acc[1][2], acc[1][3]);
}

// ==================== init-only small GEMM (split-K) ====================
__global__ __launch_bounds__(64)
void gemm_pass(const float* A0, int lda0, const float* B0, int ldb0, float* P0, int N0, int K0, int ks0, int nt0,
               const float* A1, int lda1, const float* B1, int ldb1, float* P1, int N1, int K1, int ks1, int nt1)
{
    const float* A; const float* B; float* P;
    int N, K, ks, nt, lda, ldb;
    int id = blockIdx.x;
    int blocks0 = nt0 * ks0;
    if (id < blocks0) { A=A0; B=B0; P=P0; N=N0; K=K0; ks=ks0; nt=nt0; lda=lda0; ldb=ldb0; }
    else { id -= blocks0; A=A1; B=B1; P=P1; N=N1; K=K1; ks=ks1; nt=nt1; lda=lda1; ldb=ldb1; }

    int ntile = id % nt;
    int ksi   = id / nt;
    int kLen  = K / ks;
    int kbeg  = ksi * kLen, kend = kbeg + kLen;
    int n0    = ntile * 32;

    __shared__ float As[32][36];
    __shared__ float Bs[32][32];
    const int tid = threadIdx.x;
    const int tx = tid & 7, ty = tid >> 3;
    const int lrow = tid >> 3, lc4 = tid & 7;

    float acc[4][4];
#pragma unroll
    for (int i = 0; i < 4; i++)
#pragma unroll
        for (int j = 0; j < 4; j++) acc[i][j] = 0.f;

    for (int k0 = kbeg; k0 < kend; k0 += 32) {
#pragma unroll
        for (int i = 0; i < 4; i++)
            *(float4*)&As[lrow + 8 * i][lc4 * 4] =
                *(const float4*)(A + (size_t)(lrow + 8 * i) * lda + k0 + lc4 * 4);
#pragma unroll
        for (int i = 0; i < 4; i++)
            *(float4*)&Bs[lrow + 8 * i][lc4 * 4] =
                *(const float4*)(B + (size_t)(k0 + lrow + 8 * i) * ldb + n0 + lc4 * 4);
        __syncthreads();
#pragma unroll
        for (int kk = 0; kk < 32; kk++) {
            float a[4];
#pragma unroll
            for (int i = 0; i < 4; i++) a[i] = As[ty * 4 + i][kk];
            float4 bv = *(float4*)&Bs[kk][tx * 4];
#pragma unroll
            for (int i = 0; i < 4; i++) {
                acc[i][0] = fmaf(a[i], bv.x, acc[i][0]);
                acc[i][1] = fmaf(a[i], bv.y, acc[i][1]);
                acc[i][2] = fmaf(a[i], bv.z, acc[i][2]);
                acc[i][3] = fmaf(a[i], bv.w, acc[i][3]);
            }
        }
        __syncthreads();
    }
    float* dst = P + (size_t)ksi * 32 * N;
#pragma unroll
    for (int i = 0; i < 4; i++) {
        int m = ty * 4 + i;
#pragma unroll
        for (int j = 0; j < 4; j++)
            dst[(size_t)m * N + n0 + tx * 4 + j] = acc[i][j];
    }
}

__global__ void reduce2_kernel(float* d0, const float* P0, int ks0, int N0, const float* b0, int act0, int cnt0,
                               float* d1, const float* P1, int ks1, int N1, const float* b1, int act1, int cnt1)
{
    int i = blockIdx.x * 256 + threadIdx.x;
    float* d; const float* P; int ks, N; const float* bi; int act; int cnt;
    if (i < cnt0) { d=d0; P=P0; ks=ks0; N=N0; bi=b0; act=act0; cnt=cnt0; }
    else { i -= cnt0; d=d1; P=P1; ks=ks1; N=N1; bi=b1; act=act1; cnt=cnt1; }
    if (i >= cnt) return;
    float v = 0.f;
    for (int s = 0; s < ks; s++) v += P[(size_t)s * cnt + i];
    if (bi) v += bi[i % N];
    if (act == 1) v = tanhf(v);
    else if (act == 2) v = sigf(v);
    d[i] = v;
}

__global__ void avg_kernel(const float* __restrict__ img)
{
    int idx = blockIdx.x * blockDim.x + threadIdx.x;
    if (idx >= Bsz * (Dn / 4)) return;
    int b = idx >> 9;
    const float4* ip = (const float4*)img + (size_t)b * Pn * (Dn / 4) + (idx & 511);
    float4 s = make_float4(0.f, 0.f, 0.f, 0.f);
    for (int p = 0; p < Pn; p++) {
        float4 x = ip[(size_t)p * (Dn / 4)];
        s.x += x.x; s.y += x.y; s.z += x.z; s.w += x.w;
    }
    const float inv = 1.f / (float)Pn;
    s.x *= inv; s.y *= inv; s.z *= inv; s.w *= inv;
    ((float4*)g_avg)[idx] = s;
}

__global__ void emb_kernel(const int* __restrict__ caps, const float* __restrict__ E)
{
    int idx = blockIdx.x * blockDim.x + threadIdx.x;
    if (idx >= Bsz * Tn * Hn) return;
    int r = idx / Hn;
    int h = idx - r * Hn;
    int b = r / Tn, t = r - b * Tn;
    g_emb[idx] = E[(size_t)caps[b * 20 + t] * Hn + h];
}

// ==================== fused attention step (R7, static smem) ====================
__global__ __launch_bounds__(1024)
void attctx_kernel(const float* __restrict__ img,
                   const float* __restrict__ v_att, const float* __restrict__ b_v_att,
                   const float* __restrict__ b_att_h, const float* __restrict__ b_fbeta,
                   float* __restrict__ out_alphas, int t)
{
    const int b = blockIdx.x, tid = threadIdx.x;
    const int w = tid >> 5, lane = tid & 31;
    __shared__ float hp[Hn];
    __shared__ float va[Hn];
    __shared__ float ee[Pn];
    __shared__ float sred[8];
    __shared__ __align__(16) float4 redD[2 * (Dn / 4)];

    if (tid < Hn) {
        float v = b_att_h[tid];
#pragma unroll
        for (int s = 0; s < 8; s++) v += g_pp_h[s * Bsz * Hn + b * Hn + tid];
        hp[tid] = v;
        va[tid] = v_att[tid];
    }
    __syncthreads();

    const float* ai = g_att_img + (size_t)b * Pn * Hn;
    const float bv0 = b_v_att[0];
    for (int p = w; p < Pn; p += 32) {
        const float* aip = ai + (size_t)p * Hn;
        float s = 0.f;
#pragma unroll
        for (int ii = 0; ii < Hn / 32; ii++) {
            int hx = lane + 32 * ii;
            float x = aip[hx] + hp[hx];
            float th;
            asm("tanh.approx.f32 %0, %1;" : "=f"(th) : "f"(x));
            s = fmaf(th, va[hx], s);
        }
#pragma unroll
        for (int o = 16; o; o >>= 1) s += __shfl_down_sync(0xffffffffu, s, o);
        if (lane == 0) ee[p] = s + bv0;
    }
    __syncthreads();

    float v = (tid < Pn) ? ee[tid] : -1e30f;
    if (tid < 256) {
        float m = v;
#pragma unroll
        for (int o = 16; o; o >>= 1) m = fmaxf(m, __shfl_xor_sync(0xffffffffu, m, o));
        if (lane == 0) sred[w] = m;
    }
    __syncthreads();
    if (tid < 32) {
        float mm = (tid < 8) ? sred[tid] : -1e30f;
#pragma unroll
        for (int o = 4; o; o >>= 1) mm = fmaxf(mm, __shfl_xor_sync(0xffffffffu, mm, o));
        if (tid == 0) sred[0] = mm;
    }
    __syncthreads();
    float exv = (tid < Pn) ? expf(v - sred[0]) : 0.f;
    __syncthreads();
    if (tid < 256) {
        float s = exv;
#pragma unroll
        for (int o = 16; o; o >>= 1) s += __shfl_xor_sync(0xffffffffu, s, o);
        if (lane == 0) sred[w] = s;
    }
    __syncthreads();
    if (tid < 32) {
        float ss = (tid < 8) ? sred[tid] : 0.f;
#pragma unroll
        for (int o = 4; o; o >>= 1) ss += __shfl_xor_sync(0xffffffffu, ss, o);
        if (tid == 0) sred[0] = ss;
    }
    __syncthreads();
    if (tid < Pn) {
        float a = exv / sred[0];
        ee[tid] = a;
        out_alphas[((size_t)b * Tn + t) * Pn + tid] = a;
    }
    __syncthreads();

    const int ps = tid >> 9;
    const int d4 = tid & 511;
    const float4* ip = (const float4*)img + (size_t)b * Pn * (Dn / 4) + d4;
    float4 cx = make_float4(0.f, 0.f, 0.f, 0.f);
#pragma unroll 8
    for (int p = ps; p < Pn; p += 2) {
        float a = ee[p];
        float4 x = ip[(size_t)p * (Dn / 4)];
        cx.x = fmaf(a, x.x, cx.x); cx.y = fmaf(a, x.y, cx.y);
        cx.z = fmaf(a, x.z, cx.z); cx.w = fmaf(a, x.w, cx.w);
    }
    redD[ps * (Dn / 4) + d4] = cx;
    __syncthreads();
    if (tid < Dn / 4) {
        float4 r0 = redD[tid], r1 = redD[(Dn / 4) + tid];
        float4 gb = *(const float4*)(b_fbeta + tid * 4);
#pragma unroll
        for (int sp = 0; sp < 8; sp++) {
            float4 pv = ((const float4*)g_pp_g)[sp * (Bsz * Dn / 4) + b * (Dn / 4) + tid];
            gb.x += pv.x; gb.y += pv.y; gb.z += pv.z; gb.w += pv.w;
        }
        float4 o4;
        o4.x = (r0.x + r1.x) * sigf(gb.x);
        o4.y = (r0.y + r1.y) * sigf(gb.y);
        o4.z = (r0.z + r1.z) * sigf(gb.z);
        o4.w = (r0.w + r1.w) * sigf(gb.w);
        ((float4*)g_xc)[b * (Dn / 4) + tid] = o4;
    }
}

// LSTM pointwise: sum 8 pa + 4 pb partials + embW + biases; writes h + bf16 split
__global__ void lstm_kernel(const float* __restrict__ bih, const float* __restrict__ bhh, int t)
{
    int idx = blockIdx.x * blockDim.x + threadIdx.x;
    if (idx >= Bsz * Hn) return;
    int b = idx >> 9;
    int j = idx & 511;
    int rowE = (b * Tn + t) * 4 * Hn;
    int rowP = b * 4 * Hn;

    float gv[4];
#pragma unroll
    for (int g = 0; g < 4; g++) {
        int n = g * Hn + j;
        float v = g_embW[rowE + n] + bih[n] + bhh[n];
#pragma unroll
        for (int s = 0; s < 8; s++) v += g_pa[s * Bsz * 4 * Hn + rowP + n];
#pragma unroll
        for (int s = 0; s < 4; s++) v += g_pb[s * Bsz * 4 * Hn + rowP + n];
        gv[g] = v;
    }
    float c = sigf(gv[1]) * g_c[idx] + sigf(gv[0]) * tanhf(gv[2]);
    g_c[idx] = c;
    float h = sigf(gv[3]) * tanhf(c);
    g_h[idx] = h;
    size_t ro = (size_t)(t * Bsz + b) * Hn + j;
    __nv_bfloat16 hh = __float2bfloat16(h);
    g_hallh[ro] = hh;
    g_halll[ro] = __float2bfloat16(h - __bfloat162float(hh));
}

// ================================================================================
extern "C" void kernel_launch(void* const* d_in, const int* in_sizes, int n_in,
                              void* d_out, int out_size)
{
    const float* img      = (const float*)d_in[0];
    const int*   caps     = (const int*)d_in[1];
    const float* Wih      = (const float*)d_in[2];
    const float* Whh      = (const float*)d_in[3];
    const float* bih      = (const float*)d_in[4];
    const float* bhh      = (const float*)d_in[5];
    const float* W_init_h = (const float*)d_in[6];
    const float* b_init_h = (const float*)d_in[7];
    const float* W_init_c = (const float*)d_in[8];
    const float* b_init_c = (const float*)d_in[9];
    const float* W_fbeta  = (const float*)d_in[10];
    const float* b_fbeta  = (const float*)d_in[11];
    const float* W_out    = (const float*)d_in[12];
    const float* b_out    = (const float*)d_in[13];
    const float* W_att_im = (const float*)d_in[14];
    const float* b_att_im = (const float*)d_in[15];
    const float* W_att_h  = (const float*)d_in[16];
    const float* b_att_h  = (const float*)d_in[17];
    const float* v_att    = (const float*)d_in[18];
    const float* b_v_att  = (const float*)d_in[19];
    const float* E        = (const float*)d_in[20];

    float* preds  = (float*)d_out;
    float* alphas = (float*)d_out + (size_t)Bsz * Tn * Vn;

    float *p_avg, *p_h, *p_c, *p_att, *p_emb, *p_embW, *p_xc, *p_pph, *p_ppg;
    float *p_pa, *p_pb, *p_pih, *p_pic;
    __nv_bfloat16 *p_imgh, *p_imgl, *p_watth, *p_wattl, *p_wouth, *p_woutl;
    __nv_bfloat16 *p_wihh, *p_wihl, *p_embh, *p_embl, *p_hallh, *p_halll;
    cudaGetSymbolAddress((void**)&p_avg,   g_avg);
    cudaGetSymbolAddress((void**)&p_h,     g_h);
    cudaGetSymbolAddress((void**)&p_c,     g_c);
    cudaGetSymbolAddress((void**)&p_att,   g_att_img);
    cudaGetSymbolAddress((void**)&p_emb,   g_emb);
    cudaGetSymbolAddress((void**)&p_embW,  g_embW);
    cudaGetSymbolAddress((void**)&p_xc,    g_xc);
    cudaGetSymbolAddress((void**)&p_pph,   g_pp_h);
    cudaGetSymbolAddress((void**)&p_ppg,   g_pp_g);
    cudaGetSymbolAddress((void**)&p_pa,    g_pa);
    cudaGetSymbolAddress((void**)&p_pb,    g_pb);
    cudaGetSymbolAddress((void**)&p_pih,   g_pi_h);
    cudaGetSymbolAddress((void**)&p_pic,   g_pi_c);
    cudaGetSymbolAddress((void**)&p_imgh,  g_img_hi);
    cudaGetSymbolAddress((void**)&p_imgl,  g_img_lo);
    cudaGetSymbolAddress((void**)&p_watth, g_watt_hi);
    cudaGetSymbolAddress((void**)&p_wattl, g_watt_lo);
    cudaGetSymbolAddress((void**)&p_wouth, g_wout_hi);
    cudaGetSymbolAddress((void**)&p_woutl, g_wout_lo);
    cudaGetSymbolAddress((void**)&p_wihh,  g_wih_hi);
    cudaGetSymbolAddress((void**)&p_wihl,  g_wih_lo);
    cudaGetSymbolAddress((void**)&p_embh,  g_embh);
    cudaGetSymbolAddress((void**)&p_embl,  g_embl);
    cudaGetSymbolAddress((void**)&p_hallh, g_hallh);
    cudaGetSymbolAddress((void**)&p_halll, g_halll);

    cudaFuncSetAttribute(hmma_gemm<0>, cudaFuncAttributeMaxDynamicSharedMemorySize, HMMA_SMEM);
    cudaFuncSetAttribute(hmma_gemm<1>, cudaFuncAttributeMaxDynamicSharedMemorySize, HMMA_SMEM);
    cudaFuncSetAttribute(hmma_gemm64,  cudaFuncAttributeMaxDynamicSharedMemorySize, HMMA64_SMEM);

    // ---- setup (launch index 3 = att hmma64 -> ncu slot) ----
    conv_split4<<<(Bsz * Pn * Dn / 4 + 255) / 256, 256>>>(img, p_imgh, p_imgl, Bsz * Pn * Dn / 4);    // 0
    conv_splitT<<<dim3(Hn / 32, Dn / 32), dim3(32, 8)>>>(W_att_im, Hn, p_watth, p_wattl, Dn, Hn, Hn); // 1
    avg_kernel<<<64, 256>>>(img);                                                                     // 2
    hmma_gemm64<<<dim3(Hn / 64, (Bsz * Pn) / 128), 256, HMMA64_SMEM>>>(                               // 3 <- ncu
        p_imgh, p_imgl, p_watth, p_wattl, b_att_im, p_att, Bsz * Pn, Hn, Dn, Hn);
    conv_splitT<<<dim3(Vp / 32, Hn / 32), dim3(32, 8)>>>(W_out, Vn, p_wouth, p_woutl, Hn, Vn, Vp);
    conv_splitT<<<dim3(4 * Hn / 32, Hn / 32), dim3(32, 8)>>>(Wih, 4 * Hn, p_wihh, p_wihl, Hn, 4 * Hn, 4 * Hn);
    gemm_pass<<<256, 64>>>(p_avg, Dn, W_init_h, Hn, p_pih, Hn, Dn, 8, 16,
                           p_avg, Dn, W_init_c, Hn, p_pic, Hn, Dn, 8, 16);
    reduce2_kernel<<<128, 256>>>(p_h, p_pih, 8, Hn, b_init_h, 1, Bsz * Hn,
                                 p_c, p_pic, 8, Hn, b_init_c, 1, Bsz * Hn);
    emb_kernel<<<(Bsz * Tn * Hn) / 256, 256>>>(caps, E);
    conv_split<<<(Mp * Hn) / 256, 256>>>(p_emb, p_embh, p_embl, Mrows, Hn, Mp);
    hmma_gemm64<<<dim3(4 * Hn / 64, Mp / 128), 256, HMMA64_SMEM>>>(
        p_embh, p_embl, p_wihh, p_wihl, nullptr, p_embW, Mrows, 4 * Hn, Hn, 4 * Hn);
    pad_hall_kernel<<<((Mp - Mrows) * Hn + 255) / 256, 256>>>();

    const float* WihBot = Wih + (size_t)Hn * 4 * Hn;

    // ---- recurrent steps: exact R7 structure ----
    for (int t = 0; t < Tn; t++) {
        // pass1: hproj (ks=8, 128 blk) + fbeta (ks=8, 512 blk) + Whh (ks=4, 256 blk)
        gemm_pass3<<<128 + 512 + 256, 128>>>(
            p_h, Hn, W_att_h, Hn,     p_pph, Hn,     Hn, 8,
            p_h, Hn, W_fbeta, Dn,     p_ppg, Dn,     Hn, 8,
            p_h, Hn, Whh,     4 * Hn, p_pb,  4 * Hn, Hn, 4);
        attctx_kernel<<<Bsz, 1024>>>(img, v_att, b_v_att, b_att_h, b_fbeta, alphas, t);
        // pass2: Wih_bot (ks=8, 512 blk)
        gemm_pass3<<<512, 128>>>(
            p_xc, Dn, WihBot, 4 * Hn, p_pa, 4 * Hn, Dn, 8,
            p_xc, Dn, WihBot, 4 * Hn, p_pa, 0,      Dn, 8,
            p_xc, Dn, WihBot, 4 * Hn, p_pa, 0,      Dn, 8);
        lstm_kernel<<<(Bsz * Hn) / 256, 256>>>(bih, bhh, t);
    }

    // ---- final: preds = h_all @ W_out + b_out ----
    hmma_gemm<1><<<dim3(Vp / 128, Mp / 128), 256, HMMA_SMEM>>>(
        p_hallh, p_halll, p_wouth, p_woutl, b_out, preds, Mrows, Vn, Hn, Vn);
}

// round 16
// speedup vs baseline: 1.3252x; 1.0549x over previous
#include <cuda_runtime.h>
#include <cuda_bf16.h>
#include <math.h>
#include <stdint.h>

#define Bsz 32
#define Pn  196
#define Dn  2048
#define Hn  512
#define Vn  30000
#define Tn  19
#define Vp  30080
#define Mrows 608
#define Mp  640

// ---------------- fp32 scratch ----------------
__device__ float g_avg[Bsz * Dn];
__device__ float g_h[Bsz * Hn];
__device__ float g_c[Bsz * Hn];
__device__ float g_att_img[Bsz * Pn * Hn];
__device__ float g_emb[Bsz * Tn * Hn];
__device__ float g_embW[Bsz * Tn * 4 * Hn];
__device__ float g_xc[Bsz * Dn];
__device__ float g_pp_h[8 * Bsz * Hn];           // hproj (ks=8)
__device__ float g_pp_g[8 * Bsz * Dn];           // fbeta (ks=8)
__device__ float g_pa[8 * Bsz * 4 * Hn];         // xc@Wih_bot (ks=8)
__device__ float g_pb[4 * Bsz * 4 * Hn];         // h@Whh (ks=4)
__device__ float g_pi_h[8 * Bsz * Hn];
__device__ float g_pi_c[8 * Bsz * Hn];

// ---------------- bf16 split scratch ----------------
__device__ __nv_bfloat16 g_img_hi[Bsz * Pn * Dn];
__device__ __nv_bfloat16 g_img_lo[Bsz * Pn * Dn];
__device__ __nv_bfloat16 g_watt_hi[Hn * Dn];
__device__ __nv_bfloat16 g_watt_lo[Hn * Dn];
__device__ __nv_bfloat16 g_wout_hi[Vp * Hn];
__device__ __nv_bfloat16 g_wout_lo[Vp * Hn];
__device__ __nv_bfloat16 g_wih_hi[4 * Hn * Hn];
__device__ __nv_bfloat16 g_wih_lo[4 * Hn * Hn];
__device__ __nv_bfloat16 g_embh[Mp * Hn];
__device__ __nv_bfloat16 g_embl[Mp * Hn];
__device__ __nv_bfloat16 g_hallh[Mp * Hn];
__device__ __nv_bfloat16 g_halll[Mp * Hn];

__device__ __forceinline__ float sigf(float x) { return 1.f / (1.f + expf(-x)); }

__device__ __forceinline__ uint32_t smem_u32(const void* p) {
    uint32_t a;
    asm("{ .reg .u64 t; cvta.to.shared.u64 t, %1; cvt.u32.u64 %0, t; }" : "=r"(a) : "l"(p));
    return a;
}
__device__ __forceinline__ void ldmx4(uint32_t* r, uint32_t addr) {
    asm volatile("ldmatrix.sync.aligned.m8n8.x4.shared.b16 {%0,%1,%2,%3}, [%4];"
                 : "=r"(r[0]), "=r"(r[1]), "=r"(r[2]), "=r"(r[3]) : "r"(addr));
}
__device__ __forceinline__ void mma16816(float* d, const uint32_t* a, const uint32_t* b) {
    asm volatile(
        "mma.sync.aligned.m16n8k16.row.col.f32.bf16.bf16.f32 "
        "{%0,%1,%2,%3}, {%4,%5,%6,%7}, {%8,%9}, {%0,%1,%2,%3};"
        : "+f"(d[0]), "+f"(d[1]), "+f"(d[2]), "+f"(d[3])
        : "r"(a[0]), "r"(a[1]), "r"(a[2]), "r"(a[3]), "r"(b[0]), "r"(b[1]));
}
#define CP16(s, g)  asm volatile("cp.async.cg.shared.global [%0], [%1], 16;" :: "r"(s), "l"(g))
#define CPCOMMIT()  asm volatile("cp.async.commit_group;" ::: "memory")
#define CPWAIT1()   asm volatile("cp.async.wait_group 1;" ::: "memory")
#define CPWAIT0()   asm volatile("cp.async.wait_group 0;" ::: "memory")

#define RSB 80

// ==================== hmma 128x128 (preds) ====================
#define TSZ (128 * RSB)
#define STG (4 * TSZ)
#define HMMA_SMEM (2 * STG)      // 81920

template <int OUTMAP>
__global__ __launch_bounds__(256, 2)
void hmma_gemm(const __nv_bfloat16* __restrict__ Ahi, const __nv_bfloat16* __restrict__ Alo,
               const __nv_bfloat16* __restrict__ Bhi, const __nv_bfloat16* __restrict__ Blo,
               const float* __restrict__ bias, float* __restrict__ C,
               int M, int N, int K, int ldc)
{
    extern __shared__ char smc[];
    const uint32_t sb = smem_u32(smc);
    const int tid = threadIdx.x;
    const int lane = tid & 31, wid = tid >> 5;
    const int wm = wid & 1, wn = wid >> 1;
    const int m0 = blockIdx.y * 128, n0 = blockIdx.x * 128;

    int r0 = tid >> 2, c0 = tid & 3;
    int r1 = (tid + 256) >> 2, c1 = tid & 3;
    const __nv_bfloat16* base0[4] = {
        Ahi + (size_t)(m0 + r0) * K + c0 * 8,
        Alo + (size_t)(m0 + r0) * K + c0 * 8,
        Bhi + (size_t)(n0 + r0) * K + c0 * 8,
        Blo + (size_t)(n0 + r0) * K + c0 * 8 };
    const __nv_bfloat16* base1[4] = {
        Ahi + (size_t)(m0 + r1) * K + c1 * 8,
        Alo + (size_t)(m0 + r1) * K + c1 * 8,
        Bhi + (size_t)(n0 + r1) * K + c1 * 8,
        Blo + (size_t)(n0 + r1) * K + c1 * 8 };
    const uint32_t so0 = (uint32_t)(r0 * RSB + c0 * 16);
    const uint32_t so1 = (uint32_t)(r1 * RSB + c1 * 16);

    const int arow = (lane & 7) | (((lane >> 3) & 1) << 3);
    const int akh  = lane >> 4;
    const int brow = (lane & 7) + ((lane >> 4) << 3);
    const int bkh  = (lane >> 3) & 1;

    float acc[4][4][4];
#pragma unroll
    for (int i = 0; i < 4; i++)
#pragma unroll
        for (int j = 0; j < 4; j++)
#pragma unroll
            for (int e = 0; e < 4; e++) acc[i][j][e] = 0.f;

    const int nit = K / 32;

#pragma unroll
    for (int pi = 0; pi < 2; pi++) {
        uint32_t dst = sb + pi * STG;
        int kof = pi * 32;
#pragma unroll
        for (int tno = 0; tno < 4; tno++) {
            CP16(dst + tno * TSZ + so0, base0[tno] + kof);
            CP16(dst + tno * TSZ + so1, base1[tno] + kof);
        }
        CPCOMMIT();
    }

    for (int it = 0; it < nit; it++) {
        if (it + 1 < nit) { CPWAIT1(); } else { CPWAIT0(); }
        __syncthreads();

        const uint32_t stb = sb + (it & 1) * STG;
#pragma unroll
        for (int ks = 0; ks < 2; ks++) {
            uint32_t ah[4][4], al[4][4], bh[4][2], bl[4][2];
#pragma unroll
            for (int mt = 0; mt < 4; mt++) {
                uint32_t ra = (uint32_t)((wm * 64 + mt * 16 + arow) * RSB + ks * 32 + akh * 16);
                ldmx4(ah[mt], stb + 0 * TSZ + ra);
                ldmx4(al[mt], stb + 1 * TSZ + ra);
            }
#pragma unroll
            for (int g = 0; g < 2; g++) {
                uint32_t rb = (uint32_t)((wn * 32 + g * 16 + brow) * RSB + ks * 32 + bkh * 16);
                uint32_t t0[4], t1[4];
                ldmx4(t0, stb + 2 * TSZ + rb);
                ldmx4(t1, stb + 3 * TSZ + rb);
                bh[g * 2][0] = t0[0]; bh[g * 2][1] = t0[1];
                bh[g * 2 + 1][0] = t0[2]; bh[g * 2 + 1][1] = t0[3];
                bl[g * 2][0] = t1[0]; bl[g * 2][1] = t1[1];
                bl[g * 2 + 1][0] = t1[2]; bl[g * 2 + 1][1] = t1[3];
            }
#pragma unroll
            for (int mt = 0; mt < 4; mt++)
#pragma unroll
                for (int nt = 0; nt < 4; nt++) {
                    mma16816(acc[mt][nt], ah[mt], bh[nt]);
                    mma16816(acc[mt][nt], ah[mt], bl[nt]);
                    mma16816(acc[mt][nt], al[mt], bh[nt]);
                }
        }
        __syncthreads();

        if (it + 2 < nit) {
            uint32_t dst = sb + (it & 1) * STG;
            int kof = (it + 2) * 32;
#pragma unroll
            for (int tno = 0; tno < 4; tno++) {
                CP16(dst + tno * TSZ + so0, base0[tno] + kof);
                CP16(dst + tno * TSZ + so1, base1[tno] + kof);
            }
            CPCOMMIT();
        }
    }

#pragma unroll
    for (int mt = 0; mt < 4; mt++) {
#pragma unroll
        for (int half = 0; half < 2; half++) {
            int r = m0 + wm * 64 + mt * 16 + (lane >> 2) + half * 8;
            bool rowok; float* Crow;
            if (OUTMAP) {
                int ob = r & 31, ot = r >> 5;
                rowok = (ot < Tn);
                Crow = C + (size_t)(ob * Tn + ot) * ldc;
            } else {
                rowok = (r < M);
                Crow = C + (size_t)r * ldc;
            }
            if (!rowok) continue;
#pragma unroll
            for (int nt = 0; nt < 4; nt++) {
                int n = n0 + wn * 32 + nt * 8 + (lane & 3) * 2;
                if (n + 1 < N) {
                    float v0 = acc[mt][nt][half * 2 + 0];
                    float v1 = acc[mt][nt][half * 2 + 1];
                    if (bias) { v0 += bias[n]; v1 += bias[n + 1]; }
                    *(float2*)(Crow + n) = make_float2(v0, v1);
                } else if (n < N) {
                    float v0 = acc[mt][nt][half * 2 + 0];
                    if (bias) v0 += bias[n];
                    Crow[n] = v0;
                }
            }
        }
    }
}

// ==================== hmma 128x64 (att/embW) ====================
#define ATSZ (128 * RSB)
#define BTSZ (64 * RSB)
#define STG64 (2 * ATSZ + 2 * BTSZ)    // 30720
#define HMMA64_SMEM (2 * STG64)        // 61440
#define OFF_AH 0
#define OFF_AL ATSZ
#define OFF_BH (2 * ATSZ)
#define OFF_BL (2 * ATSZ + BTSZ)

__global__ __launch_bounds__(256, 2)
void hmma_gemm64(const __nv_bfloat16* __restrict__ Ahi, const __nv_bfloat16* __restrict__ Alo,
                 const __nv_bfloat16* __restrict__ Bhi, const __nv_bfloat16* __restrict__ Blo,
                 const float* __restrict__ bias, float* __restrict__ C,
                 int M, int N, int K, int ldc)
{
    extern __shared__ char smc[];
    const uint32_t sb = smem_u32(smc);
    const int tid = threadIdx.x;
    const int lane = tid & 31, wid = tid >> 5;
    const int wm = wid & 3, wn = wid >> 2;
    const int m0 = blockIdx.y * 128, n0 = blockIdx.x * 64;

    const int ra0 = tid >> 2, ca0 = tid & 3;
    const int ra1 = (tid + 256) >> 2, ca1 = tid & 3;
    const __nv_bfloat16* aHi0 = Ahi + (size_t)(m0 + ra0) * K + ca0 * 8;
    const __nv_bfloat16* aLo0 = Alo + (size_t)(m0 + ra0) * K + ca0 * 8;
    const __nv_bfloat16* aHi1 = Ahi + (size_t)(m0 + ra1) * K + ca1 * 8;
    const __nv_bfloat16* aLo1 = Alo + (size_t)(m0 + ra1) * K + ca1 * 8;
    const uint32_t soA0 = (uint32_t)(ra0 * RSB + ca0 * 16);
    const uint32_t soA1 = (uint32_t)(ra1 * RSB + ca1 * 16);
    const int rb = tid >> 2, cb = tid & 3;
    const __nv_bfloat16* bHi = Bhi + (size_t)(n0 + rb) * K + cb * 8;
    const __nv_bfloat16* bLo = Blo + (size_t)(n0 + rb) * K + cb * 8;
    const uint32_t soB = (uint32_t)(rb * RSB + cb * 16);

    const int arow = (lane & 7) | (((lane >> 3) & 1) << 3);
    const int akh  = lane >> 4;
    const int brow = (lane & 7) + ((lane >> 4) << 3);
    const int bkh  = (lane >> 3) & 1;

    float acc[2][4][4];
#pragma unroll
    for (int i = 0; i < 2; i++)
#pragma unroll
        for (int j = 0; j < 4; j++)
#pragma unroll
            for (int e = 0; e < 4; e++) acc[i][j][e] = 0.f;

    const int nit = K / 32;

#pragma unroll
    for (int pi = 0; pi < 2; pi++) {
        uint32_t dst = sb + pi * STG64;
        int kof = pi * 32;
        CP16(dst + OFF_AH + soA0, aHi0 + kof);
        CP16(dst + OFF_AH + soA1, aHi1 + kof);
        CP16(dst + OFF_AL + soA0, aLo0 + kof);
        CP16(dst + OFF_AL + soA1, aLo1 + kof);
        CP16(dst + OFF_BH + soB,  bHi  + kof);
        CP16(dst + OFF_BL + soB,  bLo  + kof);
        CPCOMMIT();
    }

    for (int it = 0; it < nit; it++) {
        if (it + 1 < nit) { CPWAIT1(); } else { CPWAIT0(); }
        __syncthreads();

        const uint32_t stb = sb + (it & 1) * STG64;
#pragma unroll
        for (int ks = 0; ks < 2; ks++) {
            uint32_t ah[2][4], al[2][4], bh[4][2], bl[4][2];
#pragma unroll
            for (int mt = 0; mt < 2; mt++) {
                uint32_t ra = (uint32_t)((wm * 32 + mt * 16 + arow) * RSB + ks * 32 + akh * 16);
                ldmx4(ah[mt], stb + OFF_AH + ra);
                ldmx4(al[mt], stb + OFF_AL + ra);
            }
#pragma unroll
            for (int g = 0; g < 2; g++) {
                uint32_t rbr = (uint32_t)((wn * 32 + g * 16 + brow) * RSB + ks * 32 + bkh * 16);
                uint32_t t0[4], t1[4];
                ldmx4(t0, stb + OFF_BH + rbr);
                ldmx4(t1, stb + OFF_BL + rbr);
                bh[g * 2][0] = t0[0]; bh[g * 2][1] = t0[1];
                bh[g * 2 + 1][0] = t0[2]; bh[g * 2 + 1][1] = t0[3];
                bl[g * 2][0] = t1[0]; bl[g * 2][1] = t1[1];
                bl[g * 2 + 1][0] = t1[2]; bl[g * 2 + 1][1] = t1[3];
            }
#pragma unroll
            for (int mt = 0; mt < 2; mt++)
#pragma unroll
                for (int nt = 0; nt < 4; nt++) {
                    mma16816(acc[mt][nt], ah[mt], bh[nt]);
                    mma16816(acc[mt][nt], ah[mt], bl[nt]);
                    mma16816(acc[mt][nt], al[mt], bh[nt]);
                }
        }
        __syncthreads();

        if (it + 2 < nit) {
            uint32_t dst = sb + (it & 1) * STG64;
            int kof = (it + 2) * 32;
            CP16(dst + OFF_AH + soA0, aHi0 + kof);
            CP16(dst + OFF_AH + soA1, aHi1 + kof);
            CP16(dst + OFF_AL + soA0, aLo0 + kof);
            CP16(dst + OFF_AL + soA1, aLo1 + kof);
            CP16(dst + OFF_BH + soB,  bHi  + kof);
            CP16(dst + OFF_BL + soB,  bLo  + kof);
            CPCOMMIT();
        }
    }

#pragma unroll
    for (int mt = 0; mt < 2; mt++) {
#pragma unroll
        for (int half = 0; half < 2; half++) {
            int r = m0 + wm * 32 + mt * 16 + (lane >> 2) + half * 8;
            if (r >= M) continue;
            float* Crow = C + (size_t)r * ldc;
#pragma unroll
            for (int nt = 0; nt < 4; nt++) {
                int n = n0 + wn * 32 + nt * 8 + (lane & 3) * 2;
                if (n + 1 < N) {
                    float v0 = acc[mt][nt][half * 2 + 0];
                    float v1 = acc[mt][nt][half * 2 + 1];
                    if (bias) { v0 += bias[n]; v1 += bias[n + 1]; }
                    *(float2*)(Crow + n) = make_float2(v0, v1);
                } else if (n < N) {
                    float v0 = acc[mt][nt][half * 2 + 0];
                    if (bias) v0 += bias[n];
                    Crow[n] = v0;
                }
            }
        }
    }
}

// ==================== conversions ====================
__global__ void conv_split4(const float* __restrict__ src, __nv_bfloat16* __restrict__ hi,
                            __nv_bfloat16* __restrict__ lo, int total4)
{
    int idx = blockIdx.x * 256 + threadIdx.x;
    if (idx >= total4) return;
    float4 v = ((const float4*)src)[idx];
    __nv_bfloat162 h01, h23, l01, l23;
    h01.x = __float2bfloat16(v.x); h01.y = __float2bfloat16(v.y);
    h23.x = __float2bfloat16(v.z); h23.y = __float2bfloat16(v.w);
    l01.x = __float2bfloat16(v.x - __bfloat162float(h01.x));
    l01.y = __float2bfloat16(v.y - __bfloat162float(h01.y));
    l23.x = __float2bfloat16(v.z - __bfloat162float(h23.x));
    l23.y = __float2bfloat16(v.w - __bfloat162float(h23.y));
    ((uint2*)hi)[idx] = make_uint2(*(uint32_t*)&h01, *(uint32_t*)&h23);
    ((uint2*)lo)[idx] = make_uint2(*(uint32_t*)&l01, *(uint32_t*)&l23);
}

__global__ void conv_split(const float* __restrict__ src, __nv_bfloat16* __restrict__ hi,
                           __nv_bfloat16* __restrict__ lo, int M, int K, int Mpad)
{
    int idx = blockIdx.x * 256 + threadIdx.x;
    if (idx >= Mpad * K) return;
    float v;
    if (M == Mpad) {
        v = src[idx];
    } else {
        int r = idx / K;
        v = (r < M) ? src[idx] : 0.f;
    }
    __nv_bfloat16 h = __float2bfloat16(v);
    hi[idx] = h;
    lo[idx] = __float2bfloat16(v - __bfloat162float(h));
}

__global__ void conv_splitT(const float* __restrict__ src, int ldsrc,
                            __nv_bfloat16* __restrict__ hi, __nv_bfloat16* __restrict__ lo,
                            int K, int N, int Npad)
{
    __shared__ float tile[32][33];
    int n0 = blockIdx.x * 32, k0 = blockIdx.y * 32;
    int tx = threadIdx.x, ty = threadIdx.y;
#pragma unroll
    for (int i = 0; i < 32; i += 8) {
        int n = n0 + tx;
        tile[ty + i][tx] = (n < N) ? src[(size_t)(k0 + ty + i) * ldsrc + n] : 0.f;
    }
    __syncthreads();
#pragma unroll
    for (int i = 0; i < 32; i += 8) {
        int n = n0 + ty + i, k = k0 + tx;
        if (n < Npad) {
            float v = tile[tx][ty + i];
            __nv_bfloat16 h = __float2bfloat16(v);
            hi[(size_t)n * K + k] = h;
            lo[(size_t)n * K + k] = __float2bfloat16(v - __bfloat162float(h));
        }
    }
}

__global__ void pad_hall_kernel()
{
    int idx = blockIdx.x * 256 + threadIdx.x;
    if (idx >= (Mp - Mrows) * Hn) return;
    g_hallh[Mrows * Hn + idx] = __float2bfloat16(0.f);
    g_halll[Mrows * Hn + idx] = __float2bfloat16(0.f);
}

// ==================== 3-segment fast step GEMM ====================
__global__ __launch_bounds__(128)
void gemm_pass3(const float* A0, int lda0, const float* B0, int ldb0, float* P0, int N0, int K0, int ks0,
                const float* A1, int lda1, const float* B1, int ldb1, float* P1, int N1, int K1, int ks1,
                const float* A2, int lda2, const float* B2, int ldb2, float* P2, int N2, int K2, int ks2)
{
    const float *A, *B; float* P;
    int lda, ldb, N, K, ks;
    int id = blockIdx.x;
    const int b0 = (N0 / 32) * ks0, b1 = (N1 / 32) * ks1;
    if (id < b0)            { A=A0; B=B0; P=P0; lda=lda0; ldb=ldb0; N=N0; K=K0; ks=ks0; }
    else if (id < b0 + b1)  { id -= b0; A=A1; B=B1; P=P1; lda=lda1; ldb=ldb1; N=N1; K=K1; ks=ks1; }
    else                    { id -= b0 + b1; A=A2; B=B2; P=P2; lda=lda2; ldb=ldb2; N=N2; K=K2; ks=ks2; }

    const int nt = N / 32;
    const int ntile = id % nt, ksi = id / nt;
    const int kLen = K / ks;
    const int kbeg = ksi * kLen;
    const int n0 = ntile * 32;

    __shared__ __align__(16) float As[32][68];
    __shared__ __align__(16) float Bs[64][36];

    const int tid = threadIdx.x;
    const int m = (tid >> 3) * 2;
    const int nn = (tid & 7) * 4;

    float acc[2][4];
#pragma unroll
    for (int i = 0; i < 2; i++)
#pragma unroll
        for (int j = 0; j < 4; j++) acc[i][j] = 0.f;

    for (int kb = kbeg; kb < kbeg + kLen; kb += 64) {
#pragma unroll
        for (int i = 0; i < 4; i++) {
            int fi = tid + 128 * i;
            int ar = fi >> 4, ac = (fi & 15) * 4;
            *(float4*)&As[ar][ac] = *(const float4*)(A + (size_t)ar * lda + kb + ac);
            int br = fi >> 3, bc = (fi & 7) * 4;
            *(float4*)&Bs[br][bc] = *(const float4*)(B + (size_t)(kb + br) * ldb + n0 + bc);
        }
        __syncthreads();
#pragma unroll
        for (int k = 0; k < 64; k++) {
            float a0 = As[m][k], a1 = As[m + 1][k];
            float4 b4 = *(float4*)&Bs[k][nn];
            acc[0][0] = fmaf(a0, b4.x, acc[0][0]); acc[0][1] = fmaf(a0, b4.y, acc[0][1]);
            acc[0][2] = fmaf(a0, b4.z, acc[0][2]); acc[0][3] = fmaf(a0, b4.w, acc[0][3]);
            acc[1][0] = fmaf(a1, b4.x, acc[1][0]); acc[1][1] = fmaf(a1, b4.y, acc[1][1]);
            acc[1][2] = fmaf(a1, b4.z, acc[1][2]); acc[1][3] = fmaf(a1, b4.w, acc[1][3]);
        }
        __syncthreads();
    }

    float* dst = P + (size_t)ksi * 32 * N + n0;
    *(float4*)(dst + (size_t)m * N + nn)       = make_float4(acc[0][0], acc[0][1], acc[0][2], acc[0][3]);
    *(float4*)(dst + (size_t)(m + 1) * N + nn) = make_float4(acc[1][0], acc[1][1], acc[1][2], acc[1][3]);
}

// ==================== init-only small GEMM (split-K) ====================
__global__ __launch_bounds__(64)
void gemm_pass(const float* A0, int lda0, const float* B0, int ldb0, float* P0, int N0, int K0, int ks0, int nt0,
               const float* A1, int lda1, const float* B1, int ldb1, float* P1, int N1, int K1, int ks1, int nt1)
{
    const float* A; const float* B; float* P;
    int N, K, ks, nt, lda, ldb;
    int id = blockIdx.x;
    int blocks0 = nt0 * ks0;
    if (id < blocks0) { A=A0; B=B0; P=P0; N=N0; K=K0; ks=ks0; nt=nt0; lda=lda0; ldb=ldb0; }
    else { id -= blocks0; A=A1; B=B1; P=P1; N=N1; K=K1; ks=ks1; nt=nt1; lda=lda1; ldb=ldb1; }

    int ntile = id % nt;
    int ksi   = id / nt;
    int kLen  = K / ks;
    int kbeg  = ksi * kLen, kend = kbeg + kLen;
    int n0    = ntile * 32;

    __shared__ float As[32][36];
    __shared__ float Bs[32][32];
    const int tid = threadIdx.x;
    const int tx = tid & 7, ty = tid >> 3;
    const int lrow = tid >> 3, lc4 = tid & 7;

    float acc[4][4];
#pragma unroll
    for (int i = 0; i < 4; i++)
#pragma unroll
        for (int j = 0; j < 4; j++) acc[i][j] = 0.f;

    for (int k0 = kbeg; k0 < kend; k0 += 32) {
#pragma unroll
        for (int i = 0; i < 4; i++)
            *(float4*)&As[lrow + 8 * i][lc4 * 4] =
                *(const float4*)(A + (size_t)(lrow + 8 * i) * lda + k0 + lc4 * 4);
#pragma unroll
        for (int i = 0; i < 4; i++)
            *(float4*)&Bs[lrow + 8 * i][lc4 * 4] =
                *(const float4*)(B + (size_t)(k0 + lrow + 8 * i) * ldb + n0 + lc4 * 4);
        __syncthreads();
#pragma unroll
        for (int kk = 0; kk < 32; kk++) {
            float a[4];
#pragma unroll
            for (int i = 0; i < 4; i++) a[i] = As[ty * 4 + i][kk];
            float4 bv = *(float4*)&Bs[kk][tx * 4];
#pragma unroll
            for (int i = 0; i < 4; i++) {
                acc[i][0] = fmaf(a[i], bv.x, acc[i][0]);
                acc[i][1] = fmaf(a[i], bv.y, acc[i][1]);
                acc[i][2] = fmaf(a[i], bv.z, acc[i][2]);
                acc[i][3] = fmaf(a[i], bv.w, acc[i][3]);
            }
        }
        __syncthreads();
    }
    float* dst = P + (size_t)ksi * 32 * N;
#pragma unroll
    for (int i = 0; i < 4; i++) {
        int m = ty * 4 + i;
#pragma unroll
        for (int j = 0; j < 4; j++)
            dst[(size_t)m * N + n0 + tx * 4 + j] = acc[i][j];
    }
}

__global__ void reduce2_kernel(float* d0, const float* P0, int ks0, int N0, const float* b0, int act0, int cnt0,
                               float* d1, const float* P1, int ks1, int N1, const float* b1, int act1, int cnt1)
{
    int i = blockIdx.x * 256 + threadIdx.x;
    float* d; const float* P; int ks, N; const float* bi; int act; int cnt;
    if (i < cnt0) { d=d0; P=P0; ks=ks0; N=N0; bi=b0; act=act0; cnt=cnt0; }
    else { i -= cnt0; d=d1; P=P1; ks=ks1; N=N1; bi=b1; act=act1; cnt=cnt1; }
    if (i >= cnt) return;
    float v = 0.f;
    for (int s = 0; s < ks; s++) v += P[(size_t)s * cnt + i];
    if (bi) v += bi[i % N];
    if (act == 1) v = tanhf(v);
    else if (act == 2) v = sigf(v);
    d[i] = v;
}

__global__ void avg_kernel(const float* __restrict__ img)
{
    int idx = blockIdx.x * blockDim.x + threadIdx.x;
    if (idx >= Bsz * (Dn / 4)) return;
    int b = idx >> 9;
    const float4* ip = (const float4*)img + (size_t)b * Pn * (Dn / 4) + (idx & 511);
    float4 s = make_float4(0.f, 0.f, 0.f, 0.f);
    for (int p = 0; p < Pn; p++) {
        float4 x = ip[(size_t)p * (Dn / 4)];
        s.x += x.x; s.y += x.y; s.z += x.z; s.w += x.w;
    }
    const float inv = 1.f / (float)Pn;
    s.x *= inv; s.y *= inv; s.z *= inv; s.w *= inv;
    ((float4*)g_avg)[idx] = s;
}

__global__ void emb_kernel(const int* __restrict__ caps, const float* __restrict__ E)
{
    int idx = blockIdx.x * blockDim.x + threadIdx.x;
    if (idx >= Bsz * Tn * Hn) return;
    int r = idx / Hn;
    int h = idx - r * Hn;
    int b = r / Tn, t = r - b * Tn;
    g_emb[idx] = E[(size_t)caps[b * 20 + t] * Hn + h];
}

// ==================== attctx v3: 2 blocks per b (D split), scores duplicated ====
__global__ __launch_bounds__(1024)
void attctx_kernel(const float* __restrict__ img,
                   const float* __restrict__ v_att, const float* __restrict__ b_v_att,
                   const float* __restrict__ b_att_h, const float* __restrict__ b_fbeta,
                   float* __restrict__ out_alphas, int t)
{
    const int blk = blockIdx.x;
    const int b = blk >> 1, sl = blk & 1;
    const int tid = threadIdx.x;
    const int w = tid >> 5, lane = tid & 31;
    __shared__ float hp[Hn];
    __shared__ float va[Hn];
    __shared__ float ee[Pn];
    __shared__ float sred[8];
    __shared__ __align__(16) float4 redD[4 * 256];   // 16KB

    if (tid < Hn) {
        float v = b_att_h[tid];
#pragma unroll
        for (int s = 0; s < 8; s++) v += g_pp_h[s * Bsz * Hn + b * Hn + tid];
        hp[tid] = v;
        va[tid] = v_att[tid];
    }
    __syncthreads();

    const float* ai = g_att_img + (size_t)b * Pn * Hn;
    const float bv0 = b_v_att[0];
    for (int p = w; p < Pn; p += 32) {
        const float* aip = ai + (size_t)p * Hn;
        float s = 0.f;
#pragma unroll
        for (int ii = 0; ii < Hn / 32; ii++) {
            int hx = lane + 32 * ii;
            float x = aip[hx] + hp[hx];
            float th;
            asm("tanh.approx.f32 %0, %1;" : "=f"(th) : "f"(x));
            s = fmaf(th, va[hx], s);
        }
#pragma unroll
        for (int o = 16; o; o >>= 1) s += __shfl_down_sync(0xffffffffu, s, o);
        if (lane == 0) ee[p] = s + bv0;
    }
    __syncthreads();

    float v = (tid < Pn) ? ee[tid] : -1e30f;
    if (tid < 256) {
        float m = v;
#pragma unroll
        for (int o = 16; o; o >>= 1) m = fmaxf(m, __shfl_xor_sync(0xffffffffu, m, o));
        if (lane == 0) sred[w] = m;
    }
    __syncthreads();
    if (tid < 32) {
        float mm = (tid < 8) ? sred[tid] : -1e30f;
#pragma unroll
        for (int o = 4; o; o >>= 1) mm = fmaxf(mm, __shfl_xor_sync(0xffffffffu, mm, o));
        if (tid == 0) sred[0] = mm;
    }
    __syncthreads();
    float exv = (tid < Pn) ? expf(v - sred[0]) : 0.f;
    __syncthreads();
    if (tid < 256) {
        float s = exv;
#pragma unroll
        for (int o = 16; o; o >>= 1) s += __shfl_xor_sync(0xffffffffu, s, o);
        if (lane == 0) sred[w] = s;
    }
    __syncthreads();
    if (tid < 32) {
        float ss = (tid < 8) ? sred[tid] : 0.f;
#pragma unroll
        for (int o = 4; o; o >>= 1) ss += __shfl_xor_sync(0xffffffffu, ss, o);
        if (tid == 0) sred[0] = ss;
    }
    __syncthreads();
    if (tid < Pn) {
        float a = exv / sred[0];
        ee[tid] = a;
        if (sl == 0) out_alphas[((size_t)b * Tn + t) * Pn + tid] = a;
    }
    __syncthreads();

    // context: this block handles D-columns [sl*1024, sl*1024+1024) = 256 float4s
    const int dl = tid & 255;          // 256 d4 columns
    const int ps = tid >> 8;           // 4-way p split
    const int d4 = sl * 256 + dl;
    const float4* ip = (const float4*)img + (size_t)b * Pn * (Dn / 4) + d4;
    float4 cx = make_float4(0.f, 0.f, 0.f, 0.f);
#pragma unroll 8
    for (int p = ps; p < Pn; p += 4) {
        float a = ee[p];
        float4 x = ip[(size_t)p * (Dn / 4)];
        cx.x = fmaf(a, x.x, cx.x); cx.y = fmaf(a, x.y, cx.y);
        cx.z = fmaf(a, x.z, cx.z); cx.w = fmaf(a, x.w, cx.w);
    }
    redD[ps * 256 + dl] = cx;
    __syncthreads();
    if (tid < 256) {
        float4 r0 = redD[tid], r1 = redD[256 + tid], r2 = redD[512 + tid], r3 = redD[768 + tid];
        float4 sum = make_float4(r0.x + r1.x + r2.x + r3.x, r0.y + r1.y + r2.y + r3.y,
                                 r0.z + r1.z + r2.z + r3.z, r0.w + r1.w + r2.w + r3.w);
        int dd = sl * 256 + tid;
        float4 gb = ((const float4*)b_fbeta)[dd];
#pragma unroll
        for (int sp = 0; sp < 8; sp++) {
            float4 pv = ((const float4*)g_pp_g)[sp * (Bsz * Dn / 4) + b * (Dn / 4) + dd];
            gb.x += pv.x; gb.y += pv.y; gb.z += pv.z; gb.w += pv.w;
        }
        sum.x *= sigf(gb.x); sum.y *= sigf(gb.y);
        sum.z *= sigf(gb.z); sum.w *= sigf(gb.w);
        ((float4*)g_xc)[b * (Dn / 4) + dd] = sum;
    }
}

// LSTM pointwise
__global__ void lstm_kernel(const float* __restrict__ bih, const float* __restrict__ bhh, int t)
{
    int idx = blockIdx.x * blockDim.x + threadIdx.x;
    if (idx >= Bsz * Hn) return;
    int b = idx >> 9;
    int j = idx & 511;
    int rowE = (b * Tn + t) * 4 * Hn;
    int rowP = b * 4 * Hn;

    float gv[4];
#pragma unroll
    for (int g = 0; g < 4; g++) {
        int n = g * Hn + j;
        float v = g_embW[rowE + n] + bih[n] + bhh[n];
#pragma unroll
        for (int s = 0; s < 8; s++) v += g_pa[s * Bsz * 4 * Hn + rowP + n];
#pragma unroll
        for (int s = 0; s < 4; s++) v += g_pb[s * Bsz * 4 * Hn + rowP + n];
        gv[g] = v;
    }
    float c = sigf(gv[1]) * g_c[idx] + sigf(gv[0]) * tanhf(gv[2]);
    g_c[idx] = c;
    float h = sigf(gv[3]) * tanhf(c);
    g_h[idx] = h;
    size_t ro = (size_t)(t * Bsz + b) * Hn + j;
    __nv_bfloat16 hh = __float2bfloat16(h);
    g_hallh[ro] = hh;
    g_halll[ro] = __float2bfloat16(h - __bfloat162float(hh));
}

// ================================================================================
extern "C" void kernel_launch(void* const* d_in, const int* in_sizes, int n_in,
                              void* d_out, int out_size)
{
    const float* img      = (const float*)d_in[0];
    const int*   caps     = (const int*)d_in[1];
    const float* Wih      = (const float*)d_in[2];
    const float* Whh      = (const float*)d_in[3];
    const float* bih      = (const float*)d_in[4];
    const float* bhh      = (const float*)d_in[5];
    const float* W_init_h = (const float*)d_in[6];
    const float* b_init_h = (const float*)d_in[7];
    const float* W_init_c = (const float*)d_in[8];
    const float* b_init_c = (const float*)d_in[9];
    const float* W_fbeta  = (const float*)d_in[10];
    const float* b_fbeta  = (const float*)d_in[11];
    const float* W_out    = (const float*)d_in[12];
    const float* b_out    = (const float*)d_in[13];
    const float* W_att_im = (const float*)d_in[14];
    const float* b_att_im = (const float*)d_in[15];
    const float* W_att_h  = (const float*)d_in[16];
    const float* b_att_h  = (const float*)d_in[17];
    const float* v_att    = (const float*)d_in[18];
    const float* b_v_att  = (const float*)d_in[19];
    const float* E        = (const float*)d_in[20];

    float* preds  = (float*)d_out;
    float* alphas = (float*)d_out + (size_t)Bsz * Tn * Vn;

    float *p_avg, *p_h, *p_c, *p_att, *p_emb, *p_embW, *p_xc, *p_pph, *p_ppg;
    float *p_pa, *p_pb, *p_pih, *p_pic;
    __nv_bfloat16 *p_imgh, *p_imgl, *p_watth, *p_wattl, *p_wouth, *p_woutl;
    __nv_bfloat16 *p_wihh, *p_wihl, *p_embh, *p_embl, *p_hallh, *p_halll;
    cudaGetSymbolAddress((void**)&p_avg,   g_avg);
    cudaGetSymbolAddress((void**)&p_h,     g_h);
    cudaGetSymbolAddress((void**)&p_c,     g_c);
    cudaGetSymbolAddress((void**)&p_att,   g_att_img);
    cudaGetSymbolAddress((void**)&p_emb,   g_emb);
    cudaGetSymbolAddress((void**)&p_embW,  g_embW);
    cudaGetSymbolAddress((void**)&p_xc,    g_xc);
    cudaGetSymbolAddress((void**)&p_pph,   g_pp_h);
    cudaGetSymbolAddress((void**)&p_ppg,   g_pp_g);
    cudaGetSymbolAddress((void**)&p_pa,    g_pa);
    cudaGetSymbolAddress((void**)&p_pb,    g_pb);
    cudaGetSymbolAddress((void**)&p_pih,   g_pi_h);
    cudaGetSymbolAddress((void**)&p_pic,   g_pi_c);
    cudaGetSymbolAddress((void**)&p_imgh,  g_img_hi);
    cudaGetSymbolAddress((void**)&p_imgl,  g_img_lo);
    cudaGetSymbolAddress((void**)&p_watth, g_watt_hi);
    cudaGetSymbolAddress((void**)&p_wattl, g_watt_lo);
    cudaGetSymbolAddress((void**)&p_wouth, g_wout_hi);
    cudaGetSymbolAddress((void**)&p_woutl, g_wout_lo);
    cudaGetSymbolAddress((void**)&p_wihh,  g_wih_hi);
    cudaGetSymbolAddress((void**)&p_wihl,  g_wih_lo);
    cudaGetSymbolAddress((void**)&p_embh,  g_embh);
    cudaGetSymbolAddress((void**)&p_embl,  g_embl);
    cudaGetSymbolAddress((void**)&p_hallh, g_hallh);
    cudaGetSymbolAddress((void**)&p_halll, g_halll);

    cudaFuncSetAttribute(hmma_gemm<0>, cudaFuncAttributeMaxDynamicSharedMemorySize, HMMA_SMEM);
    cudaFuncSetAttribute(hmma_gemm<1>, cudaFuncAttributeMaxDynamicSharedMemorySize, HMMA_SMEM);
    cudaFuncSetAttribute(hmma_gemm64,  cudaFuncAttributeMaxDynamicSharedMemorySize, HMMA64_SMEM);

    // ---- setup; launch index 3 = attctx PROBE (outputs overwritten by real t=0) ----
    conv_split4<<<(Bsz * Pn * Dn / 4 + 255) / 256, 256>>>(img, p_imgh, p_imgl, Bsz * Pn * Dn / 4);    // 0
    conv_splitT<<<dim3(Hn / 32, Dn / 32), dim3(32, 8)>>>(W_att_im, Hn, p_watth, p_wattl, Dn, Hn, Hn); // 1
    avg_kernel<<<64, 256>>>(img);                                                                     // 2
    attctx_kernel<<<2 * Bsz, 1024>>>(img, v_att, b_v_att, b_att_h, b_fbeta, alphas, 0);               // 3 <- ncu
    hmma_gemm64<<<dim3(Hn / 64, (Bsz * Pn) / 128), 256, HMMA64_SMEM>>>(                               // 4
        p_imgh, p_imgl, p_watth, p_wattl, b_att_im, p_att, Bsz * Pn, Hn, Dn, Hn);
    conv_splitT<<<dim3(Vp / 32, Hn / 32), dim3(32, 8)>>>(W_out, Vn, p_wouth, p_woutl, Hn, Vn, Vp);
    conv_splitT<<<dim3(4 * Hn / 32, Hn / 32), dim3(32, 8)>>>(Wih, 4 * Hn, p_wihh, p_wihl, Hn, 4 * Hn, 4 * Hn);
    gemm_pass<<<256, 64>>>(p_avg, Dn, W_init_h, Hn, p_pih, Hn, Dn, 8, 16,
                           p_avg, Dn, W_init_c, Hn, p_pic, Hn, Dn, 8, 16);
    reduce2_kernel<<<128, 256>>>(p_h, p_pih, 8, Hn, b_init_h, 1, Bsz * Hn,
                                 p_c, p_pic, 8, Hn, b_init_c, 1, Bsz * Hn);
    emb_kernel<<<(Bsz * Tn * Hn) / 256, 256>>>(caps, E);
    conv_split<<<(Mp * Hn) / 256, 256>>>(p_emb, p_embh, p_embl, Mrows, Hn, Mp);
    hmma_gemm64<<<dim3(4 * Hn / 64, Mp / 128), 256, HMMA64_SMEM>>>(
        p_embh, p_embl, p_wihh, p_wihl, nullptr, p_embW, Mrows, 4 * Hn, Hn, 4 * Hn);
    pad_hall_kernel<<<((Mp - Mrows) * Hn + 255) / 256, 256>>>();

    const float* WihBot = Wih + (size_t)Hn * 4 * Hn;

    // ---- recurrent steps: R7 structure, attctx v3 (64 blocks) ----
    for (int t = 0; t < Tn; t++) {
        gemm_pass3<<<128 + 512 + 256, 128>>>(
            p_h, Hn, W_att_h, Hn,     p_pph, Hn,     Hn, 8,
            p_h, Hn, W_fbeta, Dn,     p_ppg, Dn,     Hn, 8,
            p_h, Hn, Whh,     4 * Hn, p_pb,  4 * Hn, Hn, 4);
        attctx_kernel<<<2 * Bsz, 1024>>>(img, v_att, b_v_att, b_att_h, b_fbeta, alphas, t);
        gemm_pass3<<<512, 128>>>(
            p_xc, Dn, WihBot, 4 * Hn, p_pa, 4 * Hn, Dn, 8,
            p_xc, Dn, WihBot, 4 * Hn, p_pa, 0,      Dn, 8,
            p_xc, Dn, WihBot, 4 * Hn, p_pa, 0,      Dn, 8);
        lstm_kernel<<<(Bsz * Hn) / 256, 256>>>(bih, bhh, t);
    }

    // ---- final: preds = h_all @ W_out + b_out ----
    hmma_gemm<1><<<dim3(Vp / 128, Mp / 128), 256, HMMA_SMEM>>>(
        p_hallh, p_halll, p_wouth, p_woutl, b_out, preds, Mrows, Vn, Hn, Vn);
}

// round 17
// speedup vs baseline: 1.3319x; 1.0051x over previous
#include <cuda_runtime.h>
#include <cuda_bf16.h>
#include <math.h>
#include <stdint.h>

#define Bsz 32
#define Pn  196
#define Dn  2048
#define Hn  512
#define Vn  30000
#define Tn  19
#define Vp  30080
#define Mrows 608
#define Mp  640

// ---------------- fp32 scratch ----------------
__device__ float g_avg[Bsz * Dn];
__device__ float g_h[Bsz * Hn];
__device__ float g_c[Bsz * Hn];
__device__ float g_att_img[Bsz * Pn * Hn];
__device__ float g_emb[Bsz * Tn * Hn];
__device__ float g_embW[Bsz * Tn * 4 * Hn];
__device__ float g_xc[Bsz * Dn];
__device__ float g_pp_h[8 * Bsz * Hn];           // hproj (ks=8)
__device__ float g_pp_g[8 * Bsz * Dn];           // fbeta (ks=8)
__device__ float g_pa[8 * Bsz * 4 * Hn];         // xc@Wih_bot (ks=8)
__device__ float g_pb[4 * Bsz * 4 * Hn];         // h@Whh (ks=4)
__device__ float g_pi_h[8 * Bsz * Hn];
__device__ float g_pi_c[8 * Bsz * Hn];

// ---------------- bf16 split scratch ----------------
__device__ __nv_bfloat16 g_img_hi[Bsz * Pn * Dn];
__device__ __nv_bfloat16 g_img_lo[Bsz * Pn * Dn];
__device__ __nv_bfloat16 g_watt_hi[Hn * Dn];
__device__ __nv_bfloat16 g_watt_lo[Hn * Dn];
__device__ __nv_bfloat16 g_wout_hi[Vp * Hn];
__device__ __nv_bfloat16 g_wout_lo[Vp * Hn];
__device__ __nv_bfloat16 g_wih_hi[4 * Hn * Hn];
__device__ __nv_bfloat16 g_wih_lo[4 * Hn * Hn];
__device__ __nv_bfloat16 g_embh[Mp * Hn];
__device__ __nv_bfloat16 g_embl[Mp * Hn];
__device__ __nv_bfloat16 g_hallh[Mp * Hn];
__device__ __nv_bfloat16 g_halll[Mp * Hn];

__device__ __forceinline__ float sigf(float x) { return 1.f / (1.f + expf(-x)); }

__device__ __forceinline__ uint32_t smem_u32(const void* p) {
    uint32_t a;
    asm("{ .reg .u64 t; cvta.to.shared.u64 t, %1; cvt.u32.u64 %0, t; }" : "=r"(a) : "l"(p));
    return a;
}
__device__ __forceinline__ void ldmx4(uint32_t* r, uint32_t addr) {
    asm volatile("ldmatrix.sync.aligned.m8n8.x4.shared.b16 {%0,%1,%2,%3}, [%4];"
                 : "=r"(r[0]), "=r"(r[1]), "=r"(r[2]), "=r"(r[3]) : "r"(addr));
}
__device__ __forceinline__ void mma16816(float* d, const uint32_t* a, const uint32_t* b) {
    asm volatile(
        "mma.sync.aligned.m16n8k16.row.col.f32.bf16.bf16.f32 "
        "{%0,%1,%2,%3}, {%4,%5,%6,%7}, {%8,%9}, {%0,%1,%2,%3};"
        : "+f"(d[0]), "+f"(d[1]), "+f"(d[2]), "+f"(d[3])
        : "r"(a[0]), "r"(a[1]), "r"(a[2]), "r"(a[3]), "r"(b[0]), "r"(b[1]));
}
#define CP16(s, g)  asm volatile("cp.async.cg.shared.global [%0], [%1], 16;" :: "r"(s), "l"(g))
#define CPCOMMIT()  asm volatile("cp.async.commit_group;" ::: "memory")
#define CPWAIT1()   asm volatile("cp.async.wait_group 1;" ::: "memory")
#define CPWAIT0()   asm volatile("cp.async.wait_group 0;" ::: "memory")

#define RSB 80

// ==================== hmma 128x64 (all HMMA GEMMs) ====================
#define ATSZ (128 * RSB)
#define BTSZ (64 * RSB)
#define STG64 (2 * ATSZ + 2 * BTSZ)    // 30720
#define HMMA64_SMEM (2 * STG64)        // 61440
#define OFF_AH 0
#define OFF_AL ATSZ
#define OFF_BH (2 * ATSZ)
#define OFF_BL (2 * ATSZ + BTSZ)

template <int OUTMAP>
__global__ __launch_bounds__(256, 2)
void hmma_gemm64(const __nv_bfloat16* __restrict__ Ahi, const __nv_bfloat16* __restrict__ Alo,
                 const __nv_bfloat16* __restrict__ Bhi, const __nv_bfloat16* __restrict__ Blo,
                 const float* __restrict__ bias, float* __restrict__ C,
                 int M, int N, int K, int ldc)
{
    extern __shared__ char smc[];
    const uint32_t sb = smem_u32(smc);
    const int tid = threadIdx.x;
    const int lane = tid & 31, wid = tid >> 5;
    const int wm = wid & 3, wn = wid >> 2;
    const int m0 = blockIdx.y * 128, n0 = blockIdx.x * 64;

    const int ra0 = tid >> 2, ca0 = tid & 3;
    const int ra1 = (tid + 256) >> 2, ca1 = tid & 3;
    const __nv_bfloat16* aHi0 = Ahi + (size_t)(m0 + ra0) * K + ca0 * 8;
    const __nv_bfloat16* aLo0 = Alo + (size_t)(m0 + ra0) * K + ca0 * 8;
    const __nv_bfloat16* aHi1 = Ahi + (size_t)(m0 + ra1) * K + ca1 * 8;
    const __nv_bfloat16* aLo1 = Alo + (size_t)(m0 + ra1) * K + ca1 * 8;
    const uint32_t soA0 = (uint32_t)(ra0 * RSB + ca0 * 16);
    const uint32_t soA1 = (uint32_t)(ra1 * RSB + ca1 * 16);
    const int rb = tid >> 2, cb = tid & 3;
    const __nv_bfloat16* bHi = Bhi + (size_t)(n0 + rb) * K + cb * 8;
    const __nv_bfloat16* bLo = Blo + (size_t)(n0 + rb) * K + cb * 8;
    const uint32_t soB = (uint32_t)(rb * RSB + cb * 16);

    const int arow = (lane & 7) | (((lane >> 3) & 1) << 3);
    const int akh  = lane >> 4;
    const int brow = (lane & 7) + ((lane >> 4) << 3);
    const int bkh  = (lane >> 3) & 1;

    float acc[2][4][4];
#pragma unroll
    for (int i = 0; i < 2; i++)
#pragma unroll
        for (int j = 0; j < 4; j++)
#pragma unroll
            for (int e = 0; e < 4; e++) acc[i][j][e] = 0.f;

    const int nit = K / 32;

#pragma unroll
    for (int pi = 0; pi < 2; pi++) {
        uint32_t dst = sb + pi * STG64;
        int kof = pi * 32;
        CP16(dst + OFF_AH + soA0, aHi0 + kof);
        CP16(dst + OFF_AH + soA1, aHi1 + kof);
        CP16(dst + OFF_AL + soA0, aLo0 + kof);
        CP16(dst + OFF_AL + soA1, aLo1 + kof);
        CP16(dst + OFF_BH + soB,  bHi  + kof);
        CP16(dst + OFF_BL + soB,  bLo  + kof);
        CPCOMMIT();
    }

    for (int it = 0; it < nit; it++) {
        if (it + 1 < nit) { CPWAIT1(); } else { CPWAIT0(); }
        __syncthreads();

        const uint32_t stb = sb + (it & 1) * STG64;
#pragma unroll
        for (int ks = 0; ks < 2; ks++) {
            uint32_t ah[2][4], al[2][4], bh[4][2], bl[4][2];
#pragma unroll
            for (int mt = 0; mt < 2; mt++) {
                uint32_t ra = (uint32_t)((wm * 32 + mt * 16 + arow) * RSB + ks * 32 + akh * 16);
                ldmx4(ah[mt], stb + OFF_AH + ra);
                ldmx4(al[mt], stb + OFF_AL + ra);
            }
#pragma unroll
            for (int g = 0; g < 2; g++) {
                uint32_t rbr = (uint32_t)((wn * 32 + g * 16 + brow) * RSB + ks * 32 + bkh * 16);
                uint32_t t0[4], t1[4];
                ldmx4(t0, stb + OFF_BH + rbr);
                ldmx4(t1, stb + OFF_BL + rbr);
                bh[g * 2][0] = t0[0]; bh[g * 2][1] = t0[1];
                bh[g * 2 + 1][0] = t0[2]; bh[g * 2 + 1][1] = t0[3];
                bl[g * 2][0] = t1[0]; bl[g * 2][1] = t1[1];
                bl[g * 2 + 1][0] = t1[2]; bl[g * 2 + 1][1] = t1[3];
            }
#pragma unroll
            for (int mt = 0; mt < 2; mt++)
#pragma unroll
                for (int nt = 0; nt < 4; nt++) {
                    mma16816(acc[mt][nt], ah[mt], bh[nt]);
                    mma16816(acc[mt][nt], ah[mt], bl[nt]);
                    mma16816(acc[mt][nt], al[mt], bh[nt]);
                }
        }
        __syncthreads();

        if (it + 2 < nit) {
            uint32_t dst = sb + (it & 1) * STG64;
            int kof = (it + 2) * 32;
            CP16(dst + OFF_AH + soA0, aHi0 + kof);
            CP16(dst + OFF_AH + soA1, aHi1 + kof);
            CP16(dst + OFF_AL + soA0, aLo0 + kof);
            CP16(dst + OFF_AL + soA1, aLo1 + kof);
            CP16(dst + OFF_BH + soB,  bHi  + kof);
            CP16(dst + OFF_BL + soB,  bLo  + kof);
            CPCOMMIT();
        }
    }

#pragma unroll
    for (int mt = 0; mt < 2; mt++) {
#pragma unroll
        for (int half = 0; half < 2; half++) {
            int r = m0 + wm * 32 + mt * 16 + (lane >> 2) + half * 8;
            bool rowok; float* Crow;
            if (OUTMAP) {
                int ob = r & 31, ot = r >> 5;
                rowok = (ot < Tn);
                Crow = C + (size_t)(ob * Tn + ot) * ldc;
            } else {
                rowok = (r < M);
                Crow = C + (size_t)r * ldc;
            }
            if (!rowok) continue;
#pragma unroll
            for (int nt = 0; nt < 4; nt++) {
                int n = n0 + wn * 32 + nt * 8 + (lane & 3) * 2;
                if (n + 1 < N) {
                    float v0 = acc[mt][nt][half * 2 + 0];
                    float v1 = acc[mt][nt][half * 2 + 1];
                    if (bias) { v0 += bias[n]; v1 += bias[n + 1]; }
                    *(float2*)(Crow + n) = make_float2(v0, v1);
                } else if (n < N) {
                    float v0 = acc[mt][nt][half * 2 + 0];
                    if (bias) v0 += bias[n];
                    Crow[n] = v0;
                }
            }
        }
    }
}

// ==================== conversions ====================
__global__ void conv_split4(const float* __restrict__ src, __nv_bfloat16* __restrict__ hi,
                            __nv_bfloat16* __restrict__ lo, int total4)
{
    int idx = blockIdx.x * 256 + threadIdx.x;
    if (idx >= total4) return;
    float4 v = ((const float4*)src)[idx];
    __nv_bfloat162 h01, h23, l01, l23;
    h01.x = __float2bfloat16(v.x); h01.y = __float2bfloat16(v.y);
    h23.x = __float2bfloat16(v.z); h23.y = __float2bfloat16(v.w);
    l01.x = __float2bfloat16(v.x - __bfloat162float(h01.x));
    l01.y = __float2bfloat16(v.y - __bfloat162float(h01.y));
    l23.x = __float2bfloat16(v.z - __bfloat162float(h23.x));
    l23.y = __float2bfloat16(v.w - __bfloat162float(h23.y));
    ((uint2*)hi)[idx] = make_uint2(*(uint32_t*)&h01, *(uint32_t*)&h23);
    ((uint2*)lo)[idx] = make_uint2(*(uint32_t*)&l01, *(uint32_t*)&l23);
}

__global__ void conv_split(const float* __restrict__ src, __nv_bfloat16* __restrict__ hi,
                           __nv_bfloat16* __restrict__ lo, int M, int K, int Mpad)
{
    int idx = blockIdx.x * 256 + threadIdx.x;
    if (idx >= Mpad * K) return;
    float v;
    if (M == Mpad) {
        v = src[idx];
    } else {
        int r = idx / K;
        v = (r < M) ? src[idx] : 0.f;
    }
    __nv_bfloat16 h = __float2bfloat16(v);
    hi[idx] = h;
    lo[idx] = __float2bfloat16(v - __bfloat162float(h));
}

__global__ void conv_splitT(const float* __restrict__ src, int ldsrc,
                            __nv_bfloat16* __restrict__ hi, __nv_bfloat16* __restrict__ lo,
                            int K, int N, int Npad)
{
    __shared__ float tile[32][33];
    int n0 = blockIdx.x * 32, k0 = blockIdx.y * 32;
    int tx = threadIdx.x, ty = threadIdx.y;
#pragma unroll
    for (int i = 0; i < 32; i += 8) {
        int n = n0 + tx;
        tile[ty + i][tx] = (n < N) ? src[(size_t)(k0 + ty + i) * ldsrc + n] : 0.f;
    }
    __syncthreads();
#pragma unroll
    for (int i = 0; i < 32; i += 8) {
        int n = n0 + ty + i, k = k0 + tx;
        if (n < Npad) {
            float v = tile[tx][ty + i];
            __nv_bfloat16 h = __float2bfloat16(v);
            hi[(size_t)n * K + k] = h;
            lo[(size_t)n * K + k] = __float2bfloat16(v - __bfloat162float(h));
        }
    }
}

__global__ void pad_hall_kernel()
{
    int idx = blockIdx.x * 256 + threadIdx.x;
    if (idx >= (Mp - Mrows) * Hn) return;
    g_hallh[Mrows * Hn + idx] = __float2bfloat16(0.f);
    g_halll[Mrows * Hn + idx] = __float2bfloat16(0.f);
}

// ==================== 3-segment fast step GEMM ====================
__global__ __launch_bounds__(128)
void gemm_pass3(const float* A0, int lda0, const float* B0, int ldb0, float* P0, int N0, int K0, int ks0,
                const float* A1, int lda1, const float* B1, int ldb1, float* P1, int N1, int K1, int ks1,
                const float* A2, int lda2, const float* B2, int ldb2, float* P2, int N2, int K2, int ks2)
{
    const float *A, *B; float* P;
    int lda, ldb, N, K, ks;
    int id = blockIdx.x;
    const int b0 = (N0 / 32) * ks0, b1 = (N1 / 32) * ks1;
    if (id < b0)            { A=A0; B=B0; P=P0; lda=lda0; ldb=ldb0; N=N0; K=K0; ks=ks0; }
    else if (id < b0 + b1)  { id -= b0; A=A1; B=B1; P=P1; lda=lda1; ldb=ldb1; N=N1; K=K1; ks=ks1; }
    else                    { id -= b0 + b1; A=A2; B=B2; P=P2; lda=lda2; ldb=ldb2; N=N2; K=K2; ks=ks2; }

    const int nt = N / 32;
    const int ntile = id % nt, ksi = id / nt;
    const int kLen = K / ks;
    const int kbeg = ksi * kLen;
    const int n0 = ntile * 32;

    __shared__ __align__(16) float As[32][68];
    __shared__ __align__(16) float Bs[64][36];

    const int tid = threadIdx.x;
    const int m = (tid >> 3) * 2;
    const int nn = (tid & 7) * 4;

    float acc[2][4];
#pragma unroll
    for (int i = 0; i < 2; i++)
#pragma unroll
        for (int j = 0; j < 4; j++) acc[i][j] = 0.f;

    for (int kb = kbeg; kb < kbeg + kLen; kb += 64) {
#pragma unroll
        for (int i = 0; i < 4; i++) {
            int fi = tid + 128 * i;
            int ar = fi >> 4, ac = (fi & 15) * 4;
            *(float4*)&As[ar][ac] = *(const float4*)(A + (size_t)ar * lda + kb + ac);
            int br = fi >> 3, bc = (fi & 7) * 4;
            *(float4*)&Bs[br][bc] = *(const float4*)(B + (size_t)(kb + br) * ldb + n0 + bc);
        }
        __syncthreads();
#pragma unroll
        for (int k = 0; k < 64; k++) {
            float a0 = As[m][k], a1 = As[m + 1][k];
            float4 b4 = *(float4*)&Bs[k][nn];
            acc[0][0] = fmaf(a0, b4.x, acc[0][0]); acc[0][1] = fmaf(a0, b4.y, acc[0][1]);
            acc[0][2] = fmaf(a0, b4.z, acc[0][2]); acc[0][3] = fmaf(a0, b4.w, acc[0][3]);
            acc[1][0] = fmaf(a1, b4.x, acc[1][0]); acc[1][1] = fmaf(a1, b4.y, acc[1][1]);
            acc[1][2] = fmaf(a1, b4.z, acc[1][2]); acc[1][3] = fmaf(a1, b4.w, acc[1][3]);
        }
        __syncthreads();
    }

    float* dst = P + (size_t)ksi * 32 * N + n0;
    *(float4*)(dst + (size_t)m * N + nn)       = make_float4(acc[0][0], acc[0][1], acc[0][2], acc[0][3]);
    *(float4*)(dst + (size_t)(m + 1) * N + nn) = make_float4(acc[1][0], acc[1][1], acc[1][2], acc[1][3]);
}

// ==================== init-only small GEMM (split-K) ====================
__global__ __launch_bounds__(64)
void gemm_pass(const float* A0, int lda0, const float* B0, int ldb0, float* P0, int N0, int K0, int ks0, int nt0,
               const float* A1, int lda1, const float* B1, int ldb1, float* P1, int N1, int K1, int ks1, int nt1)
{
    const float* A; const float* B; float* P;
    int N, K, ks, nt, lda, ldb;
    int id = blockIdx.x;
    int blocks0 = nt0 * ks0;
    if (id < blocks0) { A=A0; B=B0; P=P0; N=N0; K=K0; ks=ks0; nt=nt0; lda=lda0; ldb=ldb0; }
    else { id -= blocks0; A=A1; B=B1; P=P1; N=N1; K=K1; ks=ks1; nt=nt1; lda=lda1; ldb=ldb1; }

    int ntile = id % nt;
    int ksi   = id / nt;
    int kLen  = K / ks;
    int kbeg  = ksi * kLen, kend = kbeg + kLen;
    int n0    = ntile * 32;

    __shared__ float As[32][36];
    __shared__ float Bs[32][32];
    const int tid = threadIdx.x;
    const int tx = tid & 7, ty = tid >> 3;
    const int lrow = tid >> 3, lc4 = tid & 7;

    float acc[4][4];
#pragma unroll
    for (int i = 0; i < 4; i++)
#pragma unroll
        for (int j = 0; j < 4; j++) acc[i][j] = 0.f;

    for (int k0 = kbeg; k0 < kend; k0 += 32) {
#pragma unroll
        for (int i = 0; i < 4; i++)
            *(float4*)&As[lrow + 8 * i][lc4 * 4] =
                *(const float4*)(A + (size_t)(lrow + 8 * i) * lda + k0 + lc4 * 4);
#pragma unroll
        for (int i = 0; i < 4; i++)
            *(float4*)&Bs[lrow + 8 * i][lc4 * 4] =
                *(const float4*)(B + (size_t)(k0 + lrow + 8 * i) * ldb + n0 + lc4 * 4);
        __syncthreads();
#pragma unroll
        for (int kk = 0; kk < 32; kk++) {
            float a[4];
#pragma unroll
            for (int i = 0; i < 4; i++) a[i] = As[ty * 4 + i][kk];
            float4 bv = *(float4*)&Bs[kk][tx * 4];
#pragma unroll
            for (int i = 0; i < 4; i++) {
                acc[i][0] = fmaf(a[i], bv.x, acc[i][0]);
                acc[i][1] = fmaf(a[i], bv.y, acc[i][1]);
                acc[i][2] = fmaf(a[i], bv.z, acc[i][2]);
                acc[i][3] = fmaf(a[i], bv.w, acc[i][3]);
            }
        }
        __syncthreads();
    }
    float* dst = P + (size_t)ksi * 32 * N;
#pragma unroll
    for (int i = 0; i < 4; i++) {
        int m = ty * 4 + i;
#pragma unroll
        for (int j = 0; j < 4; j++)
            dst[(size_t)m * N + n0 + tx * 4 + j] = acc[i][j];
    }
}

__global__ void reduce2_kernel(float* d0, const float* P0, int ks0, int N0, const float* b0, int act0, int cnt0,
                               float* d1, const float* P1, int ks1, int N1, const float* b1, int act1, int cnt1)
{
    int i = blockIdx.x * 256 + threadIdx.x;
    float* d; const float* P; int ks, N; const float* bi; int act; int cnt;
    if (i < cnt0) { d=d0; P=P0; ks=ks0; N=N0; bi=b0; act=act0; cnt=cnt0; }
    else { i -= cnt0; d=d1; P=P1; ks=ks1; N=N1; bi=b1; act=act1; cnt=cnt1; }
    if (i >= cnt) return;
    float v = 0.f;
    for (int s = 0; s < ks; s++) v += P[(size_t)s * cnt + i];
    if (bi) v += bi[i % N];
    if (act == 1) v = tanhf(v);
    else if (act == 2) v = sigf(v);
    d[i] = v;
}

__global__ void avg_kernel(const float* __restrict__ img)
{
    int idx = blockIdx.x * blockDim.x + threadIdx.x;
    if (idx >= Bsz * (Dn / 4)) return;
    int b = idx >> 9;
    const float4* ip = (const float4*)img + (size_t)b * Pn * (Dn / 4) + (idx & 511);
    float4 s = make_float4(0.f, 0.f, 0.f, 0.f);
    for (int p = 0; p < Pn; p++) {
        float4 x = ip[(size_t)p * (Dn / 4)];
        s.x += x.x; s.y += x.y; s.z += x.z; s.w += x.w;
    }
    const float inv = 1.f / (float)Pn;
    s.x *= inv; s.y *= inv; s.z *= inv; s.w *= inv;
    ((float4*)g_avg)[idx] = s;
}

__global__ void emb_kernel(const int* __restrict__ caps, const float* __restrict__ E)
{
    int idx = blockIdx.x * blockDim.x + threadIdx.x;
    if (idx >= Bsz * Tn * Hn) return;
    int r = idx / Hn;
    int h = idx - r * Hn;
    int b = r / Tn, t = r - b * Tn;
    g_emb[idx] = E[(size_t)caps[b * 20 + t] * Hn + h];
}

// ==================== attctx v4: 4 blocks per b (D split), scores duplicated ====
__global__ __launch_bounds__(1024)
void attctx_kernel(const float* __restrict__ img,
                   const float* __restrict__ v_att, const float* __restrict__ b_v_att,
                   const float* __restrict__ b_att_h, const float* __restrict__ b_fbeta,
                   float* __restrict__ out_alphas, int t)
{
    const int blk = blockIdx.x;
    const int b = blk >> 2, sl = blk & 3;
    const int tid = threadIdx.x;
    const int w = tid >> 5, lane = tid & 31;
    __shared__ float hp[Hn];
    __shared__ float va[Hn];
    __shared__ float ee[Pn];
    __shared__ float sred[8];
    __shared__ __align__(16) float4 redD[8 * 128];   // 16KB

    if (tid < Hn) {
        float v = b_att_h[tid];
#pragma unroll
        for (int s = 0; s < 8; s++) v += g_pp_h[s * Bsz * Hn + b * Hn + tid];
        hp[tid] = v;
        va[tid] = v_att[tid];
    }
    __syncthreads();

    const float* ai = g_att_img + (size_t)b * Pn * Hn;
    const float bv0 = b_v_att[0];
    for (int p = w; p < Pn; p += 32) {
        const float* aip = ai + (size_t)p * Hn;
        float s = 0.f;
#pragma unroll
        for (int ii = 0; ii < Hn / 32; ii++) {
            int hx = lane + 32 * ii;
            float x = aip[hx] + hp[hx];
            float th;
            asm("tanh.approx.f32 %0, %1;" : "=f"(th) : "f"(x));
            s = fmaf(th, va[hx], s);
        }
#pragma unroll
        for (int o = 16; o; o >>= 1) s += __shfl_down_sync(0xffffffffu, s, o);
        if (lane == 0) ee[p] = s + bv0;
    }
    __syncthreads();

    float v = (tid < Pn) ? ee[tid] : -1e30f;
    if (tid < 256) {
        float m = v;
#pragma unroll
        for (int o = 16; o; o >>= 1) m = fmaxf(m, __shfl_xor_sync(0xffffffffu, m, o));
        if (lane == 0) sred[w] = m;
    }
    __syncthreads();
    if (tid < 32) {
        float mm = (tid < 8) ? sred[tid] : -1e30f;
#pragma unroll
        for (int o = 4; o; o >>= 1) mm = fmaxf(mm, __shfl_xor_sync(0xffffffffu, mm, o));
        if (tid == 0) sred[0] = mm;
    }
    __syncthreads();
    float exv = (tid < Pn) ? expf(v - sred[0]) : 0.f;
    __syncthreads();
    if (tid < 256) {
        float s = exv;
#pragma unroll
        for (int o = 16; o; o >>= 1) s += __shfl_xor_sync(0xffffffffu, s, o);
        if (lane == 0) sred[w] = s;
    }
    __syncthreads();
    if (tid < 32) {
        float ss = (tid < 8) ? sred[tid] : 0.f;
#pragma unroll
        for (int o = 4; o; o >>= 1) ss += __shfl_xor_sync(0xffffffffu, ss, o);
        if (tid == 0) sred[0] = ss;
    }
    __syncthreads();
    if (tid < Pn) {
        float a = exv / sred[0];
        ee[tid] = a;
        if (sl == 0) out_alphas[((size_t)b * Tn + t) * Pn + tid] = a;
    }
    __syncthreads();

    // context: this block handles D-columns [sl*512, sl*512+512) = 128 float4s
    const int dl = tid & 127;          // 128 d4 columns
    const int ps = tid >> 7;           // 8-way p split
    const int d4 = sl * 128 + dl;
    const float4* ip = (const float4*)img + (size_t)b * Pn * (Dn / 4) + d4;
    float4 cx = make_float4(0.f, 0.f, 0.f, 0.f);
#pragma unroll 8
    for (int p = ps; p < Pn; p += 8) {
        float a = ee[p];
        float4 x = ip[(size_t)p * (Dn / 4)];
        cx.x = fmaf(a, x.x, cx.x); cx.y = fmaf(a, x.y, cx.y);
        cx.z = fmaf(a, x.z, cx.z); cx.w = fmaf(a, x.w, cx.w);
    }
    redD[ps * 128 + dl] = cx;
    __syncthreads();
    if (tid < 128) {
        float4 sum = redD[tid];
#pragma unroll
        for (int k = 1; k < 8; k++) {
            float4 r = redD[k * 128 + tid];
            sum.x += r.x; sum.y += r.y; sum.z += r.z; sum.w += r.w;
        }
        int dd = sl * 128 + tid;
        float4 gb = ((const float4*)b_fbeta)[dd];
#pragma unroll
        for (int sp = 0; sp < 8; sp++) {
            float4 pv = ((const float4*)g_pp_g)[sp * (Bsz * Dn / 4) + b * (Dn / 4) + dd];
            gb.x += pv.x; gb.y += pv.y; gb.z += pv.z; gb.w += pv.w;
        }
        sum.x *= sigf(gb.x); sum.y *= sigf(gb.y);
        sum.z *= sigf(gb.z); sum.w *= sigf(gb.w);
        ((float4*)g_xc)[b * (Dn / 4) + dd] = sum;
    }
}

// LSTM pointwise
__global__ void lstm_kernel(const float* __restrict__ bih, const float* __restrict__ bhh, int t)
{
    int idx = blockIdx.x * blockDim.x + threadIdx.x;
    if (idx >= Bsz * Hn) return;
    int b = idx >> 9;
    int j = idx & 511;
    int rowE = (b * Tn + t) * 4 * Hn;
    int rowP = b * 4 * Hn;

    float gv[4];
#pragma unroll
    for (int g = 0; g < 4; g++) {
        int n = g * Hn + j;
        float v = g_embW[rowE + n] + bih[n] + bhh[n];
#pragma unroll
        for (int s = 0; s < 8; s++) v += g_pa[s * Bsz * 4 * Hn + rowP + n];
#pragma unroll
        for (int s = 0; s < 4; s++) v += g_pb[s * Bsz * 4 * Hn + rowP + n];
        gv[g] = v;
    }
    float c = sigf(gv[1]) * g_c[idx] + sigf(gv[0]) * tanhf(gv[2]);
    g_c[idx] = c;
    float h = sigf(gv[3]) * tanhf(c);
    g_h[idx] = h;
    size_t ro = (size_t)(t * Bsz + b) * Hn + j;
    __nv_bfloat16 hh = __float2bfloat16(h);
    g_hallh[ro] = hh;
    g_halll[ro] = __float2bfloat16(h - __bfloat162float(hh));
}

// ================================================================================
extern "C" void kernel_launch(void* const* d_in, const int* in_sizes, int n_in,
                              void* d_out, int out_size)
{
    const float* img      = (const float*)d_in[0];
    const int*   caps     = (const int*)d_in[1];
    const float* Wih      = (const float*)d_in[2];
    const float* Whh      = (const float*)d_in[3];
    const float* bih      = (const float*)d_in[4];
    const float* bhh      = (const float*)d_in[5];
    const float* W_init_h = (const float*)d_in[6];
    const float* b_init_h = (const float*)d_in[7];
    const float* W_init_c = (const float*)d_in[8];
    const float* b_init_c = (const float*)d_in[9];
    const float* W_fbeta  = (const float*)d_in[10];
    const float* b_fbeta  = (const float*)d_in[11];
    const float* W_out    = (const float*)d_in[12];
    const float* b_out    = (const float*)d_in[13];
    const float* W_att_im = (const float*)d_in[14];
    const float* b_att_im = (const float*)d_in[15];
    const float* W_att_h  = (const float*)d_in[16];
    const float* b_att_h  = (const float*)d_in[17];
    const float* v_att    = (const float*)d_in[18];
    const float* b_v_att  = (const float*)d_in[19];
    const float* E        = (const float*)d_in[20];

    float* preds  = (float*)d_out;
    float* alphas = (float*)d_out + (size_t)Bsz * Tn * Vn;

    float *p_avg, *p_h, *p_c, *p_att, *p_emb, *p_embW, *p_xc, *p_pph, *p_ppg;
    float *p_pa, *p_pb, *p_pih, *p_pic;
    __nv_bfloat16 *p_imgh, *p_imgl, *p_watth, *p_wattl, *p_wouth, *p_woutl;
    __nv_bfloat16 *p_wihh, *p_wihl, *p_embh, *p_embl, *p_hallh, *p_halll;
    cudaGetSymbolAddress((void**)&p_avg,   g_avg);
    cudaGetSymbolAddress((void**)&p_h,     g_h);
    cudaGetSymbolAddress((void**)&p_c,     g_c);
    cudaGetSymbolAddress((void**)&p_att,   g_att_img);
    cudaGetSymbolAddress((void**)&p_emb,   g_emb);
    cudaGetSymbolAddress((void**)&p_embW,  g_embW);
    cudaGetSymbolAddress((void**)&p_xc,    g_xc);
    cudaGetSymbolAddress((void**)&p_pph,   g_pp_h);
    cudaGetSymbolAddress((void**)&p_ppg,   g_pp_g);
    cudaGetSymbolAddress((void**)&p_pa,    g_pa);
    cudaGetSymbolAddress((void**)&p_pb,    g_pb);
    cudaGetSymbolAddress((void**)&p_pih,   g_pi_h);
    cudaGetSymbolAddress((void**)&p_pic,   g_pi_c);
    cudaGetSymbolAddress((void**)&p_imgh,  g_img_hi);
    cudaGetSymbolAddress((void**)&p_imgl,  g_img_lo);
    cudaGetSymbolAddress((void**)&p_watth, g_watt_hi);
    cudaGetSymbolAddress((void**)&p_wattl, g_watt_lo);
    cudaGetSymbolAddress((void**)&p_wouth, g_wout_hi);
    cudaGetSymbolAddress((void**)&p_woutl, g_wout_lo);
    cudaGetSymbolAddress((void**)&p_wihh,  g_wih_hi);
    cudaGetSymbolAddress((void**)&p_wihl,  g_wih_lo);
    cudaGetSymbolAddress((void**)&p_embh,  g_embh);
    cudaGetSymbolAddress((void**)&p_embl,  g_embl);
    cudaGetSymbolAddress((void**)&p_hallh, g_hallh);
    cudaGetSymbolAddress((void**)&p_halll, g_halll);

    cudaFuncSetAttribute(hmma_gemm64<0>, cudaFuncAttributeMaxDynamicSharedMemorySize, HMMA64_SMEM);
    cudaFuncSetAttribute(hmma_gemm64<1>, cudaFuncAttributeMaxDynamicSharedMemorySize, HMMA64_SMEM);

    // ---- setup; launch index 3 = attctx PROBE (outputs overwritten by real t=0) ----
    conv_split4<<<(Bsz * Pn * Dn / 4 + 255) / 256, 256>>>(img, p_imgh, p_imgl, Bsz * Pn * Dn / 4);    // 0
    conv_splitT<<<dim3(Hn / 32, Dn / 32), dim3(32, 8)>>>(W_att_im, Hn, p_watth, p_wattl, Dn, Hn, Hn); // 1
    avg_kernel<<<64, 256>>>(img);                                                                     // 2
    attctx_kernel<<<4 * Bsz, 1024>>>(img, v_att, b_v_att, b_att_h, b_fbeta, alphas, 0);               // 3 <- ncu
    hmma_gemm64<0><<<dim3(Hn / 64, (Bsz * Pn) / 128), 256, HMMA64_SMEM>>>(                            // 4
        p_imgh, p_imgl, p_watth, p_wattl, b_att_im, p_att, Bsz * Pn, Hn, Dn, Hn);
    conv_splitT<<<dim3(Vp / 32, Hn / 32), dim3(32, 8)>>>(W_out, Vn, p_wouth, p_woutl, Hn, Vn, Vp);
    conv_splitT<<<dim3(4 * Hn / 32, Hn / 32), dim3(32, 8)>>>(Wih, 4 * Hn, p_wihh, p_wihl, Hn, 4 * Hn, 4 * Hn);
    gemm_pass<<<256, 64>>>(p_avg, Dn, W_init_h, Hn, p_pih, Hn, Dn, 8, 16,
                           p_avg, Dn, W_init_c, Hn, p_pic, Hn, Dn, 8, 16);
    reduce2_kernel<<<128, 256>>>(p_h, p_pih, 8, Hn, b_init_h, 1, Bsz * Hn,
                                 p_c, p_pic, 8, Hn, b_init_c, 1, Bsz * Hn);
    emb_kernel<<<(Bsz * Tn * Hn) / 256, 256>>>(caps, E);
    conv_split<<<(Mp * Hn) / 256, 256>>>(p_emb, p_embh, p_embl, Mrows, Hn, Mp);
    hmma_gemm64<0><<<dim3(4 * Hn / 64, Mp / 128), 256, HMMA64_SMEM>>>(
        p_embh, p_embl, p_wihh, p_wihl, nullptr, p_embW, Mrows, 4 * Hn, Hn, 4 * Hn);
    pad_hall_kernel<<<((Mp - Mrows) * Hn + 255) / 256, 256>>>();

    const float* WihBot = Wih + (size_t)Hn * 4 * Hn;

    // ---- recurrent steps ----
    for (int t = 0; t < Tn; t++) {
        gemm_pass3<<<128 + 512 + 256, 128>>>(
            p_h, Hn, W_att_h, Hn,     p_pph, Hn,     Hn, 8,
            p_h, Hn, W_fbeta, Dn,     p_ppg, Dn,     Hn, 8,
            p_h, Hn, Whh,     4 * Hn, p_pb,  4 * Hn, Hn, 4);
        attctx_kernel<<<4 * Bsz, 1024>>>(img, v_att, b_v_att, b_att_h, b_fbeta, alphas, t);
        gemm_pass3<<<512, 128>>>(
            p_xc, Dn, WihBot, 4 * Hn, p_pa, 4 * Hn, Dn, 8,
            p_xc, Dn, WihBot, 4 * Hn, p_pa, 0,      Dn, 8,
            p_xc, Dn, WihBot, 4 * Hn, p_pa, 0,      Dn, 8);
        lstm_kernel<<<(Bsz * Hn) / 256, 256>>>(bih, bhh, t);
    }

    // ---- final: preds = h_all @ W_out + b_out (hmma64, OUTMAP) ----
    hmma_gemm64<1><<<dim3(Vp / 64, Mp / 128), 256, HMMA64_SMEM>>>(
        p_hallh, p_halll, p_wouth, p_woutl, b_out, preds, Mrows, Vn, Hn, Vn);
}